// round 1
// baseline (speedup 1.0000x reference)
#include <cuda_runtime.h>
#include <cstdint>

#define S_LEN 4096
#define BATCH 2
#define EMB   768
#define NH    12
#define HDIM  64
#define WIN   256
#define GLB   32
#define QT    32
#define LDK   68

// -------- scratch (device globals; no allocation allowed) --------
__device__ float g_q [BATCH * S_LEN * EMB];
__device__ float g_k [BATCH * S_LEN * EMB];
__device__ float g_v [BATCH * S_LEN * EMB];
__device__ float g_kg[BATCH * S_LEN * EMB];
__device__ float g_vg[BATCH * S_LEN * EMB];
__device__ float g_qg[BATCH * GLB * EMB];

// ---------------- GEMM: Y = (A @ W + bias) * scale ----------------
// 128x64 tile, 256 threads, 8x4 microtile, TK=8
__device__ __forceinline__ void gemm_body(
    const float* __restrict__ A, const float* __restrict__ Wm,
    const float* __restrict__ bias, float* __restrict__ Y,
    int M, float scale, int rowmod, int rowstride)
{
    const int N = EMB, K = EMB;
    __shared__ float As[8][132];
    __shared__ float Bs[8][68];

    int m0 = blockIdx.y * 128, n0 = blockIdx.x * 64;
    int t  = threadIdx.x;
    int tx = t & 15, ty = t >> 4;

    float acc[8][4];
#pragma unroll
    for (int r = 0; r < 8; r++)
#pragma unroll
        for (int c = 0; c < 4; c++) acc[r][c] = 0.f;

    int lr = t >> 1;            // 0..127 (A row in tile)
    int lk = (t & 1) * 4;       // 0 or 4 (k offset)
    int gr = m0 + lr;
    const float* arow = nullptr;
    if (gr < M) {
        int sr = rowmod ? (gr / rowmod) * rowstride + (gr % rowmod) : gr;
        arow = A + (size_t)sr * K;
    }

    for (int k0 = 0; k0 < K; k0 += 8) {
        float4 av = make_float4(0.f, 0.f, 0.f, 0.f);
        if (arow) av = *(const float4*)(arow + k0 + lk);
        if (t < 128) {
            int kk = t >> 4, nq = (t & 15) << 2;
            *(float4*)&Bs[kk][nq] =
                *(const float4*)&Wm[(size_t)(k0 + kk) * N + n0 + nq];
        }
        As[lk + 0][lr] = av.x; As[lk + 1][lr] = av.y;
        As[lk + 2][lr] = av.z; As[lk + 3][lr] = av.w;
        __syncthreads();
#pragma unroll
        for (int kk = 0; kk < 8; kk++) {
            float4 b4 = *(const float4*)&Bs[kk][tx << 2];
            float4 a0 = *(const float4*)&As[kk][ty << 3];
            float4 a1 = *(const float4*)&As[kk][(ty << 3) + 4];
            float ar[8] = {a0.x, a0.y, a0.z, a0.w, a1.x, a1.y, a1.z, a1.w};
#pragma unroll
            for (int r = 0; r < 8; r++) {
                acc[r][0] += ar[r] * b4.x;
                acc[r][1] += ar[r] * b4.y;
                acc[r][2] += ar[r] * b4.z;
                acc[r][3] += ar[r] * b4.w;
            }
        }
        __syncthreads();
    }

    float4 bi = *(const float4*)&bias[n0 + (tx << 2)];
#pragma unroll
    for (int r = 0; r < 8; r++) {
        int grr = m0 + (ty << 3) + r;
        if (grr < M) {
            float4 o;
            o.x = (acc[r][0] + bi.x) * scale;
            o.y = (acc[r][1] + bi.y) * scale;
            o.z = (acc[r][2] + bi.z) * scale;
            o.w = (acc[r][3] + bi.w) * scale;
            *(float4*)&Y[(size_t)grr * N + n0 + (tx << 2)] = o;
        }
    }
}

__global__ __launch_bounds__(256) void gemm5_kernel(
    const float* __restrict__ x,
    const float* __restrict__ wq,  const float* __restrict__ bq,
    const float* __restrict__ wk,  const float* __restrict__ bk,
    const float* __restrict__ wv,  const float* __restrict__ bv,
    const float* __restrict__ wkg, const float* __restrict__ bkg,
    const float* __restrict__ wvg, const float* __restrict__ bvg,
    float* q, float* k, float* v, float* kg, float* vg)
{
    const int M = BATCH * S_LEN;
    switch (blockIdx.z) {
        case 0: gemm_body(x, wq,  bq,  q,  M, 0.125f, 0, 0); break;
        case 1: gemm_body(x, wk,  bk,  k,  M, 1.0f,   0, 0); break;
        case 2: gemm_body(x, wv,  bv,  v,  M, 1.0f,   0, 0); break;
        case 3: gemm_body(x, wkg, bkg, kg, M, 1.0f,   0, 0); break;
        default: gemm_body(x, wvg, bvg, vg, M, 1.0f,  0, 0); break;
    }
}

__global__ __launch_bounds__(256) void gemm_qg_kernel(
    const float* __restrict__ x, const float* __restrict__ wqg,
    const float* __restrict__ bqg, float* qg)
{
    gemm_body(x, wqg, bqg, qg, BATCH * GLB, 0.125f, GLB, S_LEN);
}

// ---------------- Local (banded + global-key) attention ----------------
// One block = (b, h, 32 consecutive queries). Online softmax over:
//   chunk -1: the G=32 global keys (no mask, no band limit)  [sel_w part]
//   chunks 0..: window keys [i0-W, i0+31+W] with mask penalty [band part]
__global__ __launch_bounds__(256, 2) void local_attn_kernel(
    const float* __restrict__ q, const float* __restrict__ k,
    const float* __restrict__ v, const int* __restrict__ mask,
    float* __restrict__ out)
{
    __shared__ float ks[QT][LDK];
    __shared__ float vs[QT][LDK];
    __shared__ float sc[QT][36];

    int b = blockIdx.z, h = blockIdx.y;
    int i0 = blockIdx.x * QT;
    int t = threadIdx.x;
    int qi = t >> 3, sub = t & 7;
    int iq = i0 + qi;

    float qf[64];
    {
        const float* qrow = q + ((size_t)(b * S_LEN + iq)) * EMB + h * HDIM;
#pragma unroll
        for (int e4 = 0; e4 < 16; e4++) {
            float4 t4 = *(const float4*)(qrow + e4 * 4);
            qf[e4 * 4 + 0] = t4.x; qf[e4 * 4 + 1] = t4.y;
            qf[e4 * 4 + 2] = t4.z; qf[e4 * 4 + 3] = t4.w;
        }
    }
    float acc[8] = {0.f, 0.f, 0.f, 0.f, 0.f, 0.f, 0.f, 0.f};
    float m_run = -1e30f, l_run = 0.f;

    int lo = i0 - WIN; if (lo < 0) lo = 0;
    int hi = i0 + QT - 1 + WIN; if (hi > S_LEN - 1) hi = S_LEN - 1;
    int wstart = lo & ~(QT - 1);
    int nwin = (hi - wstart) / QT + 1;

    for (int ci = -1; ci < nwin; ci++) {
        bool gl = (ci < 0);
        int kstart = gl ? 0 : wstart + ci * QT;

        __syncthreads();   // protect ks/vs from previous accumulation
        for (int u = t; u < QT * 16; u += 256) {
            int r = u >> 4, c = (u & 15) << 2;
            int p = kstart + r;
            float4 kv4 = make_float4(0.f, 0.f, 0.f, 0.f);
            float4 vv4 = make_float4(0.f, 0.f, 0.f, 0.f);
            if (p < S_LEN) {
                size_t off = ((size_t)(b * S_LEN + p)) * EMB + h * HDIM + c;
                kv4 = *(const float4*)(k + off);
                vv4 = *(const float4*)(v + off);
            }
            *(float4*)&ks[r][c] = kv4;
            *(float4*)&vs[r][c] = vv4;
        }
        __syncthreads();

        // scores for 4 keys (j = sub*4 + u)
        float sv[4];
#pragma unroll
        for (int u = 0; u < 4; u++) {
            int j = sub * 4 + u;
            int p = kstart + j;
            bool valid = gl || (p < S_LEN && p >= iq - WIN && p <= iq + WIN);
            float s = -1e30f;
            if (valid) {
                float d = 0.f;
#pragma unroll
                for (int e4 = 0; e4 < 16; e4++) {
                    float4 k4 = *(const float4*)&ks[j][e4 * 4];
                    d += qf[e4 * 4 + 0] * k4.x + qf[e4 * 4 + 1] * k4.y
                       + qf[e4 * 4 + 2] * k4.z + qf[e4 * 4 + 3] * k4.w;
                }
                if (!gl && mask[b * S_LEN + p]) d -= 10000.f;
                s = d;
            }
            sv[u] = s;
        }
        // online softmax update (8-lane groups per query)
        float cm = fmaxf(fmaxf(sv[0], sv[1]), fmaxf(sv[2], sv[3]));
        cm = fmaxf(cm, __shfl_xor_sync(0xffffffffu, cm, 1));
        cm = fmaxf(cm, __shfl_xor_sync(0xffffffffu, cm, 2));
        cm = fmaxf(cm, __shfl_xor_sync(0xffffffffu, cm, 4));
        float m_new = fmaxf(m_run, cm);
        float rsc = expf(m_run - m_new);
        float psum = 0.f;
#pragma unroll
        for (int u = 0; u < 4; u++) {
            float e = expf(sv[u] - m_new);
            sc[qi][sub * 4 + u] = e;
            psum += e;
        }
        psum += __shfl_xor_sync(0xffffffffu, psum, 1);
        psum += __shfl_xor_sync(0xffffffffu, psum, 2);
        psum += __shfl_xor_sync(0xffffffffu, psum, 4);
        l_run = l_run * rsc + psum;
        m_run = m_new;
        __syncwarp();      // sc[qi][*] produced/consumed within one warp

#pragma unroll
        for (int d8 = 0; d8 < 8; d8++) acc[d8] *= rsc;
#pragma unroll 4
        for (int j = 0; j < QT; j++) {
            float e = sc[qi][j];
            float4 v0 = *(const float4*)&vs[j][sub * 8];
            float4 v1 = *(const float4*)&vs[j][sub * 8 + 4];
            acc[0] += e * v0.x; acc[1] += e * v0.y;
            acc[2] += e * v0.z; acc[3] += e * v0.w;
            acc[4] += e * v1.x; acc[5] += e * v1.y;
            acc[6] += e * v1.z; acc[7] += e * v1.w;
        }
    }

    float inv = 1.f / l_run;
    size_t ob = ((size_t)(b * S_LEN + iq)) * EMB + h * HDIM + sub * 8;
    float4 o0 = make_float4(acc[0] * inv, acc[1] * inv, acc[2] * inv, acc[3] * inv);
    float4 o1 = make_float4(acc[4] * inv, acc[5] * inv, acc[6] * inv, acc[7] * inv);
    *(float4*)&out[ob]     = o0;
    *(float4*)&out[ob + 4] = o1;
}

// ---------------- Global rows (i < G): full attention ----------------
__global__ __launch_bounds__(256) void global_attn_kernel(
    const float* __restrict__ qg, const float* __restrict__ kg,
    const float* __restrict__ vg, float* __restrict__ out)
{
    __shared__ float sc[S_LEN];
    __shared__ float qv[64];
    __shared__ float red[8];
    __shared__ float part[8][64];

    int b = blockIdx.z, h = blockIdx.y, g = blockIdx.x;
    int t = threadIdx.x, w = t >> 5, lane = t & 31;

    if (t < 16)
        *(float4*)&qv[t * 4] =
            *(const float4*)&qg[((size_t)(b * GLB + g)) * EMB + h * HDIM + t * 4];
    __syncthreads();
    float qa = qv[lane], qb = qv[lane + 32];

    for (int s = w; s < S_LEN; s += 8) {
        const float* kr = kg + ((size_t)(b * S_LEN + s)) * EMB + h * HDIM;
        float p = qa * kr[lane] + qb * kr[lane + 32];
#pragma unroll
        for (int o = 16; o > 0; o >>= 1) p += __shfl_xor_sync(0xffffffffu, p, o);
        if (lane == 0) sc[s] = p;
    }
    __syncthreads();

    float mx = -1e30f;
    for (int s = t; s < S_LEN; s += 256) mx = fmaxf(mx, sc[s]);
#pragma unroll
    for (int o = 16; o > 0; o >>= 1) mx = fmaxf(mx, __shfl_xor_sync(0xffffffffu, mx, o));
    if (lane == 0) red[w] = mx;
    __syncthreads();
    mx = red[0];
#pragma unroll
    for (int i = 1; i < 8; i++) mx = fmaxf(mx, red[i]);
    __syncthreads();   // everyone done reading red before reuse

    float ps = 0.f;
    for (int s = t; s < S_LEN; s += 256) {
        float e = expf(sc[s] - mx);
        sc[s] = e;
        ps += e;
    }
#pragma unroll
    for (int o = 16; o > 0; o >>= 1) ps += __shfl_xor_sync(0xffffffffu, ps, o);
    if (lane == 0) red[w] = ps;
    __syncthreads();
    float l = 0.f;
#pragma unroll
    for (int i = 0; i < 8; i++) l += red[i];

    float a0 = 0.f, a1 = 0.f;
    for (int s = w; s < S_LEN; s += 8) {
        float e = sc[s];
        const float* vr = vg + ((size_t)(b * S_LEN + s)) * EMB + h * HDIM;
        a0 += e * vr[lane];
        a1 += e * vr[lane + 32];
    }
    part[w][lane] = a0;
    part[w][lane + 32] = a1;
    __syncthreads();

    if (t < 64) {
        float sum = 0.f;
#pragma unroll
        for (int ww = 0; ww < 8; ww++) sum += part[ww][t];
        out[((size_t)(b * S_LEN + g)) * EMB + h * HDIM + t] = sum / l;
    }
}

// ---------------- launch ----------------
extern "C" void kernel_launch(void* const* d_in, const int* in_sizes, int n_in,
                              void* d_out, int out_size)
{
    (void)n_in; (void)out_size;
    // layer_id (scalar) may or may not occupy slot 2; wq has E*E elements
    int base = (in_sizes[2] == EMB * EMB) ? 2 : 3;

    const float* x    = (const float*)d_in[0];
    const int*   mask = (const int*)d_in[1];
    const float* wq   = (const float*)d_in[base + 0];
    const float* bq   = (const float*)d_in[base + 1];
    const float* wk   = (const float*)d_in[base + 2];
    const float* bk   = (const float*)d_in[base + 3];
    const float* wv   = (const float*)d_in[base + 4];
    const float* bv   = (const float*)d_in[base + 5];
    const float* wqg  = (const float*)d_in[base + 6];
    const float* bqg  = (const float*)d_in[base + 7];
    const float* wkg  = (const float*)d_in[base + 8];
    const float* bkg  = (const float*)d_in[base + 9];
    const float* wvg  = (const float*)d_in[base + 10];
    const float* bvg  = (const float*)d_in[base + 11];
    float* out = (float*)d_out;

    float *q, *k, *v, *kg, *vg, *qg;
    cudaGetSymbolAddress((void**)&q,  g_q);
    cudaGetSymbolAddress((void**)&k,  g_k);
    cudaGetSymbolAddress((void**)&v,  g_v);
    cudaGetSymbolAddress((void**)&kg, g_kg);
    cudaGetSymbolAddress((void**)&vg, g_vg);
    cudaGetSymbolAddress((void**)&qg, g_qg);

    dim3 g5(EMB / 64, (BATCH * S_LEN + 127) / 128, 5);
    gemm5_kernel<<<g5, 256>>>(x, wq, bq, wk, bk, wv, bv, wkg, bkg, wvg, bvg,
                              q, k, v, kg, vg);
    gemm_qg_kernel<<<dim3(EMB / 64, 1, 1), 256>>>(x, wqg, bqg, qg);
    local_attn_kernel<<<dim3(S_LEN / QT, NH, BATCH), 256>>>(q, k, v, mask, out);
    global_attn_kernel<<<dim3(GLB, NH, BATCH), 256>>>(qg, kg, vg, out);
}

// round 2
// speedup vs baseline: 1.1189x; 1.1189x over previous
#include <cuda_runtime.h>
#include <cstdint>

#define S_LEN 4096
#define BATCH 2
#define EMB   768
#define NH    12
#define HDIM  64
#define WIN   256
#define GLB   32
#define QT    32
#define LDK   68

typedef unsigned long long u64;

// ---------- packed f32x2 helpers (sm_100+): 2 IEEE fp32 FMAs per issue ----------
__device__ __forceinline__ u64 pk2(float x, float y) {
    u64 r; asm("mov.b64 %0, {%1,%2};" : "=l"(r) : "f"(x), "f"(y)); return r;
}
__device__ __forceinline__ u64 dup2(float x) { return pk2(x, x); }
__device__ __forceinline__ float2 up2(u64 v) {
    float2 f; asm("mov.b64 {%0,%1}, %2;" : "=f"(f.x), "=f"(f.y) : "l"(v)); return f;
}
__device__ __forceinline__ u64 ffma2(u64 a, u64 b, u64 c) {
    u64 d; asm("fma.rn.f32x2 %0, %1, %2, %3;" : "=l"(d) : "l"(a), "l"(b), "l"(c)); return d;
}
__device__ __forceinline__ u64 fadd2(u64 a, u64 b) {
    u64 d; asm("add.rn.f32x2 %0, %1, %2;" : "=l"(d) : "l"(a), "l"(b)); return d;
}
__device__ __forceinline__ u64 fmul2(u64 a, u64 b) {
    u64 d; asm("mul.rn.f32x2 %0, %1, %2;" : "=l"(d) : "l"(a), "l"(b)); return d;
}

// -------- scratch (device globals; no allocation allowed) --------
__device__ float g_q [BATCH * S_LEN * EMB];
__device__ float g_k [BATCH * S_LEN * EMB];
__device__ float g_v [BATCH * S_LEN * EMB];
__device__ float g_kg[BATCH * S_LEN * EMB];
__device__ float g_vg[BATCH * S_LEN * EMB];
__device__ float g_qg[BATCH * GLB * EMB];

// ---------------- GEMM: Y = (A @ W + bias) * scale ----------------
// 128x64 tile, 256 threads, 8x4 microtile, TK=8, FFMA2 inner loop
__device__ __forceinline__ void gemm_body(
    const float* __restrict__ A, const float* __restrict__ Wm,
    const float* __restrict__ bias, float* __restrict__ Y,
    int M, float scale, int rowmod, int rowstride)
{
    const int N = EMB, K = EMB;
    __shared__ float As[8][132];
    __shared__ float Bs[8][68];

    int m0 = blockIdx.y * 128, n0 = blockIdx.x * 64;
    int t  = threadIdx.x;
    int tx = t & 15, ty = t >> 4;

    // acc2[p][c] holds rows (2p, 2p+1) of the 8-row microtile, col c
    u64 acc2[4][4];
#pragma unroll
    for (int p = 0; p < 4; p++)
#pragma unroll
        for (int c = 0; c < 4; c++) acc2[p][c] = 0ULL;

    int lr = t >> 1;            // 0..127 (A row in tile)
    int lk = (t & 1) * 4;       // 0 or 4 (k offset)
    int gr = m0 + lr;
    const float* arow = nullptr;
    if (gr < M) {
        int sr = rowmod ? (gr / rowmod) * rowstride + (gr % rowmod) : gr;
        arow = A + (size_t)sr * K;
    }

    for (int k0 = 0; k0 < K; k0 += 8) {
        float4 av = make_float4(0.f, 0.f, 0.f, 0.f);
        if (arow) av = *(const float4*)(arow + k0 + lk);
        if (t < 128) {
            int kk = t >> 4, nq = (t & 15) << 2;
            *(float4*)&Bs[kk][nq] =
                *(const float4*)&Wm[(size_t)(k0 + kk) * N + n0 + nq];
        }
        As[lk + 0][lr] = av.x; As[lk + 1][lr] = av.y;
        As[lk + 2][lr] = av.z; As[lk + 3][lr] = av.w;
        __syncthreads();
#pragma unroll
        for (int kk = 0; kk < 8; kk++) {
            // A rows pair naturally in smem (consecutive rows)
            ulonglong2 A0 = *(const ulonglong2*)&As[kk][ty << 3];
            ulonglong2 A1 = *(const ulonglong2*)&As[kk][(ty << 3) + 4];
            float4 b4 = *(const float4*)&Bs[kk][tx << 2];
            u64 b0 = dup2(b4.x), b1 = dup2(b4.y), b2 = dup2(b4.z), b3 = dup2(b4.w);
            acc2[0][0] = ffma2(A0.x, b0, acc2[0][0]);
            acc2[0][1] = ffma2(A0.x, b1, acc2[0][1]);
            acc2[0][2] = ffma2(A0.x, b2, acc2[0][2]);
            acc2[0][3] = ffma2(A0.x, b3, acc2[0][3]);
            acc2[1][0] = ffma2(A0.y, b0, acc2[1][0]);
            acc2[1][1] = ffma2(A0.y, b1, acc2[1][1]);
            acc2[1][2] = ffma2(A0.y, b2, acc2[1][2]);
            acc2[1][3] = ffma2(A0.y, b3, acc2[1][3]);
            acc2[2][0] = ffma2(A1.x, b0, acc2[2][0]);
            acc2[2][1] = ffma2(A1.x, b1, acc2[2][1]);
            acc2[2][2] = ffma2(A1.x, b2, acc2[2][2]);
            acc2[2][3] = ffma2(A1.x, b3, acc2[2][3]);
            acc2[3][0] = ffma2(A1.y, b0, acc2[3][0]);
            acc2[3][1] = ffma2(A1.y, b1, acc2[3][1]);
            acc2[3][2] = ffma2(A1.y, b2, acc2[3][2]);
            acc2[3][3] = ffma2(A1.y, b3, acc2[3][3]);
        }
        __syncthreads();
    }

    float4 bi = *(const float4*)&bias[n0 + (tx << 2)];
#pragma unroll
    for (int p = 0; p < 4; p++) {
        float2 vx = up2(acc2[p][0]), vy = up2(acc2[p][1]);
        float2 vz = up2(acc2[p][2]), vw = up2(acc2[p][3]);
        int r0 = m0 + (ty << 3) + 2 * p;
        if (r0 < M) {
            float4 o;
            o.x = (vx.x + bi.x) * scale; o.y = (vy.x + bi.y) * scale;
            o.z = (vz.x + bi.z) * scale; o.w = (vw.x + bi.w) * scale;
            *(float4*)&Y[(size_t)r0 * N + n0 + (tx << 2)] = o;
        }
        if (r0 + 1 < M) {
            float4 o;
            o.x = (vx.y + bi.x) * scale; o.y = (vy.y + bi.y) * scale;
            o.z = (vz.y + bi.z) * scale; o.w = (vw.y + bi.w) * scale;
            *(float4*)&Y[(size_t)(r0 + 1) * N + n0 + (tx << 2)] = o;
        }
    }
}

__global__ __launch_bounds__(256) void gemm5_kernel(
    const float* __restrict__ x,
    const float* __restrict__ wq,  const float* __restrict__ bq,
    const float* __restrict__ wk,  const float* __restrict__ bk,
    const float* __restrict__ wv,  const float* __restrict__ bv,
    const float* __restrict__ wkg, const float* __restrict__ bkg,
    const float* __restrict__ wvg, const float* __restrict__ bvg,
    float* q, float* k, float* v, float* kg, float* vg)
{
    const int M = BATCH * S_LEN;
    switch (blockIdx.z) {
        case 0: gemm_body(x, wq,  bq,  q,  M, 0.125f, 0, 0); break;
        case 1: gemm_body(x, wk,  bk,  k,  M, 1.0f,   0, 0); break;
        case 2: gemm_body(x, wv,  bv,  v,  M, 1.0f,   0, 0); break;
        case 3: gemm_body(x, wkg, bkg, kg, M, 1.0f,   0, 0); break;
        default: gemm_body(x, wvg, bvg, vg, M, 1.0f,  0, 0); break;
    }
}

__global__ __launch_bounds__(256) void gemm_qg_kernel(
    const float* __restrict__ x, const float* __restrict__ wqg,
    const float* __restrict__ bqg, float* qg)
{
    gemm_body(x, wqg, bqg, qg, BATCH * GLB, 0.125f, GLB, S_LEN);
}

// ---------------- Local (banded + global-key) attention ----------------
// One block = (b, h, 32 consecutive queries). Online softmax over:
//   chunk -1: the G=32 global keys (sel_w part)
//   chunks 0..: window keys with mask penalty (band part)
__global__ __launch_bounds__(256, 2) void local_attn_kernel(
    const float* __restrict__ q, const float* __restrict__ k,
    const float* __restrict__ v, const int* __restrict__ mask,
    float* __restrict__ out)
{
    __shared__ float ks[QT][LDK];
    __shared__ float vs[QT][LDK];
    __shared__ float sc[QT][36];

    int b = blockIdx.z, h = blockIdx.y;
    int i0 = blockIdx.x * QT;
    int t = threadIdx.x;
    int qi = t >> 3, sub = t & 7;
    int iq = i0 + qi;

    // q row as 32 packed pairs
    u64 q2[32];
    {
        const ulonglong2* qrow = (const ulonglong2*)
            (q + ((size_t)(b * S_LEN + iq)) * EMB + h * HDIM);
#pragma unroll
        for (int e = 0; e < 16; e++) {
            ulonglong2 t2 = qrow[e];
            q2[e * 2] = t2.x; q2[e * 2 + 1] = t2.y;
        }
    }
    // output accumulators: dims {sub*4 .. +3} and {32+sub*4 .. +3} as 4 pairs
    u64 acc2[4] = {0ULL, 0ULL, 0ULL, 0ULL};
    float m_run = -1e30f, l_run = 0.f;

    int lo = i0 - WIN; if (lo < 0) lo = 0;
    int hi = i0 + QT - 1 + WIN; if (hi > S_LEN - 1) hi = S_LEN - 1;
    int wstart = lo & ~(QT - 1);
    int nwin = (hi - wstart) / QT + 1;

    for (int ci = -1; ci < nwin; ci++) {
        bool gl = (ci < 0);
        int kstart = gl ? 0 : wstart + ci * QT;

        __syncthreads();   // protect ks/vs from previous accumulation
        for (int u = t; u < QT * 16; u += 256) {
            int r = u >> 4, c = (u & 15) << 2;
            int p = kstart + r;
            float4 kv4 = make_float4(0.f, 0.f, 0.f, 0.f);
            float4 vv4 = make_float4(0.f, 0.f, 0.f, 0.f);
            if (p < S_LEN) {
                size_t off = ((size_t)(b * S_LEN + p)) * EMB + h * HDIM + c;
                kv4 = *(const float4*)(k + off);
                vv4 = *(const float4*)(v + off);
            }
            *(float4*)&ks[r][c] = kv4;
            *(float4*)&vs[r][c] = vv4;
        }
        __syncthreads();

        // scores for 4 keys (j = sub*4 + u), packed-pair dot products
        float sv[4];
#pragma unroll
        for (int u = 0; u < 4; u++) {
            int j = sub * 4 + u;
            int p = kstart + j;
            bool valid = gl || (p < S_LEN && p >= iq - WIN && p <= iq + WIN);
            float s = -1e30f;
            if (valid) {
                const ulonglong2* kr = (const ulonglong2*)&ks[j][0];
                u64 s0 = 0ULL, s1 = 0ULL, s2 = 0ULL, s3 = 0ULL;
#pragma unroll
                for (int e = 0; e < 16; e += 2) {
                    ulonglong2 ka = kr[e];
                    ulonglong2 kb = kr[e + 1];
                    s0 = ffma2(q2[e * 2],     ka.x, s0);
                    s1 = ffma2(q2[e * 2 + 1], ka.y, s1);
                    s2 = ffma2(q2[e * 2 + 2], kb.x, s2);
                    s3 = ffma2(q2[e * 2 + 3], kb.y, s3);
                }
                float2 r2 = up2(fadd2(fadd2(s0, s1), fadd2(s2, s3)));
                float d = r2.x + r2.y;
                if (!gl && mask[b * S_LEN + p]) d -= 10000.f;
                s = d;
            }
            sv[u] = s;
        }
        // online softmax update (8-lane groups per query)
        float cm = fmaxf(fmaxf(sv[0], sv[1]), fmaxf(sv[2], sv[3]));
        cm = fmaxf(cm, __shfl_xor_sync(0xffffffffu, cm, 1));
        cm = fmaxf(cm, __shfl_xor_sync(0xffffffffu, cm, 2));
        cm = fmaxf(cm, __shfl_xor_sync(0xffffffffu, cm, 4));
        float m_new = fmaxf(m_run, cm);
        float rsc = __expf(m_run - m_new);
        float psum = 0.f;
#pragma unroll
        for (int u = 0; u < 4; u++) {
            float e = __expf(sv[u] - m_new);
            sc[qi][sub * 4 + u] = e;
            psum += e;
        }
        psum += __shfl_xor_sync(0xffffffffu, psum, 1);
        psum += __shfl_xor_sync(0xffffffffu, psum, 2);
        psum += __shfl_xor_sync(0xffffffffu, psum, 4);
        l_run = l_run * rsc + psum;
        m_run = m_new;
        __syncwarp();      // sc[qi][*] produced/consumed within one warp

        u64 rb = dup2(rsc);
#pragma unroll
        for (int d = 0; d < 4; d++) acc2[d] = fmul2(acc2[d], rb);
#pragma unroll 4
        for (int j = 0; j < QT; j++) {
            u64 eb = dup2(sc[qi][j]);
            // dims sub*4..+3 and 32+sub*4..+3 (bank-conflict-free: 8 subs -> 8 distinct bank quads)
            ulonglong2 v0 = *(const ulonglong2*)&vs[j][sub * 4];
            ulonglong2 v1 = *(const ulonglong2*)&vs[j][sub * 4 + 32];
            acc2[0] = ffma2(eb, v0.x, acc2[0]);
            acc2[1] = ffma2(eb, v0.y, acc2[1]);
            acc2[2] = ffma2(eb, v1.x, acc2[2]);
            acc2[3] = ffma2(eb, v1.y, acc2[3]);
        }
    }

    float inv = 1.f / l_run;
    size_t ob = ((size_t)(b * S_LEN + iq)) * EMB + h * HDIM;
    float2 a0 = up2(acc2[0]), a1 = up2(acc2[1]);
    float2 a2 = up2(acc2[2]), a3 = up2(acc2[3]);
    float4 o0 = make_float4(a0.x * inv, a0.y * inv, a1.x * inv, a1.y * inv);
    float4 o1 = make_float4(a2.x * inv, a2.y * inv, a3.x * inv, a3.y * inv);
    *(float4*)&out[ob + sub * 4]      = o0;
    *(float4*)&out[ob + 32 + sub * 4] = o1;
}

// ---------------- Global rows (i < G): full attention ----------------
__global__ __launch_bounds__(256) void global_attn_kernel(
    const float* __restrict__ qg, const float* __restrict__ kg,
    const float* __restrict__ vg, float* __restrict__ out)
{
    __shared__ float sc[S_LEN];
    __shared__ float qv[64];
    __shared__ float red[8];
    __shared__ float part[8][64];

    int b = blockIdx.z, h = blockIdx.y, g = blockIdx.x;
    int t = threadIdx.x, w = t >> 5, lane = t & 31;

    if (t < 16)
        *(float4*)&qv[t * 4] =
            *(const float4*)&qg[((size_t)(b * GLB + g)) * EMB + h * HDIM + t * 4];
    __syncthreads();
    float qa = qv[lane], qb = qv[lane + 32];

    for (int s = w; s < S_LEN; s += 8) {
        const float* kr = kg + ((size_t)(b * S_LEN + s)) * EMB + h * HDIM;
        float p = qa * kr[lane] + qb * kr[lane + 32];
#pragma unroll
        for (int o = 16; o > 0; o >>= 1) p += __shfl_xor_sync(0xffffffffu, p, o);
        if (lane == 0) sc[s] = p;
    }
    __syncthreads();

    float mx = -1e30f;
    for (int s = t; s < S_LEN; s += 256) mx = fmaxf(mx, sc[s]);
#pragma unroll
    for (int o = 16; o > 0; o >>= 1) mx = fmaxf(mx, __shfl_xor_sync(0xffffffffu, mx, o));
    if (lane == 0) red[w] = mx;
    __syncthreads();
    mx = red[0];
#pragma unroll
    for (int i = 1; i < 8; i++) mx = fmaxf(mx, red[i]);
    __syncthreads();   // everyone done reading red before reuse

    float ps = 0.f;
    for (int s = t; s < S_LEN; s += 256) {
        float e = __expf(sc[s] - mx);
        sc[s] = e;
        ps += e;
    }
#pragma unroll
    for (int o = 16; o > 0; o >>= 1) ps += __shfl_xor_sync(0xffffffffu, ps, o);
    if (lane == 0) red[w] = ps;
    __syncthreads();
    float l = 0.f;
#pragma unroll
    for (int i = 0; i < 8; i++) l += red[i];

    float a0 = 0.f, a1 = 0.f;
    for (int s = w; s < S_LEN; s += 8) {
        float e = sc[s];
        const float* vr = vg + ((size_t)(b * S_LEN + s)) * EMB + h * HDIM;
        a0 += e * vr[lane];
        a1 += e * vr[lane + 32];
    }
    part[w][lane] = a0;
    part[w][lane + 32] = a1;
    __syncthreads();

    if (t < 64) {
        float sum = 0.f;
#pragma unroll
        for (int ww = 0; ww < 8; ww++) sum += part[ww][t];
        out[((size_t)(b * S_LEN + g)) * EMB + h * HDIM + t] = sum / l;
    }
}

// ---------------- launch ----------------
extern "C" void kernel_launch(void* const* d_in, const int* in_sizes, int n_in,
                              void* d_out, int out_size)
{
    (void)n_in; (void)out_size;
    int base = (in_sizes[2] == EMB * EMB) ? 2 : 3;

    const float* x    = (const float*)d_in[0];
    const int*   mask = (const int*)d_in[1];
    const float* wq   = (const float*)d_in[base + 0];
    const float* bq   = (const float*)d_in[base + 1];
    const float* wk   = (const float*)d_in[base + 2];
    const float* bk   = (const float*)d_in[base + 3];
    const float* wv   = (const float*)d_in[base + 4];
    const float* bv   = (const float*)d_in[base + 5];
    const float* wqg  = (const float*)d_in[base + 6];
    const float* bqg  = (const float*)d_in[base + 7];
    const float* wkg  = (const float*)d_in[base + 8];
    const float* bkg  = (const float*)d_in[base + 9];
    const float* wvg  = (const float*)d_in[base + 10];
    const float* bvg  = (const float*)d_in[base + 11];
    float* out = (float*)d_out;

    float *q, *k, *v, *kg, *vg, *qg;
    cudaGetSymbolAddress((void**)&q,  g_q);
    cudaGetSymbolAddress((void**)&k,  g_k);
    cudaGetSymbolAddress((void**)&v,  g_v);
    cudaGetSymbolAddress((void**)&kg, g_kg);
    cudaGetSymbolAddress((void**)&vg, g_vg);
    cudaGetSymbolAddress((void**)&qg, g_qg);

    dim3 g5(EMB / 64, (BATCH * S_LEN + 127) / 128, 5);
    gemm5_kernel<<<g5, 256>>>(x, wq, bq, wk, bk, wv, bv, wkg, bkg, wvg, bvg,
                              q, k, v, kg, vg);
    gemm_qg_kernel<<<dim3(EMB / 64, 1, 1), 256>>>(x, wqg, bqg, qg);
    local_attn_kernel<<<dim3(S_LEN / QT, NH, BATCH), 256>>>(q, k, v, mask, out);
    global_attn_kernel<<<dim3(GLB, NH, BATCH), 256>>>(qg, kg, vg, out);
}

// round 4
// speedup vs baseline: 1.3357x; 1.1938x over previous
#include <cuda_runtime.h>
#include <cuda_bf16.h>
#include <cstdint>

#define S_LEN 4096
#define BATCH 2
#define EMB   768
#define NH    12
#define HDIM  64
#define WIN   256
#define GLB   32
#define QT    32
#define LDK   68

typedef unsigned long long u64;

// ---------- packed f32x2 helpers ----------
__device__ __forceinline__ u64 pk2(float x, float y) {
    u64 r; asm("mov.b64 %0, {%1,%2};" : "=l"(r) : "f"(x), "f"(y)); return r;
}
__device__ __forceinline__ u64 dup2(float x) { return pk2(x, x); }
__device__ __forceinline__ float2 up2(u64 v) {
    float2 f; asm("mov.b64 {%0,%1}, %2;" : "=f"(f.x), "=f"(f.y) : "l"(v)); return f;
}
__device__ __forceinline__ u64 ffma2(u64 a, u64 b, u64 c) {
    u64 d; asm("fma.rn.f32x2 %0, %1, %2, %3;" : "=l"(d) : "l"(a), "l"(b), "l"(c)); return d;
}
__device__ __forceinline__ u64 fadd2(u64 a, u64 b) {
    u64 d; asm("add.rn.f32x2 %0, %1, %2;" : "=l"(d) : "l"(a), "l"(b)); return d;
}
__device__ __forceinline__ u64 fmul2(u64 a, u64 b) {
    u64 d; asm("mul.rn.f32x2 %0, %1, %2;" : "=l"(d) : "l"(a), "l"(b)); return d;
}

__device__ __forceinline__ uint32_t smem_to_u32(const void* p) {
    uint32_t a;
    asm("{ .reg .u64 t; cvta.to.shared.u64 t, %1; cvt.u32.u64 %0, t; }" : "=r"(a) : "l"(p));
    return a;
}
#define SW128(o) ((o) ^ (((o) >> 3) & 0x70))

__device__ __forceinline__ void ldsm_x4(uint32_t* r, uint32_t addr) {
    asm volatile("ldmatrix.sync.aligned.m8n8.x4.shared.b16 {%0,%1,%2,%3}, [%4];"
                 : "=r"(r[0]), "=r"(r[1]), "=r"(r[2]), "=r"(r[3]) : "r"(addr));
}
__device__ __forceinline__ void mma16816(float* c, const uint32_t* a,
                                         uint32_t b0, uint32_t b1) {
    asm volatile(
        "mma.sync.aligned.m16n8k16.row.col.f32.bf16.bf16.f32 "
        "{%0,%1,%2,%3}, {%4,%5,%6,%7}, {%8,%9}, {%0,%1,%2,%3};"
        : "+f"(c[0]), "+f"(c[1]), "+f"(c[2]), "+f"(c[3])
        : "r"(a[0]), "r"(a[1]), "r"(a[2]), "r"(a[3]), "r"(b0), "r"(b1));
}

// -------- scratch --------
__device__ float g_q [BATCH * S_LEN * EMB];
__device__ float g_k [BATCH * S_LEN * EMB];
__device__ float g_v [BATCH * S_LEN * EMB];
__device__ float g_kg[BATCH * S_LEN * EMB];
__device__ float g_vg[BATCH * S_LEN * EMB];
__device__ float g_qg[BATCH * GLB * EMB];
__device__ __nv_bfloat16 g_xh[BATCH * S_LEN * EMB];
__device__ __nv_bfloat16 g_xl[BATCH * S_LEN * EMB];
__device__ __nv_bfloat16 g_wth[5 * EMB * EMB];
__device__ __nv_bfloat16 g_wtl[5 * EMB * EMB];

// ---------------- prep: x -> bf16 hi/lo ----------------
__global__ __launch_bounds__(256) void convx_kernel(
    const float* __restrict__ x, __nv_bfloat16* __restrict__ xh,
    __nv_bfloat16* __restrict__ xl)
{
    int i = (blockIdx.x * 256 + threadIdx.x) * 4;
    float4 a = *(const float4*)(x + i);
    __nv_bfloat16 h[4], l[4];
    float av[4] = {a.x, a.y, a.z, a.w};
#pragma unroll
    for (int j = 0; j < 4; j++) {
        h[j] = __float2bfloat16(av[j]);
        l[j] = __float2bfloat16(av[j] - __bfloat162float(h[j]));
    }
    *(uint2*)(xh + i) = *(const uint2*)h;
    *(uint2*)(xl + i) = *(const uint2*)l;
}

// ---------------- prep: W -> W^T bf16 hi/lo ----------------
__global__ __launch_bounds__(256) void convw_kernel(
    const float* __restrict__ w0, const float* __restrict__ w1,
    const float* __restrict__ w2, const float* __restrict__ w3,
    const float* __restrict__ w4,
    __nv_bfloat16* __restrict__ wth, __nv_bfloat16* __restrict__ wtl)
{
    __shared__ float tile[32][33];
    int z = blockIdx.z;
    const float* W = (z == 0) ? w0 : (z == 1) ? w1 : (z == 2) ? w2 : (z == 3) ? w3 : w4;
    int kb = blockIdx.y * 32, nb = blockIdx.x * 32;
    int tx = threadIdx.x & 31, ty = threadIdx.x >> 5;   // 32 x 8
    for (int i = ty; i < 32; i += 8)
        tile[i][tx] = W[(size_t)(kb + i) * EMB + nb + tx];
    __syncthreads();
    for (int j = ty; j < 32; j += 8) {
        float a = tile[tx][j];   // W[kb+tx][nb+j]
        __nv_bfloat16 h = __float2bfloat16(a);
        float l = a - __bfloat162float(h);
        size_t o = (size_t)z * EMB * EMB + (size_t)(nb + j) * EMB + kb + tx;
        wth[o] = h;
        wtl[o] = __float2bfloat16(l);
    }
}

// ---------------- mma.sync GEMM for 5 projections ----------------
// CTA: 128(M) x 64(N) tile, K chunks of 64.
// D = ah*wh + ah*wl + al*wh, fp32 accumulators (2-term precision split).
__global__ __launch_bounds__(256) void mma_gemm5_kernel(
    const __nv_bfloat16* __restrict__ xh, const __nv_bfloat16* __restrict__ xl,
    const __nv_bfloat16* __restrict__ wth, const __nv_bfloat16* __restrict__ wtl,
    const float* __restrict__ bq, const float* __restrict__ bk,
    const float* __restrict__ bv, const float* __restrict__ bkg,
    const float* __restrict__ bvg,
    float* q, float* k, float* v, float* kg, float* vg)
{
    __shared__ __align__(128) __nv_bfloat16 sAh[128 * 64];
    __shared__ __align__(128) __nv_bfloat16 sAl[128 * 64];
    __shared__ __align__(128) __nv_bfloat16 sBh[64 * 64];
    __shared__ __align__(128) __nv_bfloat16 sBl[64 * 64];

    int t = threadIdx.x, wid = t >> 5, lane = t & 31;
    int z = blockIdx.z;
    int m0 = blockIdx.y * 128, n0 = blockIdx.x * 64;
    int wm = wid & 3, wn = wid >> 2;    // warp tile: rows wm*32, cols wn*32

    const float* bias; float* Y; float scale;
    switch (z) {
        case 0:  bias = bq;  Y = q;  scale = 0.125f; break;
        case 1:  bias = bk;  Y = k;  scale = 1.f;    break;
        case 2:  bias = bv;  Y = v;  scale = 1.f;    break;
        case 3:  bias = bkg; Y = kg; scale = 1.f;    break;
        default: bias = bvg; Y = vg; scale = 1.f;    break;
    }
    const __nv_bfloat16* Bh = wth + (size_t)z * EMB * EMB;
    const __nv_bfloat16* Bl = wtl + (size_t)z * EMB * EMB;

    uint32_t sAh_u = smem_to_u32(sAh), sAl_u = smem_to_u32(sAl);
    uint32_t sBh_u = smem_to_u32(sBh), sBl_u = smem_to_u32(sBl);

    float acc[2][4][4];
#pragma unroll
    for (int mi = 0; mi < 2; mi++)
#pragma unroll
        for (int ni = 0; ni < 4; ni++)
#pragma unroll
            for (int c = 0; c < 4; c++) acc[mi][ni][c] = 0.f;

    // precomputed swizzled ldmatrix lane offsets (within a 128B-row tile)
    uint32_t a_off[2], b_off[2];
#pragma unroll
    for (int mi = 0; mi < 2; mi++) {
        int row = wm * 32 + mi * 16 + (lane & 15);
        a_off[mi] = (uint32_t)(row * 128) + ((lane >> 4) << 4);
    }
#pragma unroll
    for (int bi = 0; bi < 2; bi++) {
        int row = wn * 32 + bi * 16 + (lane & 15);
        b_off[bi] = (uint32_t)(row * 128) + ((lane >> 4) << 4);
    }

    for (int chunk = 0; chunk < 12; chunk++) {
        int k0 = chunk * 64;
        __syncthreads();   // previous iteration's reads done
#pragma unroll
        for (int i = 0; i < 4; i++) {
            int idx = t + i * 256;
            int r = idx >> 3, u = idx & 7;
            uint32_t sw = SW128((uint32_t)(r * 128 + u * 16));
            size_t goff = (size_t)(m0 + r) * EMB + k0;
            *(uint4*)((char*)sAh + sw) = *((const uint4*)(xh + goff) + u);
            *(uint4*)((char*)sAl + sw) = *((const uint4*)(xl + goff) + u);
        }
#pragma unroll
        for (int i = 0; i < 2; i++) {
            int idx = t + i * 256;
            int r = idx >> 3, u = idx & 7;
            uint32_t sw = SW128((uint32_t)(r * 128 + u * 16));
            size_t goff = (size_t)(n0 + r) * EMB + k0;
            *(uint4*)((char*)sBh + sw) = *((const uint4*)(Bh + goff) + u);
            *(uint4*)((char*)sBl + sw) = *((const uint4*)(Bl + goff) + u);
        }
        __syncthreads();

#pragma unroll
        for (int ks = 0; ks < 4; ks++) {
            uint32_t kb = (uint32_t)(ks * 32);
            uint32_t ah[2][4], al[2][4], bh[2][4], bl[2][4];
#pragma unroll
            for (int mi = 0; mi < 2; mi++) {
                uint32_t sw = SW128(a_off[mi] + kb);
                ldsm_x4(ah[mi], sAh_u + sw);
                ldsm_x4(al[mi], sAl_u + sw);
            }
#pragma unroll
            for (int bi = 0; bi < 2; bi++) {
                uint32_t sw = SW128(b_off[bi] + kb);
                ldsm_x4(bh[bi], sBh_u + sw);
                ldsm_x4(bl[bi], sBl_u + sw);
            }
#pragma unroll
            for (int mi = 0; mi < 2; mi++)
#pragma unroll
                for (int ni = 0; ni < 4; ni++) {
                    int bi = ni >> 1, sel = ni & 1;
                    mma16816(acc[mi][ni], ah[mi], bh[bi][sel], bh[bi][sel + 2]);
                    mma16816(acc[mi][ni], ah[mi], bl[bi][sel], bl[bi][sel + 2]);
                    mma16816(acc[mi][ni], al[mi], bh[bi][sel], bh[bi][sel + 2]);
                }
        }
    }

    // epilogue: bias + scale, direct global stores
    int r = lane >> 2, cp = (lane & 3) * 2;
#pragma unroll
    for (int mi = 0; mi < 2; mi++) {
        int mbase = m0 + wm * 32 + mi * 16;
#pragma unroll
        for (int ni = 0; ni < 4; ni++) {
            int nbase = n0 + wn * 32 + ni * 8 + cp;
            float b0 = bias[nbase], b1 = bias[nbase + 1];
            float2 o0, o1;
            o0.x = (acc[mi][ni][0] + b0) * scale;
            o0.y = (acc[mi][ni][1] + b1) * scale;
            o1.x = (acc[mi][ni][2] + b0) * scale;
            o1.y = (acc[mi][ni][3] + b1) * scale;
            *(float2*)(Y + (size_t)(mbase + r) * EMB + nbase) = o0;
            *(float2*)(Y + (size_t)(mbase + r + 8) * EMB + nbase) = o1;
        }
    }
}

// ---------------- small fp32 GEMM for qg (64 rows) ----------------
__global__ __launch_bounds__(256) void gemm_qg_kernel(
    const float* __restrict__ A, const float* __restrict__ Wm,
    const float* __restrict__ bias, float* __restrict__ Y)
{
    const int N = EMB, K = EMB, M = BATCH * GLB;
    __shared__ float As[8][132];
    __shared__ float Bs[8][68];
    int n0 = blockIdx.x * 64;
    int t = threadIdx.x, tx = t & 15, ty = t >> 4;

    u64 acc2[4][4];
#pragma unroll
    for (int p = 0; p < 4; p++)
#pragma unroll
        for (int c = 0; c < 4; c++) acc2[p][c] = 0ULL;

    int lr = t >> 1, lk = (t & 1) * 4;
    const float* arow = nullptr;
    if (lr < M) {
        int sr = (lr / GLB) * S_LEN + (lr % GLB);
        arow = A + (size_t)sr * K;
    }
    for (int k0 = 0; k0 < K; k0 += 8) {
        float4 av = make_float4(0.f, 0.f, 0.f, 0.f);
        if (arow) av = *(const float4*)(arow + k0 + lk);
        if (t < 128) {
            int kk = t >> 4, nq = (t & 15) << 2;
            *(float4*)&Bs[kk][nq] = *(const float4*)&Wm[(size_t)(k0 + kk) * N + n0 + nq];
        }
        As[lk + 0][lr] = av.x; As[lk + 1][lr] = av.y;
        As[lk + 2][lr] = av.z; As[lk + 3][lr] = av.w;
        __syncthreads();
#pragma unroll
        for (int kk = 0; kk < 8; kk++) {
            ulonglong2 A0 = *(const ulonglong2*)&As[kk][ty << 3];
            ulonglong2 A1 = *(const ulonglong2*)&As[kk][(ty << 3) + 4];
            float4 b4 = *(const float4*)&Bs[kk][tx << 2];
            u64 b0 = dup2(b4.x), b1 = dup2(b4.y), b2 = dup2(b4.z), b3 = dup2(b4.w);
            acc2[0][0] = ffma2(A0.x, b0, acc2[0][0]);
            acc2[0][1] = ffma2(A0.x, b1, acc2[0][1]);
            acc2[0][2] = ffma2(A0.x, b2, acc2[0][2]);
            acc2[0][3] = ffma2(A0.x, b3, acc2[0][3]);
            acc2[1][0] = ffma2(A0.y, b0, acc2[1][0]);
            acc2[1][1] = ffma2(A0.y, b1, acc2[1][1]);
            acc2[1][2] = ffma2(A0.y, b2, acc2[1][2]);
            acc2[1][3] = ffma2(A0.y, b3, acc2[1][3]);
            acc2[2][0] = ffma2(A1.x, b0, acc2[2][0]);
            acc2[2][1] = ffma2(A1.x, b1, acc2[2][1]);
            acc2[2][2] = ffma2(A1.x, b2, acc2[2][2]);
            acc2[2][3] = ffma2(A1.x, b3, acc2[2][3]);
            acc2[3][0] = ffma2(A1.y, b0, acc2[3][0]);
            acc2[3][1] = ffma2(A1.y, b1, acc2[3][1]);
            acc2[3][2] = ffma2(A1.y, b2, acc2[3][2]);
            acc2[3][3] = ffma2(A1.y, b3, acc2[3][3]);
        }
        __syncthreads();
    }
    float4 bi = *(const float4*)&bias[n0 + (tx << 2)];
#pragma unroll
    for (int p = 0; p < 4; p++) {
        float2 vx = up2(acc2[p][0]), vy = up2(acc2[p][1]);
        float2 vz = up2(acc2[p][2]), vw = up2(acc2[p][3]);
        int r0 = (ty << 3) + 2 * p;
        if (r0 < M) {
            float4 o;
            o.x = (vx.x + bi.x) * 0.125f; o.y = (vy.x + bi.y) * 0.125f;
            o.z = (vz.x + bi.z) * 0.125f; o.w = (vw.x + bi.w) * 0.125f;
            *(float4*)&Y[(size_t)r0 * N + n0 + (tx << 2)] = o;
        }
        if (r0 + 1 < M) {
            float4 o;
            o.x = (vx.y + bi.x) * 0.125f; o.y = (vy.y + bi.y) * 0.125f;
            o.z = (vz.y + bi.z) * 0.125f; o.w = (vw.y + bi.w) * 0.125f;
            *(float4*)&Y[(size_t)(r0 + 1) * N + n0 + (tx << 2)] = o;
        }
    }
}

// ---------------- Local (banded + global-key) attention ----------------
__global__ __launch_bounds__(256, 2) void local_attn_kernel(
    const float* __restrict__ q, const float* __restrict__ k,
    const float* __restrict__ v, const int* __restrict__ mask,
    float* __restrict__ out)
{
    __shared__ float ks[QT][LDK];
    __shared__ float vs[QT][LDK];
    __shared__ float sc[QT][36];

    int b = blockIdx.z, h = blockIdx.y;
    int i0 = blockIdx.x * QT;
    int t = threadIdx.x;
    int qi = t >> 3, sub = t & 7;
    int iq = i0 + qi;

    u64 q2[32];
    {
        const ulonglong2* qrow = (const ulonglong2*)
            (q + ((size_t)(b * S_LEN + iq)) * EMB + h * HDIM);
#pragma unroll
        for (int e = 0; e < 16; e++) {
            ulonglong2 t2 = qrow[e];
            q2[e * 2] = t2.x; q2[e * 2 + 1] = t2.y;
        }
    }
    u64 acc2[4] = {0ULL, 0ULL, 0ULL, 0ULL};
    float m_run = -1e30f, l_run = 0.f;

    int lo = i0 - WIN; if (lo < 0) lo = 0;
    int hi = i0 + QT - 1 + WIN; if (hi > S_LEN - 1) hi = S_LEN - 1;
    int wstart = lo & ~(QT - 1);
    int nwin = (hi - wstart) / QT + 1;

    for (int ci = -1; ci < nwin; ci++) {
        bool gl = (ci < 0);
        int kstart = gl ? 0 : wstart + ci * QT;

        __syncthreads();
        for (int u = t; u < QT * 16; u += 256) {
            int r = u >> 4, c = (u & 15) << 2;
            int p = kstart + r;
            float4 kv4 = make_float4(0.f, 0.f, 0.f, 0.f);
            float4 vv4 = make_float4(0.f, 0.f, 0.f, 0.f);
            if (p < S_LEN) {
                size_t off = ((size_t)(b * S_LEN + p)) * EMB + h * HDIM + c;
                kv4 = *(const float4*)(k + off);
                vv4 = *(const float4*)(v + off);
            }
            *(float4*)&ks[r][c] = kv4;
            *(float4*)&vs[r][c] = vv4;
        }
        __syncthreads();

        float sv[4];
#pragma unroll
        for (int u = 0; u < 4; u++) {
            int j = sub * 4 + u;
            int p = kstart + j;
            bool valid = gl || (p < S_LEN && p >= iq - WIN && p <= iq + WIN);
            float s = -1e30f;
            if (valid) {
                const ulonglong2* kr = (const ulonglong2*)&ks[j][0];
                u64 s0 = 0ULL, s1 = 0ULL, s2 = 0ULL, s3 = 0ULL;
#pragma unroll
                for (int e = 0; e < 16; e += 2) {
                    ulonglong2 ka = kr[e];
                    ulonglong2 kb = kr[e + 1];
                    s0 = ffma2(q2[e * 2],     ka.x, s0);
                    s1 = ffma2(q2[e * 2 + 1], ka.y, s1);
                    s2 = ffma2(q2[e * 2 + 2], kb.x, s2);
                    s3 = ffma2(q2[e * 2 + 3], kb.y, s3);
                }
                float2 r2 = up2(fadd2(fadd2(s0, s1), fadd2(s2, s3)));
                float d = r2.x + r2.y;
                if (!gl && mask[b * S_LEN + p]) d -= 10000.f;
                s = d;
            }
            sv[u] = s;
        }
        float cm = fmaxf(fmaxf(sv[0], sv[1]), fmaxf(sv[2], sv[3]));
        cm = fmaxf(cm, __shfl_xor_sync(0xffffffffu, cm, 1));
        cm = fmaxf(cm, __shfl_xor_sync(0xffffffffu, cm, 2));
        cm = fmaxf(cm, __shfl_xor_sync(0xffffffffu, cm, 4));
        float m_new = fmaxf(m_run, cm);
        float rsc = __expf(m_run - m_new);
        float psum = 0.f;
#pragma unroll
        for (int u = 0; u < 4; u++) {
            float e = __expf(sv[u] - m_new);
            sc[qi][sub * 4 + u] = e;
            psum += e;
        }
        psum += __shfl_xor_sync(0xffffffffu, psum, 1);
        psum += __shfl_xor_sync(0xffffffffu, psum, 2);
        psum += __shfl_xor_sync(0xffffffffu, psum, 4);
        l_run = l_run * rsc + psum;
        m_run = m_new;
        __syncwarp();

        u64 rb = dup2(rsc);
#pragma unroll
        for (int d = 0; d < 4; d++) acc2[d] = fmul2(acc2[d], rb);
#pragma unroll 4
        for (int j = 0; j < QT; j++) {
            u64 eb = dup2(sc[qi][j]);
            ulonglong2 v0 = *(const ulonglong2*)&vs[j][sub * 4];
            ulonglong2 v1 = *(const ulonglong2*)&vs[j][sub * 4 + 32];
            acc2[0] = ffma2(eb, v0.x, acc2[0]);
            acc2[1] = ffma2(eb, v0.y, acc2[1]);
            acc2[2] = ffma2(eb, v1.x, acc2[2]);
            acc2[3] = ffma2(eb, v1.y, acc2[3]);
        }
    }

    float inv = 1.f / l_run;
    size_t ob = ((size_t)(b * S_LEN + iq)) * EMB + h * HDIM;
    float2 a0 = up2(acc2[0]), a1 = up2(acc2[1]);
    float2 a2 = up2(acc2[2]), a3 = up2(acc2[3]);
    float4 o0 = make_float4(a0.x * inv, a0.y * inv, a1.x * inv, a1.y * inv);
    float4 o1 = make_float4(a2.x * inv, a2.y * inv, a3.x * inv, a3.y * inv);
    *(float4*)&out[ob + sub * 4]      = o0;
    *(float4*)&out[ob + 32 + sub * 4] = o1;
}

// ---------------- Global rows (i < G): full attention ----------------
__global__ __launch_bounds__(256) void global_attn_kernel(
    const float* __restrict__ qg, const float* __restrict__ kg,
    const float* __restrict__ vg, float* __restrict__ out)
{
    __shared__ float sc[S_LEN];
    __shared__ float qv[64];
    __shared__ float red[8];
    __shared__ float part[8][64];

    int b = blockIdx.z, h = blockIdx.y, g = blockIdx.x;
    int t = threadIdx.x, w = t >> 5, lane = t & 31;

    if (t < 16)
        *(float4*)&qv[t * 4] =
            *(const float4*)&qg[((size_t)(b * GLB + g)) * EMB + h * HDIM + t * 4];
    __syncthreads();
    float qa = qv[lane], qb = qv[lane + 32];

    for (int s0 = w * 4; s0 < S_LEN; s0 += 32) {
        const float* kr = kg + ((size_t)(b * S_LEN + s0)) * EMB + h * HDIM;
        float p0 = qa * kr[lane]           + qb * kr[lane + 32];
        float p1 = qa * kr[EMB + lane]     + qb * kr[EMB + lane + 32];
        float p2 = qa * kr[2 * EMB + lane] + qb * kr[2 * EMB + lane + 32];
        float p3 = qa * kr[3 * EMB + lane] + qb * kr[3 * EMB + lane + 32];
#pragma unroll
        for (int o = 16; o > 0; o >>= 1) {
            p0 += __shfl_xor_sync(0xffffffffu, p0, o);
            p1 += __shfl_xor_sync(0xffffffffu, p1, o);
            p2 += __shfl_xor_sync(0xffffffffu, p2, o);
            p3 += __shfl_xor_sync(0xffffffffu, p3, o);
        }
        if (lane == 0) {
            sc[s0] = p0; sc[s0 + 1] = p1; sc[s0 + 2] = p2; sc[s0 + 3] = p3;
        }
    }
    __syncthreads();

    float mx = -1e30f;
    for (int s = t; s < S_LEN; s += 256) mx = fmaxf(mx, sc[s]);
#pragma unroll
    for (int o = 16; o > 0; o >>= 1) mx = fmaxf(mx, __shfl_xor_sync(0xffffffffu, mx, o));
    if (lane == 0) red[w] = mx;
    __syncthreads();
    mx = red[0];
#pragma unroll
    for (int i = 1; i < 8; i++) mx = fmaxf(mx, red[i]);
    __syncthreads();

    float ps = 0.f;
    for (int s = t; s < S_LEN; s += 256) {
        float e = __expf(sc[s] - mx);
        sc[s] = e;
        ps += e;
    }
#pragma unroll
    for (int o = 16; o > 0; o >>= 1) ps += __shfl_xor_sync(0xffffffffu, ps, o);
    if (lane == 0) red[w] = ps;
    __syncthreads();
    float l = 0.f;
#pragma unroll
    for (int i = 0; i < 8; i++) l += red[i];

    float a0 = 0.f, a1 = 0.f;
    for (int s = w * 2; s < S_LEN; s += 16) {
        float e0 = sc[s], e1 = sc[s + 1];
        const float* vr = vg + ((size_t)(b * S_LEN + s)) * EMB + h * HDIM;
        a0 += e0 * vr[lane]      + e1 * vr[EMB + lane];
        a1 += e0 * vr[lane + 32] + e1 * vr[EMB + lane + 32];
    }
    part[w][lane] = a0;
    part[w][lane + 32] = a1;
    __syncthreads();

    if (t < 64) {
        float sum = 0.f;
#pragma unroll
        for (int ww = 0; ww < 8; ww++) sum += part[ww][t];
        out[((size_t)(b * S_LEN + g)) * EMB + h * HDIM + t] = sum / l;
    }
}

// ---------------- launch ----------------
extern "C" void kernel_launch(void* const* d_in, const int* in_sizes, int n_in,
                              void* d_out, int out_size)
{
    (void)n_in; (void)out_size;
    int base = (in_sizes[2] == EMB * EMB) ? 2 : 3;

    const float* x    = (const float*)d_in[0];
    const int*   mask = (const int*)d_in[1];
    const float* wq   = (const float*)d_in[base + 0];
    const float* bq   = (const float*)d_in[base + 1];
    const float* wk   = (const float*)d_in[base + 2];
    const float* bk   = (const float*)d_in[base + 3];
    const float* wv   = (const float*)d_in[base + 4];
    const float* bv   = (const float*)d_in[base + 5];
    const float* wqg  = (const float*)d_in[base + 6];
    const float* bqg  = (const float*)d_in[base + 7];
    const float* wkg  = (const float*)d_in[base + 8];
    const float* bkg  = (const float*)d_in[base + 9];
    const float* wvg  = (const float*)d_in[base + 10];
    const float* bvg  = (const float*)d_in[base + 11];
    float* out = (float*)d_out;

    float *q, *k, *v, *kg, *vg, *qg;
    __nv_bfloat16 *xh, *xl, *wth, *wtl;
    cudaGetSymbolAddress((void**)&q,   g_q);
    cudaGetSymbolAddress((void**)&k,   g_k);
    cudaGetSymbolAddress((void**)&v,   g_v);
    cudaGetSymbolAddress((void**)&kg,  g_kg);
    cudaGetSymbolAddress((void**)&vg,  g_vg);
    cudaGetSymbolAddress((void**)&qg,  g_qg);
    cudaGetSymbolAddress((void**)&xh,  g_xh);
    cudaGetSymbolAddress((void**)&xl,  g_xl);
    cudaGetSymbolAddress((void**)&wth, g_wth);
    cudaGetSymbolAddress((void**)&wtl, g_wtl);

    convx_kernel<<<(BATCH * S_LEN * EMB) / (256 * 4), 256>>>(x, xh, xl);
    convw_kernel<<<dim3(EMB / 32, EMB / 32, 5), 256>>>(wq, wk, wv, wkg, wvg, wth, wtl);
    mma_gemm5_kernel<<<dim3(EMB / 64, BATCH * S_LEN / 128, 5), 256>>>(
        xh, xl, wth, wtl, bq, bk, bv, bkg, bvg, q, k, v, kg, vg);
    gemm_qg_kernel<<<dim3(EMB / 64, 1, 1), 256>>>(x, wqg, bqg, qg);
    local_attn_kernel<<<dim3(S_LEN / QT, NH, BATCH), 256>>>(q, k, v, mask, out);
    global_attn_kernel<<<dim3(GLB, NH, BATCH), 256>>>(qg, kg, vg, out);
}

// round 5
// speedup vs baseline: 3.6610x; 2.7408x over previous
#include <cuda_runtime.h>
#include <cuda_bf16.h>
#include <cstdint>

#define S_LEN 4096
#define BATCH 2
#define EMB   768
#define NH    12
#define HDIM  64
#define WIN   256
#define GLB   32
#define QT    32

typedef unsigned long long u64;

__device__ __forceinline__ uint32_t smem_to_u32(const void* p) {
    uint32_t a;
    asm("{ .reg .u64 t; cvta.to.shared.u64 t, %1; cvt.u32.u64 %0, t; }" : "=r"(a) : "l"(p));
    return a;
}
#define SW128(o) ((o) ^ (((o) >> 3) & 0x70))

__device__ __forceinline__ void ldsm_x4(uint32_t* r, uint32_t addr) {
    asm volatile("ldmatrix.sync.aligned.m8n8.x4.shared.b16 {%0,%1,%2,%3}, [%4];"
                 : "=r"(r[0]), "=r"(r[1]), "=r"(r[2]), "=r"(r[3]) : "r"(addr));
}
__device__ __forceinline__ void ldsm_x2(uint32_t* r, uint32_t addr) {
    asm volatile("ldmatrix.sync.aligned.m8n8.x2.shared.b16 {%0,%1}, [%2];"
                 : "=r"(r[0]), "=r"(r[1]) : "r"(addr));
}
__device__ __forceinline__ void ldsm_x4t(uint32_t* r, uint32_t addr) {
    asm volatile("ldmatrix.sync.aligned.m8n8.x4.trans.shared.b16 {%0,%1,%2,%3}, [%4];"
                 : "=r"(r[0]), "=r"(r[1]), "=r"(r[2]), "=r"(r[3]) : "r"(addr));
}
__device__ __forceinline__ void mma16816(float* c, const uint32_t* a,
                                         uint32_t b0, uint32_t b1) {
    asm volatile(
        "mma.sync.aligned.m16n8k16.row.col.f32.bf16.bf16.f32 "
        "{%0,%1,%2,%3}, {%4,%5,%6,%7}, {%8,%9}, {%0,%1,%2,%3};"
        : "+f"(c[0]), "+f"(c[1]), "+f"(c[2]), "+f"(c[3])
        : "r"(a[0]), "r"(a[1]), "r"(a[2]), "r"(a[3]), "r"(b0), "r"(b1));
}

// -------- scratch --------
__device__ float g_kg[BATCH * S_LEN * EMB];
__device__ float g_vg[BATCH * S_LEN * EMB];
__device__ float g_qg[BATCH * GLB * EMB];
__device__ __nv_bfloat16 g_xh[BATCH * S_LEN * EMB];
__device__ __nv_bfloat16 g_xl[BATCH * S_LEN * EMB];
__device__ __nv_bfloat16 g_wth[6 * EMB * EMB];
__device__ __nv_bfloat16 g_wtl[6 * EMB * EMB];
__device__ __nv_bfloat16 g_qh[BATCH * S_LEN * EMB];
__device__ __nv_bfloat16 g_ql[BATCH * S_LEN * EMB];
__device__ __nv_bfloat16 g_kh[BATCH * S_LEN * EMB];
__device__ __nv_bfloat16 g_kl[BATCH * S_LEN * EMB];
__device__ __nv_bfloat16 g_vh[BATCH * S_LEN * EMB];
__device__ __nv_bfloat16 g_vl[BATCH * S_LEN * EMB];

// ---------------- prep: x -> bf16 hi/lo ----------------
__global__ __launch_bounds__(256) void convx_kernel(
    const float* __restrict__ x, __nv_bfloat16* __restrict__ xh,
    __nv_bfloat16* __restrict__ xl)
{
    int i = (blockIdx.x * 256 + threadIdx.x) * 4;
    float4 a = *(const float4*)(x + i);
    __nv_bfloat16 h[4], l[4];
    float av[4] = {a.x, a.y, a.z, a.w};
#pragma unroll
    for (int j = 0; j < 4; j++) {
        h[j] = __float2bfloat16(av[j]);
        l[j] = __float2bfloat16(av[j] - __bfloat162float(h[j]));
    }
    *(uint2*)(xh + i) = *(const uint2*)h;
    *(uint2*)(xl + i) = *(const uint2*)l;
}

// ---------------- prep: W -> W^T bf16 hi/lo (6 weights) ----------------
__global__ __launch_bounds__(256) void convw_kernel(
    const float* __restrict__ w0, const float* __restrict__ w1,
    const float* __restrict__ w2, const float* __restrict__ w3,
    const float* __restrict__ w4, const float* __restrict__ w5,
    __nv_bfloat16* __restrict__ wth, __nv_bfloat16* __restrict__ wtl)
{
    __shared__ float tile[32][33];
    int z = blockIdx.z;
    const float* W = (z == 0) ? w0 : (z == 1) ? w1 : (z == 2) ? w2 :
                     (z == 3) ? w3 : (z == 4) ? w4 : w5;
    int kb = blockIdx.y * 32, nb = blockIdx.x * 32;
    int tx = threadIdx.x & 31, ty = threadIdx.x >> 5;
    for (int i = ty; i < 32; i += 8)
        tile[i][tx] = W[(size_t)(kb + i) * EMB + nb + tx];
    __syncthreads();
    for (int j = ty; j < 32; j += 8) {
        float a = tile[tx][j];
        __nv_bfloat16 h = __float2bfloat16(a);
        float l = a - __bfloat162float(h);
        size_t o = (size_t)z * EMB * EMB + (size_t)(nb + j) * EMB + kb + tx;
        wth[o] = h;
        wtl[o] = __float2bfloat16(l);
    }
}

// ---------------- mma.sync GEMM for 6 projections ----------------
// z=0..2 (q,k,v): outputs bf16 hi/lo.  z=3,4 (kg,vg): fp32.  z=5 (qg): fp32, 64 rows.
__global__ __launch_bounds__(256) void mma_gemm6_kernel(
    const __nv_bfloat16* __restrict__ xh, const __nv_bfloat16* __restrict__ xl,
    const __nv_bfloat16* __restrict__ wth, const __nv_bfloat16* __restrict__ wtl,
    const float* __restrict__ bq, const float* __restrict__ bk,
    const float* __restrict__ bv, const float* __restrict__ bkg,
    const float* __restrict__ bvg, const float* __restrict__ bqg,
    __nv_bfloat16* qh, __nv_bfloat16* ql, __nv_bfloat16* kh, __nv_bfloat16* kl,
    __nv_bfloat16* vh, __nv_bfloat16* vl,
    float* kg, float* vg, float* qg)
{
    __shared__ __align__(128) __nv_bfloat16 sAh[128 * 64];
    __shared__ __align__(128) __nv_bfloat16 sAl[128 * 64];
    __shared__ __align__(128) __nv_bfloat16 sBh[64 * 64];
    __shared__ __align__(128) __nv_bfloat16 sBl[64 * 64];

    int z = blockIdx.z;
    if (z == 5 && blockIdx.y > 0) return;
    int t = threadIdx.x, wid = t >> 5, lane = t & 31;
    int m0 = blockIdx.y * 128, n0 = blockIdx.x * 64;
    int wm = wid & 3, wn = wid >> 2;

    const float* bias;
    switch (z) {
        case 0:  bias = bq;  break;
        case 1:  bias = bk;  break;
        case 2:  bias = bv;  break;
        case 3:  bias = bkg; break;
        case 4:  bias = bvg; break;
        default: bias = bqg; break;
    }
    float scale = (z == 0 || z == 5) ? 0.125f : 1.0f;
    const __nv_bfloat16* Bh = wth + (size_t)z * EMB * EMB;
    const __nv_bfloat16* Bl = wtl + (size_t)z * EMB * EMB;

    uint32_t sAh_u = smem_to_u32(sAh), sAl_u = smem_to_u32(sAl);
    uint32_t sBh_u = smem_to_u32(sBh), sBl_u = smem_to_u32(sBl);

    float acc[2][4][4];
#pragma unroll
    for (int mi = 0; mi < 2; mi++)
#pragma unroll
        for (int ni = 0; ni < 4; ni++)
#pragma unroll
            for (int c = 0; c < 4; c++) acc[mi][ni][c] = 0.f;

    uint32_t a_off[2], b_off[2];
#pragma unroll
    for (int mi = 0; mi < 2; mi++) {
        int row = wm * 32 + mi * 16 + (lane & 15);
        a_off[mi] = (uint32_t)(row * 128) + ((lane >> 4) << 4);
    }
#pragma unroll
    for (int bi = 0; bi < 2; bi++) {
        int row = wn * 32 + bi * 16 + (lane & 15);
        b_off[bi] = (uint32_t)(row * 128) + ((lane >> 4) << 4);
    }

    for (int chunk = 0; chunk < 12; chunk++) {
        int k0 = chunk * 64;
        __syncthreads();
#pragma unroll
        for (int i = 0; i < 4; i++) {
            int idx = t + i * 256;
            int r = idx >> 3, u = idx & 7;
            uint32_t sw = SW128((uint32_t)(r * 128 + u * 16));
            size_t arow;
            if (z == 5) {
                int rr = r & 63;
                arow = (size_t)((rr >> 5) * S_LEN + (rr & 31));
            } else {
                arow = (size_t)(m0 + r);
            }
            size_t goff = arow * EMB + k0;
            *(uint4*)((char*)sAh + sw) = *((const uint4*)(xh + goff) + u);
            *(uint4*)((char*)sAl + sw) = *((const uint4*)(xl + goff) + u);
        }
#pragma unroll
        for (int i = 0; i < 2; i++) {
            int idx = t + i * 256;
            int r = idx >> 3, u = idx & 7;
            uint32_t sw = SW128((uint32_t)(r * 128 + u * 16));
            size_t goff = (size_t)(n0 + r) * EMB + k0;
            *(uint4*)((char*)sBh + sw) = *((const uint4*)(Bh + goff) + u);
            *(uint4*)((char*)sBl + sw) = *((const uint4*)(Bl + goff) + u);
        }
        __syncthreads();

#pragma unroll
        for (int ks = 0; ks < 4; ks++) {
            uint32_t kb = (uint32_t)(ks * 32);
            uint32_t ah[2][4], al[2][4], bh[2][4], bl[2][4];
#pragma unroll
            for (int mi = 0; mi < 2; mi++) {
                uint32_t sw = SW128(a_off[mi] + kb);
                ldsm_x4(ah[mi], sAh_u + sw);
                ldsm_x4(al[mi], sAl_u + sw);
            }
#pragma unroll
            for (int bi = 0; bi < 2; bi++) {
                uint32_t sw = SW128(b_off[bi] + kb);
                ldsm_x4(bh[bi], sBh_u + sw);
                ldsm_x4(bl[bi], sBl_u + sw);
            }
#pragma unroll
            for (int mi = 0; mi < 2; mi++)
#pragma unroll
                for (int ni = 0; ni < 4; ni++) {
                    int bi = ni >> 1, sel = ni & 1;
                    mma16816(acc[mi][ni], ah[mi], bh[bi][sel], bh[bi][sel + 2]);
                    mma16816(acc[mi][ni], ah[mi], bl[bi][sel], bl[bi][sel + 2]);
                    mma16816(acc[mi][ni], al[mi], bh[bi][sel], bh[bi][sel + 2]);
                }
        }
    }

    int r = lane >> 2, cp = (lane & 3) * 2;
    if (z < 3) {
        __nv_bfloat16 *Yh, *Yl;
        if (z == 0)      { Yh = qh; Yl = ql; }
        else if (z == 1) { Yh = kh; Yl = kl; }
        else             { Yh = vh; Yl = vl; }
#pragma unroll
        for (int mi = 0; mi < 2; mi++) {
            int mbase = m0 + wm * 32 + mi * 16;
#pragma unroll
            for (int ni = 0; ni < 4; ni++) {
                int nbase = n0 + wn * 32 + ni * 8 + cp;
                float b0 = bias[nbase], b1 = bias[nbase + 1];
#pragma unroll
                for (int hr = 0; hr < 2; hr++) {
                    int row = mbase + r + hr * 8;
                    float v0 = (acc[mi][ni][hr * 2 + 0] + b0) * scale;
                    float v1 = (acc[mi][ni][hr * 2 + 1] + b1) * scale;
                    __nv_bfloat16 h0 = __float2bfloat16(v0);
                    __nv_bfloat16 h1 = __float2bfloat16(v1);
                    __nv_bfloat16 l0 = __float2bfloat16(v0 - __bfloat162float(h0));
                    __nv_bfloat16 l1 = __float2bfloat16(v1 - __bfloat162float(h1));
                    __nv_bfloat162 ph; ph.x = h0; ph.y = h1;
                    __nv_bfloat162 pl; pl.x = l0; pl.y = l1;
                    *(__nv_bfloat162*)(Yh + (size_t)row * EMB + nbase) = ph;
                    *(__nv_bfloat162*)(Yl + (size_t)row * EMB + nbase) = pl;
                }
            }
        }
    } else {
        float* Y = (z == 3) ? kg : (z == 4) ? vg : qg;
#pragma unroll
        for (int mi = 0; mi < 2; mi++) {
            int mbase = m0 + wm * 32 + mi * 16;
#pragma unroll
            for (int ni = 0; ni < 4; ni++) {
                int nbase = n0 + wn * 32 + ni * 8 + cp;
                float b0 = bias[nbase], b1 = bias[nbase + 1];
#pragma unroll
                for (int hr = 0; hr < 2; hr++) {
                    int row = mbase + r + hr * 8;
                    if (z == 5 && row >= BATCH * GLB) continue;
                    float2 o;
                    o.x = (acc[mi][ni][hr * 2 + 0] + b0) * scale;
                    o.y = (acc[mi][ni][hr * 2 + 1] + b1) * scale;
                    *(float2*)(Y + (size_t)row * EMB + nbase) = o;
                }
            }
        }
    }
}

// ---------------- Local attention, tensor-core flash style ----------------
__global__ __launch_bounds__(256) void local_attn_mma(
    const __nv_bfloat16* __restrict__ qh, const __nv_bfloat16* __restrict__ ql,
    const __nv_bfloat16* __restrict__ kh, const __nv_bfloat16* __restrict__ kl,
    const __nv_bfloat16* __restrict__ vh, const __nv_bfloat16* __restrict__ vl,
    const int* __restrict__ mask, float* __restrict__ out)
{
    __shared__ __align__(128) __nv_bfloat16 sQh[32 * 64], sQl[32 * 64];
    __shared__ __align__(128) __nv_bfloat16 sKh[32 * 64], sKl[32 * 64];
    __shared__ __align__(128) __nv_bfloat16 sVh[32 * 64], sVl[32 * 64];
    __shared__ float sc[32][36];
    __shared__ __align__(16) __nv_bfloat16 pbh[32 * 40], pbl[32 * 40];
    __shared__ float rs[32], ls[32];
    __shared__ int msk[32];

    int b = blockIdx.z, h = blockIdx.y, i0 = blockIdx.x * QT;
    int t = threadIdx.x, w = t >> 5, lane = t & 31;
    int qi = t >> 3, sub = t & 7;
    int iq = i0 + qi;

    uint32_t uQh = smem_to_u32(sQh), uQl = smem_to_u32(sQl);
    uint32_t uKh = smem_to_u32(sKh), uKl = smem_to_u32(sKl);
    uint32_t uVh = smem_to_u32(sVh), uVl = smem_to_u32(sVl);
    uint32_t uPh = smem_to_u32(pbh), uPl = smem_to_u32(pbl);

    // load Q tile (persistent)
    {
        int r = t >> 3, u = t & 7;
        size_t g = ((size_t)(b * S_LEN + i0 + r)) * EMB + h * HDIM + u * 8;
        uint32_t sw = SW128((uint32_t)(r * 128 + u * 16));
        *(uint4*)((char*)sQh + sw) = *(const uint4*)(qh + g);
        *(uint4*)((char*)sQl + sw) = *(const uint4*)(ql + g);
    }

    int wm = w & 1;        // QK m-tile / PV m-tile
    int wn = w >> 1;       // QK n-tile (keys), PV dim pair (pd)
    uint32_t aoff = (uint32_t)((wm * 16 + (lane & 15)) * 128 + ((lane >> 4) << 4));
    uint32_t boff = (uint32_t)((wn * 8 + (lane & 7)) * 128 + (((lane >> 3) & 1) << 4));
    uint32_t poff = (uint32_t)((wm * 16 + (lane & 15)) * 80 + ((lane >> 4) << 4));
    int vtile = lane >> 3, vrow = lane & 7;
    uint32_t voff = (uint32_t)(((vtile & 1) * 8 + vrow) * 128 +
                               wn * 32 + ((vtile >> 1) << 4));

    float oacc[2][4] = {{0.f, 0.f, 0.f, 0.f}, {0.f, 0.f, 0.f, 0.f}};
    float m_run = -1e30f, l_run = 0.f;

    int lo = i0 - WIN; if (lo < 0) lo = 0;
    int hi = i0 + QT - 1 + WIN; if (hi > S_LEN - 1) hi = S_LEN - 1;
    int wstart = lo & ~(QT - 1);
    int nwin = (hi - wstart) / QT + 1;

    for (int ci = -1; ci < nwin; ci++) {
        bool gl = (ci < 0);
        int kstart = gl ? 0 : wstart + ci * QT;

        __syncthreads();
        {
            int r = t >> 3, u = t & 7;
            int p = kstart + r;
            uint32_t sw = SW128((uint32_t)(r * 128 + u * 16));
            uint4 z4 = make_uint4(0, 0, 0, 0);
            uint4 akh = z4, akl = z4, avh = z4, avl = z4;
            if (p < S_LEN) {
                size_t g = ((size_t)(b * S_LEN + p)) * EMB + h * HDIM + u * 8;
                akh = *(const uint4*)(kh + g);
                akl = *(const uint4*)(kl + g);
                avh = *(const uint4*)(vh + g);
                avl = *(const uint4*)(vl + g);
            }
            *(uint4*)((char*)sKh + sw) = akh;
            *(uint4*)((char*)sKl + sw) = akl;
            *(uint4*)((char*)sVh + sw) = avh;
            *(uint4*)((char*)sVl + sw) = avl;
            if (t < 32) {
                int p2 = kstart + t;
                msk[t] = (p2 < S_LEN) ? mask[b * S_LEN + p2] : 0;
            }
        }
        __syncthreads();

        // QK: warp computes m16(wm) x n8(wn) scores, K=64, 3-term split
        {
            float f[4] = {0.f, 0.f, 0.f, 0.f};
#pragma unroll
            for (int ks = 0; ks < 4; ks++) {
                uint32_t kb = (uint32_t)(ks * 32);
                uint32_t a0[4], a1[4], b0[2], b1[2];
                ldsm_x4(a0, uQh + SW128(aoff + kb));
                ldsm_x4(a1, uQl + SW128(aoff + kb));
                ldsm_x2(b0, uKh + SW128(boff + kb));
                ldsm_x2(b1, uKl + SW128(boff + kb));
                mma16816(f, a0, b0[0], b0[1]);
                mma16816(f, a0, b1[0], b1[1]);
                mma16816(f, a1, b0[0], b0[1]);
            }
            int r = wm * 16 + (lane >> 2), c = wn * 8 + (lane & 3) * 2;
            *(float2*)&sc[r][c]     = make_float2(f[0], f[1]);
            *(float2*)&sc[r + 8][c] = make_float2(f[2], f[3]);
        }
        __syncthreads();

        // scalar online softmax (8 threads per query)
        {
            float4 s4 = *(float4*)&sc[qi][sub * 4];
            float sv[4] = {s4.x, s4.y, s4.z, s4.w};
            if (!gl) {
#pragma unroll
                for (int u2 = 0; u2 < 4; u2++) {
                    int j = sub * 4 + u2, p = kstart + j;
                    bool valid = (p < S_LEN) && (p >= iq - WIN) && (p <= iq + WIN);
                    if (!valid) sv[u2] = -1e30f;
                    else if (msk[j]) sv[u2] -= 10000.f;
                }
            }
            float cm = fmaxf(fmaxf(sv[0], sv[1]), fmaxf(sv[2], sv[3]));
            cm = fmaxf(cm, __shfl_xor_sync(0xffffffffu, cm, 1));
            cm = fmaxf(cm, __shfl_xor_sync(0xffffffffu, cm, 2));
            cm = fmaxf(cm, __shfl_xor_sync(0xffffffffu, cm, 4));
            float m_new = fmaxf(m_run, cm);
            float rsc = __expf(m_run - m_new);
            float psum = 0.f;
            __nv_bfloat16 eh[4], el[4];
#pragma unroll
            for (int u2 = 0; u2 < 4; u2++) {
                float e = __expf(sv[u2] - m_new);
                psum += e;
                eh[u2] = __float2bfloat16(e);
                el[u2] = __float2bfloat16(e - __bfloat162float(eh[u2]));
            }
            psum += __shfl_xor_sync(0xffffffffu, psum, 1);
            psum += __shfl_xor_sync(0xffffffffu, psum, 2);
            psum += __shfl_xor_sync(0xffffffffu, psum, 4);
            l_run = l_run * rsc + psum;
            m_run = m_new;
            *(uint2*)(pbh + qi * 40 + sub * 4) = *(const uint2*)eh;
            *(uint2*)(pbl + qi * 40 + sub * 4) = *(const uint2*)el;
            if (sub == 0) rs[qi] = rsc;
        }
        __syncthreads();

        // PV: warp accumulates m16(wm) x dims [wn*16, wn*16+15]
        {
            float r0 = rs[wm * 16 + (lane >> 2)];
            float r1 = rs[wm * 16 + 8 + (lane >> 2)];
#pragma unroll
            for (int ni = 0; ni < 2; ni++) {
                oacc[ni][0] *= r0; oacc[ni][1] *= r0;
                oacc[ni][2] *= r1; oacc[ni][3] *= r1;
            }
#pragma unroll
            for (int ks = 0; ks < 2; ks++) {
                uint32_t ap0[4], ap1[4], bv0[4], bv1[4];
                ldsm_x4(ap0, uPh + poff + ks * 32);
                ldsm_x4(ap1, uPl + poff + ks * 32);
                uint32_t va = SW128(voff + (uint32_t)(ks * 2048));
                ldsm_x4t(bv0, uVh + va);
                ldsm_x4t(bv1, uVl + va);
                mma16816(oacc[0], ap0, bv0[0], bv0[1]);
                mma16816(oacc[0], ap0, bv1[0], bv1[1]);
                mma16816(oacc[0], ap1, bv0[0], bv0[1]);
                mma16816(oacc[1], ap0, bv0[2], bv0[3]);
                mma16816(oacc[1], ap0, bv1[2], bv1[3]);
                mma16816(oacc[1], ap1, bv0[2], bv0[3]);
            }
        }
    }

    if (sub == 0) ls[qi] = l_run;
    __syncthreads();
    {
        float i0v = 1.f / ls[wm * 16 + (lane >> 2)];
        float i1v = 1.f / ls[wm * 16 + 8 + (lane >> 2)];
        int r = wm * 16 + (lane >> 2);
#pragma unroll
        for (int ni = 0; ni < 2; ni++) {
            int c = wn * 16 + ni * 8 + (lane & 3) * 2;
            size_t o0 = ((size_t)(b * S_LEN + i0 + r)) * EMB + h * HDIM + c;
            size_t o1 = ((size_t)(b * S_LEN + i0 + r + 8)) * EMB + h * HDIM + c;
            float2 v0; v0.x = oacc[ni][0] * i0v; v0.y = oacc[ni][1] * i0v;
            float2 v1; v1.x = oacc[ni][2] * i1v; v1.y = oacc[ni][3] * i1v;
            *(float2*)(out + o0) = v0;
            *(float2*)(out + o1) = v1;
        }
    }
}

// ---------------- Global rows (i < G): full attention ----------------
__global__ __launch_bounds__(256) void global_attn_kernel(
    const float* __restrict__ qg, const float* __restrict__ kg,
    const float* __restrict__ vg, float* __restrict__ out)
{
    __shared__ float sc[S_LEN];
    __shared__ float qv[64];
    __shared__ float red[8];
    __shared__ float part[8][64];

    int b = blockIdx.z, h = blockIdx.y, g = blockIdx.x;
    int t = threadIdx.x, w = t >> 5, lane = t & 31;

    if (t < 16)
        *(float4*)&qv[t * 4] =
            *(const float4*)&qg[((size_t)(b * GLB + g)) * EMB + h * HDIM + t * 4];
    __syncthreads();
    float qa = qv[lane], qb = qv[lane + 32];

    for (int s0 = w * 4; s0 < S_LEN; s0 += 32) {
        const float* kr = kg + ((size_t)(b * S_LEN + s0)) * EMB + h * HDIM;
        float p0 = qa * kr[lane]           + qb * kr[lane + 32];
        float p1 = qa * kr[EMB + lane]     + qb * kr[EMB + lane + 32];
        float p2 = qa * kr[2 * EMB + lane] + qb * kr[2 * EMB + lane + 32];
        float p3 = qa * kr[3 * EMB + lane] + qb * kr[3 * EMB + lane + 32];
#pragma unroll
        for (int o = 16; o > 0; o >>= 1) {
            p0 += __shfl_xor_sync(0xffffffffu, p0, o);
            p1 += __shfl_xor_sync(0xffffffffu, p1, o);
            p2 += __shfl_xor_sync(0xffffffffu, p2, o);
            p3 += __shfl_xor_sync(0xffffffffu, p3, o);
        }
        if (lane == 0) {
            sc[s0] = p0; sc[s0 + 1] = p1; sc[s0 + 2] = p2; sc[s0 + 3] = p3;
        }
    }
    __syncthreads();

    float mx = -1e30f;
    for (int s = t; s < S_LEN; s += 256) mx = fmaxf(mx, sc[s]);
#pragma unroll
    for (int o = 16; o > 0; o >>= 1) mx = fmaxf(mx, __shfl_xor_sync(0xffffffffu, mx, o));
    if (lane == 0) red[w] = mx;
    __syncthreads();
    mx = red[0];
#pragma unroll
    for (int i = 1; i < 8; i++) mx = fmaxf(mx, red[i]);
    __syncthreads();

    float ps = 0.f;
    for (int s = t; s < S_LEN; s += 256) {
        float e = __expf(sc[s] - mx);
        sc[s] = e;
        ps += e;
    }
#pragma unroll
    for (int o = 16; o > 0; o >>= 1) ps += __shfl_xor_sync(0xffffffffu, ps, o);
    if (lane == 0) red[w] = ps;
    __syncthreads();
    float l = 0.f;
#pragma unroll
    for (int i = 0; i < 8; i++) l += red[i];

    float a0 = 0.f, a1 = 0.f;
    for (int s = w * 2; s < S_LEN; s += 16) {
        float e0 = sc[s], e1 = sc[s + 1];
        const float* vr = vg + ((size_t)(b * S_LEN + s)) * EMB + h * HDIM;
        a0 += e0 * vr[lane]      + e1 * vr[EMB + lane];
        a1 += e0 * vr[lane + 32] + e1 * vr[EMB + lane + 32];
    }
    part[w][lane] = a0;
    part[w][lane + 32] = a1;
    __syncthreads();

    if (t < 64) {
        float sum = 0.f;
#pragma unroll
        for (int ww = 0; ww < 8; ww++) sum += part[ww][t];
        out[((size_t)(b * S_LEN + g)) * EMB + h * HDIM + t] = sum / l;
    }
}

// ---------------- launch ----------------
extern "C" void kernel_launch(void* const* d_in, const int* in_sizes, int n_in,
                              void* d_out, int out_size)
{
    (void)n_in; (void)out_size;
    int base = (in_sizes[2] == EMB * EMB) ? 2 : 3;

    const float* x    = (const float*)d_in[0];
    const int*   mask = (const int*)d_in[1];
    const float* wq   = (const float*)d_in[base + 0];
    const float* bq   = (const float*)d_in[base + 1];
    const float* wk   = (const float*)d_in[base + 2];
    const float* bk   = (const float*)d_in[base + 3];
    const float* wv   = (const float*)d_in[base + 4];
    const float* bv   = (const float*)d_in[base + 5];
    const float* wqg  = (const float*)d_in[base + 6];
    const float* bqg  = (const float*)d_in[base + 7];
    const float* wkg  = (const float*)d_in[base + 8];
    const float* bkg  = (const float*)d_in[base + 9];
    const float* wvg  = (const float*)d_in[base + 10];
    const float* bvg  = (const float*)d_in[base + 11];
    float* out = (float*)d_out;

    float *kg, *vg, *qg;
    __nv_bfloat16 *xh, *xl, *wth, *wtl, *qh, *ql, *kh, *kl, *vh, *vl;
    cudaGetSymbolAddress((void**)&kg,  g_kg);
    cudaGetSymbolAddress((void**)&vg,  g_vg);
    cudaGetSymbolAddress((void**)&qg,  g_qg);
    cudaGetSymbolAddress((void**)&xh,  g_xh);
    cudaGetSymbolAddress((void**)&xl,  g_xl);
    cudaGetSymbolAddress((void**)&wth, g_wth);
    cudaGetSymbolAddress((void**)&wtl, g_wtl);
    cudaGetSymbolAddress((void**)&qh,  g_qh);
    cudaGetSymbolAddress((void**)&ql,  g_ql);
    cudaGetSymbolAddress((void**)&kh,  g_kh);
    cudaGetSymbolAddress((void**)&kl,  g_kl);
    cudaGetSymbolAddress((void**)&vh,  g_vh);
    cudaGetSymbolAddress((void**)&vl,  g_vl);

    convx_kernel<<<(BATCH * S_LEN * EMB) / (256 * 4), 256>>>(x, xh, xl);
    convw_kernel<<<dim3(EMB / 32, EMB / 32, 6), 256>>>(
        wq, wk, wv, wkg, wvg, wqg, wth, wtl);
    mma_gemm6_kernel<<<dim3(EMB / 64, BATCH * S_LEN / 128, 6), 256>>>(
        xh, xl, wth, wtl, bq, bk, bv, bkg, bvg, bqg,
        qh, ql, kh, kl, vh, vl, kg, vg, qg);
    local_attn_mma<<<dim3(S_LEN / QT, NH, BATCH), 256>>>(
        qh, ql, kh, kl, vh, vl, mask, out);
    global_attn_kernel<<<dim3(GLB, NH, BATCH), 256>>>(qg, kg, vg, out);
}

// round 6
// speedup vs baseline: 3.7851x; 1.0339x over previous
#include <cuda_runtime.h>
#include <cuda_bf16.h>
#include <cstdint>

#define S_LEN 4096
#define BATCH 2
#define EMB   768
#define NH    12
#define HDIM  64
#define WIN   256
#define GLB   32
#define QT    32
#define NSEG  8
#define SEGLEN (S_LEN / NSEG)

typedef unsigned long long u64;

// ---------- packed f32x2 helpers ----------
__device__ __forceinline__ u64 pk2(float x, float y) {
    u64 r; asm("mov.b64 %0, {%1,%2};" : "=l"(r) : "f"(x), "f"(y)); return r;
}
__device__ __forceinline__ u64 dup2(float x) { return pk2(x, x); }
__device__ __forceinline__ float2 up2(u64 v) {
    float2 f; asm("mov.b64 {%0,%1}, %2;" : "=f"(f.x), "=f"(f.y) : "l"(v)); return f;
}
__device__ __forceinline__ u64 ffma2(u64 a, u64 b, u64 c) {
    u64 d; asm("fma.rn.f32x2 %0, %1, %2, %3;" : "=l"(d) : "l"(a), "l"(b), "l"(c)); return d;
}
__device__ __forceinline__ u64 fadd2(u64 a, u64 b) {
    u64 d; asm("add.rn.f32x2 %0, %1, %2;" : "=l"(d) : "l"(a), "l"(b)); return d;
}
__device__ __forceinline__ u64 fmul2(u64 a, u64 b) {
    u64 d; asm("mul.rn.f32x2 %0, %1, %2;" : "=l"(d) : "l"(a), "l"(b)); return d;
}

__device__ __forceinline__ uint32_t smem_to_u32(const void* p) {
    uint32_t a;
    asm("{ .reg .u64 t; cvta.to.shared.u64 t, %1; cvt.u32.u64 %0, t; }" : "=r"(a) : "l"(p));
    return a;
}
#define SW128(o) ((o) ^ (((o) >> 3) & 0x70))

__device__ __forceinline__ void ldsm_x4(uint32_t* r, uint32_t addr) {
    asm volatile("ldmatrix.sync.aligned.m8n8.x4.shared.b16 {%0,%1,%2,%3}, [%4];"
                 : "=r"(r[0]), "=r"(r[1]), "=r"(r[2]), "=r"(r[3]) : "r"(addr));
}
__device__ __forceinline__ void ldsm_x2(uint32_t* r, uint32_t addr) {
    asm volatile("ldmatrix.sync.aligned.m8n8.x2.shared.b16 {%0,%1}, [%2];"
                 : "=r"(r[0]), "=r"(r[1]) : "r"(addr));
}
__device__ __forceinline__ void ldsm_x4t(uint32_t* r, uint32_t addr) {
    asm volatile("ldmatrix.sync.aligned.m8n8.x4.trans.shared.b16 {%0,%1,%2,%3}, [%4];"
                 : "=r"(r[0]), "=r"(r[1]), "=r"(r[2]), "=r"(r[3]) : "r"(addr));
}
__device__ __forceinline__ void mma16816(float* c, const uint32_t* a,
                                         uint32_t b0, uint32_t b1) {
    asm volatile(
        "mma.sync.aligned.m16n8k16.row.col.f32.bf16.bf16.f32 "
        "{%0,%1,%2,%3}, {%4,%5,%6,%7}, {%8,%9}, {%0,%1,%2,%3};"
        : "+f"(c[0]), "+f"(c[1]), "+f"(c[2]), "+f"(c[3])
        : "r"(a[0]), "r"(a[1]), "r"(a[2]), "r"(a[3]), "r"(b0), "r"(b1));
}

// -------- scratch --------
__device__ float g_kg[BATCH * S_LEN * EMB];
__device__ float g_vg[BATCH * S_LEN * EMB];
__device__ float g_qg[BATCH * GLB * EMB];
__device__ __nv_bfloat16 g_xh[BATCH * S_LEN * EMB];
__device__ __nv_bfloat16 g_xl[BATCH * S_LEN * EMB];
__device__ __nv_bfloat16 g_wth[6 * EMB * EMB];
__device__ __nv_bfloat16 g_wtl[6 * EMB * EMB];
__device__ __nv_bfloat16 g_qh[BATCH * S_LEN * EMB];
__device__ __nv_bfloat16 g_ql[BATCH * S_LEN * EMB];
__device__ __nv_bfloat16 g_kh[BATCH * S_LEN * EMB];
__device__ __nv_bfloat16 g_kl[BATCH * S_LEN * EMB];
__device__ __nv_bfloat16 g_vh[BATCH * S_LEN * EMB];
__device__ __nv_bfloat16 g_vl[BATCH * S_LEN * EMB];
__device__ float g_po[NSEG * BATCH * NH * GLB * HDIM];
__device__ float g_pm[NSEG * BATCH * NH * GLB];
__device__ float g_pl[NSEG * BATCH * NH * GLB];

// ---------------- prep: x -> bf16 hi/lo ----------------
__global__ __launch_bounds__(256) void convx_kernel(
    const float* __restrict__ x, __nv_bfloat16* __restrict__ xh,
    __nv_bfloat16* __restrict__ xl)
{
    int i = (blockIdx.x * 256 + threadIdx.x) * 4;
    float4 a = *(const float4*)(x + i);
    __nv_bfloat16 h[4], l[4];
    float av[4] = {a.x, a.y, a.z, a.w};
#pragma unroll
    for (int j = 0; j < 4; j++) {
        h[j] = __float2bfloat16(av[j]);
        l[j] = __float2bfloat16(av[j] - __bfloat162float(h[j]));
    }
    *(uint2*)(xh + i) = *(const uint2*)h;
    *(uint2*)(xl + i) = *(const uint2*)l;
}

// ---------------- prep: W -> W^T bf16 hi/lo (6 weights) ----------------
__global__ __launch_bounds__(256) void convw_kernel(
    const float* __restrict__ w0, const float* __restrict__ w1,
    const float* __restrict__ w2, const float* __restrict__ w3,
    const float* __restrict__ w4, const float* __restrict__ w5,
    __nv_bfloat16* __restrict__ wth, __nv_bfloat16* __restrict__ wtl)
{
    __shared__ float tile[32][33];
    int z = blockIdx.z;
    const float* W = (z == 0) ? w0 : (z == 1) ? w1 : (z == 2) ? w2 :
                     (z == 3) ? w3 : (z == 4) ? w4 : w5;
    int kb = blockIdx.y * 32, nb = blockIdx.x * 32;
    int tx = threadIdx.x & 31, ty = threadIdx.x >> 5;
    for (int i = ty; i < 32; i += 8)
        tile[i][tx] = W[(size_t)(kb + i) * EMB + nb + tx];
    __syncthreads();
    for (int j = ty; j < 32; j += 8) {
        float a = tile[tx][j];
        __nv_bfloat16 h = __float2bfloat16(a);
        float l = a - __bfloat162float(h);
        size_t o = (size_t)z * EMB * EMB + (size_t)(nb + j) * EMB + kb + tx;
        wth[o] = h;
        wtl[o] = __float2bfloat16(l);
    }
}

// ---------------- mma.sync GEMM, 128x128 CTA tiles ----------------
// z=0..2 (q,k,v): bf16 hi/lo out.  z=3,4 (kg,vg): fp32.  z=5 (qg): fp32, 64 rows.
#define GA_H 0
#define GA_L 16384
#define GB_H 32768
#define GB_L 49152
#define GSM  65536

__global__ __launch_bounds__(256) void mma_gemm6_kernel(
    const __nv_bfloat16* __restrict__ xh, const __nv_bfloat16* __restrict__ xl,
    const __nv_bfloat16* __restrict__ wth, const __nv_bfloat16* __restrict__ wtl,
    const float* __restrict__ bq, const float* __restrict__ bk,
    const float* __restrict__ bv, const float* __restrict__ bkg,
    const float* __restrict__ bvg, const float* __restrict__ bqg,
    __nv_bfloat16* qh, __nv_bfloat16* ql, __nv_bfloat16* kh, __nv_bfloat16* kl,
    __nv_bfloat16* vh, __nv_bfloat16* vl,
    float* kg, float* vg, float* qg)
{
    extern __shared__ char dsm[];
    int z = blockIdx.z;
    if (z == 5 && blockIdx.y > 0) return;
    int t = threadIdx.x, wid = t >> 5, lane = t & 31;
    int m0 = blockIdx.y * 128, n0 = blockIdx.x * 128;
    int wm = wid & 3, wn = wid >> 2;   // warp tile: m 32 (wm), n 64 (wn)

    const float* bias;
    switch (z) {
        case 0:  bias = bq;  break;
        case 1:  bias = bk;  break;
        case 2:  bias = bv;  break;
        case 3:  bias = bkg; break;
        case 4:  bias = bvg; break;
        default: bias = bqg; break;
    }
    float scale = (z == 0 || z == 5) ? 0.125f : 1.0f;
    const __nv_bfloat16* Bh = wth + (size_t)z * EMB * EMB;
    const __nv_bfloat16* Bl = wtl + (size_t)z * EMB * EMB;

    uint32_t uAh = smem_to_u32(dsm) + GA_H;
    uint32_t uAl = smem_to_u32(dsm) + GA_L;
    uint32_t uBh = smem_to_u32(dsm) + GB_H;
    uint32_t uBl = smem_to_u32(dsm) + GB_L;

    float acc[2][8][4];
#pragma unroll
    for (int mi = 0; mi < 2; mi++)
#pragma unroll
        for (int ni = 0; ni < 8; ni++)
#pragma unroll
            for (int c = 0; c < 4; c++) acc[mi][ni][c] = 0.f;

    uint32_t a_off[2], b_off[4];
#pragma unroll
    for (int mi = 0; mi < 2; mi++) {
        int row = wm * 32 + mi * 16 + (lane & 15);
        a_off[mi] = (uint32_t)(row * 128) + ((lane >> 4) << 4);
    }
#pragma unroll
    for (int bi = 0; bi < 4; bi++) {
        int row = wn * 64 + bi * 16 + (lane & 15);
        b_off[bi] = (uint32_t)(row * 128) + ((lane >> 4) << 4);
    }

    for (int chunk = 0; chunk < 12; chunk++) {
        int k0 = chunk * 64;
        __syncthreads();
#pragma unroll
        for (int i = 0; i < 4; i++) {
            int idx = t + i * 256;
            int r = idx >> 3, u = idx & 7;
            uint32_t sw = SW128((uint32_t)(r * 128 + u * 16));
            size_t arow;
            if (z == 5) {
                int rr = r & 63;
                arow = (size_t)((rr >> 5) * S_LEN + (rr & 31));
            } else {
                arow = (size_t)(m0 + r);
            }
            size_t goff = arow * EMB + k0;
            *(uint4*)(dsm + GA_H + sw) = *((const uint4*)(xh + goff) + u);
            *(uint4*)(dsm + GA_L + sw) = *((const uint4*)(xl + goff) + u);
        }
#pragma unroll
        for (int i = 0; i < 4; i++) {
            int idx = t + i * 256;
            int r = idx >> 3, u = idx & 7;
            uint32_t sw = SW128((uint32_t)(r * 128 + u * 16));
            size_t goff = (size_t)(n0 + r) * EMB + k0;
            *(uint4*)(dsm + GB_H + sw) = *((const uint4*)(Bh + goff) + u);
            *(uint4*)(dsm + GB_L + sw) = *((const uint4*)(Bl + goff) + u);
        }
        __syncthreads();

#pragma unroll
        for (int ks = 0; ks < 4; ks++) {
            uint32_t kb = (uint32_t)(ks * 32);
            uint32_t ah[2][4], al[2][4];
#pragma unroll
            for (int mi = 0; mi < 2; mi++) {
                uint32_t sw = SW128(a_off[mi] + kb);
                ldsm_x4(ah[mi], uAh + sw);
                ldsm_x4(al[mi], uAl + sw);
            }
#pragma unroll
            for (int bi = 0; bi < 4; bi++) {
                uint32_t bh[4], bl[4];
                uint32_t sw = SW128(b_off[bi] + kb);
                ldsm_x4(bh, uBh + sw);
                ldsm_x4(bl, uBl + sw);
#pragma unroll
                for (int sel = 0; sel < 2; sel++) {
                    int ni = bi * 2 + sel;
#pragma unroll
                    for (int mi = 0; mi < 2; mi++) {
                        mma16816(acc[mi][ni], ah[mi], bh[sel], bh[sel + 2]);
                        mma16816(acc[mi][ni], ah[mi], bl[sel], bl[sel + 2]);
                        mma16816(acc[mi][ni], al[mi], bh[sel], bh[sel + 2]);
                    }
                }
            }
        }
    }

    int r = lane >> 2, cp = (lane & 3) * 2;
    if (z < 3) {
        __nv_bfloat16 *Yh, *Yl;
        if (z == 0)      { Yh = qh; Yl = ql; }
        else if (z == 1) { Yh = kh; Yl = kl; }
        else             { Yh = vh; Yl = vl; }
#pragma unroll
        for (int mi = 0; mi < 2; mi++) {
            int mbase = m0 + wm * 32 + mi * 16;
#pragma unroll
            for (int ni = 0; ni < 8; ni++) {
                int nbase = n0 + wn * 64 + ni * 8 + cp;
                float b0 = bias[nbase], b1 = bias[nbase + 1];
#pragma unroll
                for (int hr = 0; hr < 2; hr++) {
                    int row = mbase + r + hr * 8;
                    float v0 = (acc[mi][ni][hr * 2 + 0] + b0) * scale;
                    float v1 = (acc[mi][ni][hr * 2 + 1] + b1) * scale;
                    __nv_bfloat16 h0 = __float2bfloat16(v0);
                    __nv_bfloat16 h1 = __float2bfloat16(v1);
                    __nv_bfloat16 l0 = __float2bfloat16(v0 - __bfloat162float(h0));
                    __nv_bfloat16 l1 = __float2bfloat16(v1 - __bfloat162float(h1));
                    __nv_bfloat162 ph; ph.x = h0; ph.y = h1;
                    __nv_bfloat162 pl; pl.x = l0; pl.y = l1;
                    *(__nv_bfloat162*)(Yh + (size_t)row * EMB + nbase) = ph;
                    *(__nv_bfloat162*)(Yl + (size_t)row * EMB + nbase) = pl;
                }
            }
        }
    } else {
        float* Y = (z == 3) ? kg : (z == 4) ? vg : qg;
#pragma unroll
        for (int mi = 0; mi < 2; mi++) {
            int mbase = m0 + wm * 32 + mi * 16;
#pragma unroll
            for (int ni = 0; ni < 8; ni++) {
                int nbase = n0 + wn * 64 + ni * 8 + cp;
                float b0 = bias[nbase], b1 = bias[nbase + 1];
#pragma unroll
                for (int hr = 0; hr < 2; hr++) {
                    int row = mbase + r + hr * 8;
                    if (z == 5 && row >= BATCH * GLB) continue;
                    float2 o;
                    o.x = (acc[mi][ni][hr * 2 + 0] + b0) * scale;
                    o.y = (acc[mi][ni][hr * 2 + 1] + b1) * scale;
                    *(float2*)(Y + (size_t)row * EMB + nbase) = o;
                }
            }
        }
    }
}

// ---------------- Local attention, tensor-core flash style ----------------
__global__ __launch_bounds__(256) void local_attn_mma(
    const __nv_bfloat16* __restrict__ qh, const __nv_bfloat16* __restrict__ ql,
    const __nv_bfloat16* __restrict__ kh, const __nv_bfloat16* __restrict__ kl,
    const __nv_bfloat16* __restrict__ vh, const __nv_bfloat16* __restrict__ vl,
    const int* __restrict__ mask, float* __restrict__ out)
{
    __shared__ __align__(128) __nv_bfloat16 sQh[32 * 64], sQl[32 * 64];
    __shared__ __align__(128) __nv_bfloat16 sKh[32 * 64], sKl[32 * 64];
    __shared__ __align__(128) __nv_bfloat16 sVh[32 * 64], sVl[32 * 64];
    __shared__ float sc[32][36];
    __shared__ __align__(16) __nv_bfloat16 pbh[32 * 40], pbl[32 * 40];
    __shared__ float rs[32], ls[32];
    __shared__ int msk[32];

    int b = blockIdx.z, h = blockIdx.y, i0 = blockIdx.x * QT;
    int t = threadIdx.x, w = t >> 5, lane = t & 31;
    int qi = t >> 3, sub = t & 7;
    int iq = i0 + qi;

    uint32_t uQh = smem_to_u32(sQh), uQl = smem_to_u32(sQl);
    uint32_t uKh = smem_to_u32(sKh), uKl = smem_to_u32(sKl);
    uint32_t uVh = smem_to_u32(sVh), uVl = smem_to_u32(sVl);
    uint32_t uPh = smem_to_u32(pbh), uPl = smem_to_u32(pbl);

    {
        int r = t >> 3, u = t & 7;
        size_t g = ((size_t)(b * S_LEN + i0 + r)) * EMB + h * HDIM + u * 8;
        uint32_t sw = SW128((uint32_t)(r * 128 + u * 16));
        *(uint4*)((char*)sQh + sw) = *(const uint4*)(qh + g);
        *(uint4*)((char*)sQl + sw) = *(const uint4*)(ql + g);
    }

    int wm = w & 1;
    int wn = w >> 1;
    uint32_t aoff = (uint32_t)((wm * 16 + (lane & 15)) * 128 + ((lane >> 4) << 4));
    uint32_t boff = (uint32_t)((wn * 8 + (lane & 7)) * 128 + (((lane >> 3) & 1) << 4));
    uint32_t poff = (uint32_t)((wm * 16 + (lane & 15)) * 80 + ((lane >> 4) << 4));
    int vtile = lane >> 3, vrow = lane & 7;
    uint32_t voff = (uint32_t)(((vtile & 1) * 8 + vrow) * 128 +
                               wn * 32 + ((vtile >> 1) << 4));

    float oacc[2][4] = {{0.f, 0.f, 0.f, 0.f}, {0.f, 0.f, 0.f, 0.f}};
    float m_run = -1e30f, l_run = 0.f;

    int lo = i0 - WIN; if (lo < 0) lo = 0;
    int hi = i0 + QT - 1 + WIN; if (hi > S_LEN - 1) hi = S_LEN - 1;
    int wstart = lo & ~(QT - 1);
    int nwin = (hi - wstart) / QT + 1;

    for (int ci = -1; ci < nwin; ci++) {
        bool gl = (ci < 0);
        int kstart = gl ? 0 : wstart + ci * QT;

        __syncthreads();
        {
            int r = t >> 3, u = t & 7;
            int p = kstart + r;
            uint32_t sw = SW128((uint32_t)(r * 128 + u * 16));
            uint4 z4 = make_uint4(0, 0, 0, 0);
            uint4 akh = z4, akl = z4, avh = z4, avl = z4;
            if (p < S_LEN) {
                size_t g = ((size_t)(b * S_LEN + p)) * EMB + h * HDIM + u * 8;
                akh = *(const uint4*)(kh + g);
                akl = *(const uint4*)(kl + g);
                avh = *(const uint4*)(vh + g);
                avl = *(const uint4*)(vl + g);
            }
            *(uint4*)((char*)sKh + sw) = akh;
            *(uint4*)((char*)sKl + sw) = akl;
            *(uint4*)((char*)sVh + sw) = avh;
            *(uint4*)((char*)sVl + sw) = avl;
            if (t < 32) {
                int p2 = kstart + t;
                msk[t] = (p2 < S_LEN) ? mask[b * S_LEN + p2] : 0;
            }
        }
        __syncthreads();

        {
            float f[4] = {0.f, 0.f, 0.f, 0.f};
#pragma unroll
            for (int ks = 0; ks < 4; ks++) {
                uint32_t kb = (uint32_t)(ks * 32);
                uint32_t a0[4], a1[4], b0[2], b1[2];
                ldsm_x4(a0, uQh + SW128(aoff + kb));
                ldsm_x4(a1, uQl + SW128(aoff + kb));
                ldsm_x2(b0, uKh + SW128(boff + kb));
                ldsm_x2(b1, uKl + SW128(boff + kb));
                mma16816(f, a0, b0[0], b0[1]);
                mma16816(f, a0, b1[0], b1[1]);
                mma16816(f, a1, b0[0], b0[1]);
            }
            int r = wm * 16 + (lane >> 2), c = wn * 8 + (lane & 3) * 2;
            *(float2*)&sc[r][c]     = make_float2(f[0], f[1]);
            *(float2*)&sc[r + 8][c] = make_float2(f[2], f[3]);
        }
        __syncthreads();

        {
            float4 s4 = *(float4*)&sc[qi][sub * 4];
            float sv[4] = {s4.x, s4.y, s4.z, s4.w};
            if (!gl) {
#pragma unroll
                for (int u2 = 0; u2 < 4; u2++) {
                    int j = sub * 4 + u2, p = kstart + j;
                    bool valid = (p < S_LEN) && (p >= iq - WIN) && (p <= iq + WIN);
                    if (!valid) sv[u2] = -1e30f;
                    else if (msk[j]) sv[u2] -= 10000.f;
                }
            }
            float cm = fmaxf(fmaxf(sv[0], sv[1]), fmaxf(sv[2], sv[3]));
            cm = fmaxf(cm, __shfl_xor_sync(0xffffffffu, cm, 1));
            cm = fmaxf(cm, __shfl_xor_sync(0xffffffffu, cm, 2));
            cm = fmaxf(cm, __shfl_xor_sync(0xffffffffu, cm, 4));
            float m_new = fmaxf(m_run, cm);
            float rsc = __expf(m_run - m_new);
            float psum = 0.f;
            __nv_bfloat16 eh[4], el[4];
#pragma unroll
            for (int u2 = 0; u2 < 4; u2++) {
                float e = __expf(sv[u2] - m_new);
                psum += e;
                eh[u2] = __float2bfloat16(e);
                el[u2] = __float2bfloat16(e - __bfloat162float(eh[u2]));
            }
            psum += __shfl_xor_sync(0xffffffffu, psum, 1);
            psum += __shfl_xor_sync(0xffffffffu, psum, 2);
            psum += __shfl_xor_sync(0xffffffffu, psum, 4);
            l_run = l_run * rsc + psum;
            m_run = m_new;
            *(uint2*)(pbh + qi * 40 + sub * 4) = *(const uint2*)eh;
            *(uint2*)(pbl + qi * 40 + sub * 4) = *(const uint2*)el;
            if (sub == 0) rs[qi] = rsc;
        }
        __syncthreads();

        {
            float r0 = rs[wm * 16 + (lane >> 2)];
            float r1 = rs[wm * 16 + 8 + (lane >> 2)];
#pragma unroll
            for (int ni = 0; ni < 2; ni++) {
                oacc[ni][0] *= r0; oacc[ni][1] *= r0;
                oacc[ni][2] *= r1; oacc[ni][3] *= r1;
            }
#pragma unroll
            for (int ks = 0; ks < 2; ks++) {
                uint32_t ap0[4], ap1[4], bv0[4], bv1[4];
                ldsm_x4(ap0, uPh + poff + ks * 32);
                ldsm_x4(ap1, uPl + poff + ks * 32);
                uint32_t va = SW128(voff + (uint32_t)(ks * 2048));
                ldsm_x4t(bv0, uVh + va);
                ldsm_x4t(bv1, uVl + va);
                mma16816(oacc[0], ap0, bv0[0], bv0[1]);
                mma16816(oacc[0], ap0, bv1[0], bv1[1]);
                mma16816(oacc[0], ap1, bv0[0], bv0[1]);
                mma16816(oacc[1], ap0, bv0[2], bv0[3]);
                mma16816(oacc[1], ap0, bv1[2], bv1[3]);
                mma16816(oacc[1], ap1, bv0[2], bv0[3]);
            }
        }
    }

    if (sub == 0) ls[qi] = l_run;
    __syncthreads();
    {
        float i0v = 1.f / ls[wm * 16 + (lane >> 2)];
        float i1v = 1.f / ls[wm * 16 + 8 + (lane >> 2)];
        int r = wm * 16 + (lane >> 2);
#pragma unroll
        for (int ni = 0; ni < 2; ni++) {
            int c = wn * 16 + ni * 8 + (lane & 3) * 2;
            size_t o0 = ((size_t)(b * S_LEN + i0 + r)) * EMB + h * HDIM + c;
            size_t o1 = ((size_t)(b * S_LEN + i0 + r + 8)) * EMB + h * HDIM + c;
            float2 v0; v0.x = oacc[ni][0] * i0v; v0.y = oacc[ni][1] * i0v;
            float2 v1; v1.x = oacc[ni][2] * i1v; v1.y = oacc[ni][3] * i1v;
            *(float2*)(out + o0) = v0;
            *(float2*)(out + o1) = v1;
        }
    }
}

// ---------------- Global rows: split-K partial flash ----------------
__global__ __launch_bounds__(256, 2) void global_part_kernel(
    const float* __restrict__ qg, const float* __restrict__ kg,
    const float* __restrict__ vg,
    float* __restrict__ po, float* __restrict__ pm, float* __restrict__ pl)
{
    __shared__ float ks[32][68];
    __shared__ float vs[32][68];
    __shared__ float sc[32][36];

    int seg = blockIdx.x, h = blockIdx.y, b = blockIdx.z;
    int t = threadIdx.x;
    int qi = t >> 3, sub = t & 7;

    u64 q2[32];
    {
        const ulonglong2* qrow = (const ulonglong2*)
            (qg + ((size_t)(b * GLB + qi)) * EMB + h * HDIM);
#pragma unroll
        for (int e = 0; e < 16; e++) {
            ulonglong2 t2 = qrow[e];
            q2[e * 2] = t2.x; q2[e * 2 + 1] = t2.y;
        }
    }
    u64 acc2[4] = {0ULL, 0ULL, 0ULL, 0ULL};
    float m_run = -1e30f, l_run = 0.f;

    for (int c = 0; c < SEGLEN / 32; c++) {
        int kstart = seg * SEGLEN + c * 32;
        __syncthreads();
        for (int u = t; u < 32 * 16; u += 256) {
            int r = u >> 4, cc = (u & 15) << 2;
            size_t off = ((size_t)(b * S_LEN + kstart + r)) * EMB + h * HDIM + cc;
            *(float4*)&ks[r][cc] = *(const float4*)(kg + off);
            *(float4*)&vs[r][cc] = *(const float4*)(vg + off);
        }
        __syncthreads();

        float sv[4];
#pragma unroll
        for (int u2 = 0; u2 < 4; u2++) {
            int j = sub * 4 + u2;
            const ulonglong2* kr = (const ulonglong2*)&ks[j][0];
            u64 s0 = 0ULL, s1 = 0ULL, s2 = 0ULL, s3 = 0ULL;
#pragma unroll
            for (int e = 0; e < 16; e += 2) {
                ulonglong2 ka = kr[e];
                ulonglong2 kb = kr[e + 1];
                s0 = ffma2(q2[e * 2],     ka.x, s0);
                s1 = ffma2(q2[e * 2 + 1], ka.y, s1);
                s2 = ffma2(q2[e * 2 + 2], kb.x, s2);
                s3 = ffma2(q2[e * 2 + 3], kb.y, s3);
            }
            float2 r2 = up2(fadd2(fadd2(s0, s1), fadd2(s2, s3)));
            sv[u2] = r2.x + r2.y;
        }
        float cm = fmaxf(fmaxf(sv[0], sv[1]), fmaxf(sv[2], sv[3]));
        cm = fmaxf(cm, __shfl_xor_sync(0xffffffffu, cm, 1));
        cm = fmaxf(cm, __shfl_xor_sync(0xffffffffu, cm, 2));
        cm = fmaxf(cm, __shfl_xor_sync(0xffffffffu, cm, 4));
        float m_new = fmaxf(m_run, cm);
        float rsc = __expf(m_run - m_new);
        float psum = 0.f;
#pragma unroll
        for (int u2 = 0; u2 < 4; u2++) {
            float e = __expf(sv[u2] - m_new);
            sc[qi][sub * 4 + u2] = e;
            psum += e;
        }
        psum += __shfl_xor_sync(0xffffffffu, psum, 1);
        psum += __shfl_xor_sync(0xffffffffu, psum, 2);
        psum += __shfl_xor_sync(0xffffffffu, psum, 4);
        l_run = l_run * rsc + psum;
        m_run = m_new;
        __syncwarp();

        u64 rb = dup2(rsc);
#pragma unroll
        for (int d = 0; d < 4; d++) acc2[d] = fmul2(acc2[d], rb);
#pragma unroll 4
        for (int j = 0; j < 32; j++) {
            u64 eb = dup2(sc[qi][j]);
            ulonglong2 v0 = *(const ulonglong2*)&vs[j][sub * 4];
            ulonglong2 v1 = *(const ulonglong2*)&vs[j][sub * 4 + 32];
            acc2[0] = ffma2(eb, v0.x, acc2[0]);
            acc2[1] = ffma2(eb, v0.y, acc2[1]);
            acc2[2] = ffma2(eb, v1.x, acc2[2]);
            acc2[3] = ffma2(eb, v1.y, acc2[3]);
        }
    }

    size_t pidx = (((size_t)seg * BATCH + b) * NH + h) * GLB + qi;
    float2 a0 = up2(acc2[0]), a1 = up2(acc2[1]);
    float2 a2 = up2(acc2[2]), a3 = up2(acc2[3]);
    float* prow = po + pidx * HDIM;
    *(float4*)(prow + sub * 4)      = make_float4(a0.x, a0.y, a1.x, a1.y);
    *(float4*)(prow + 32 + sub * 4) = make_float4(a2.x, a2.y, a3.x, a3.y);
    if (sub == 0) { pm[pidx] = m_run; pl[pidx] = l_run; }
}

__global__ __launch_bounds__(64) void global_merge_kernel(
    const float* __restrict__ po, const float* __restrict__ pm,
    const float* __restrict__ pl, float* __restrict__ out)
{
    int g = blockIdx.x, h = blockIdx.y, b = blockIdx.z;
    int d = threadIdx.x;

    float mv[NSEG];
    float mx = -1e30f;
#pragma unroll
    for (int s = 0; s < NSEG; s++) {
        mv[s] = pm[(((size_t)s * BATCH + b) * NH + h) * GLB + g];
        mx = fmaxf(mx, mv[s]);
    }
    float num = 0.f, den = 0.f;
#pragma unroll
    for (int s = 0; s < NSEG; s++) {
        size_t pidx = (((size_t)s * BATCH + b) * NH + h) * GLB + g;
        float w = __expf(mv[s] - mx);
        num += w * po[pidx * HDIM + d];
        den += w * pl[pidx];
    }
    out[((size_t)(b * S_LEN + g)) * EMB + h * HDIM + d] = num / den;
}

// ---------------- launch ----------------
extern "C" void kernel_launch(void* const* d_in, const int* in_sizes, int n_in,
                              void* d_out, int out_size)
{
    (void)n_in; (void)out_size;
    int base = (in_sizes[2] == EMB * EMB) ? 2 : 3;

    const float* x    = (const float*)d_in[0];
    const int*   mask = (const int*)d_in[1];
    const float* wq   = (const float*)d_in[base + 0];
    const float* bq   = (const float*)d_in[base + 1];
    const float* wk   = (const float*)d_in[base + 2];
    const float* bk   = (const float*)d_in[base + 3];
    const float* wv   = (const float*)d_in[base + 4];
    const float* bv   = (const float*)d_in[base + 5];
    const float* wqg  = (const float*)d_in[base + 6];
    const float* bqg  = (const float*)d_in[base + 7];
    const float* wkg  = (const float*)d_in[base + 8];
    const float* bkg  = (const float*)d_in[base + 9];
    const float* wvg  = (const float*)d_in[base + 10];
    const float* bvg  = (const float*)d_in[base + 11];
    float* out = (float*)d_out;

    float *kg, *vg, *qg, *po, *pm, *pl;
    __nv_bfloat16 *xh, *xl, *wth, *wtl, *qh, *ql, *kh, *kl, *vh, *vl;
    cudaGetSymbolAddress((void**)&kg,  g_kg);
    cudaGetSymbolAddress((void**)&vg,  g_vg);
    cudaGetSymbolAddress((void**)&qg,  g_qg);
    cudaGetSymbolAddress((void**)&xh,  g_xh);
    cudaGetSymbolAddress((void**)&xl,  g_xl);
    cudaGetSymbolAddress((void**)&wth, g_wth);
    cudaGetSymbolAddress((void**)&wtl, g_wtl);
    cudaGetSymbolAddress((void**)&qh,  g_qh);
    cudaGetSymbolAddress((void**)&ql,  g_ql);
    cudaGetSymbolAddress((void**)&kh,  g_kh);
    cudaGetSymbolAddress((void**)&kl,  g_kl);
    cudaGetSymbolAddress((void**)&vh,  g_vh);
    cudaGetSymbolAddress((void**)&vl,  g_vl);
    cudaGetSymbolAddress((void**)&po,  g_po);
    cudaGetSymbolAddress((void**)&pm,  g_pm);
    cudaGetSymbolAddress((void**)&pl,  g_pl);

    cudaFuncSetAttribute(mma_gemm6_kernel,
                         cudaFuncAttributeMaxDynamicSharedMemorySize, GSM);

    convx_kernel<<<(BATCH * S_LEN * EMB) / (256 * 4), 256>>>(x, xh, xl);
    convw_kernel<<<dim3(EMB / 32, EMB / 32, 6), 256>>>(
        wq, wk, wv, wkg, wvg, wqg, wth, wtl);
    mma_gemm6_kernel<<<dim3(EMB / 128, BATCH * S_LEN / 128, 6), 256, GSM>>>(
        xh, xl, wth, wtl, bq, bk, bv, bkg, bvg, bqg,
        qh, ql, kh, kl, vh, vl, kg, vg, qg);
    local_attn_mma<<<dim3(S_LEN / QT, NH, BATCH), 256>>>(
        qh, ql, kh, kl, vh, vl, mask, out);
    global_part_kernel<<<dim3(NSEG, NH, BATCH), 256>>>(qg, kg, vg, po, pm, pl);
    global_merge_kernel<<<dim3(GLB, NH, BATCH), 64>>>(po, pm, pl, out);
}

// round 7
// speedup vs baseline: 4.1225x; 1.0891x over previous
#include <cuda_runtime.h>
#include <cuda_bf16.h>
#include <cstdint>

#define S_LEN 4096
#define BATCH 2
#define EMB   768
#define NH    12
#define HDIM  64
#define WIN   256
#define GLB   32
#define QT    32
#define NSEG  8
#define SEGLEN (S_LEN / NSEG)

typedef unsigned long long u64;

// ---------- packed f32x2 helpers ----------
__device__ __forceinline__ u64 pk2(float x, float y) {
    u64 r; asm("mov.b64 %0, {%1,%2};" : "=l"(r) : "f"(x), "f"(y)); return r;
}
__device__ __forceinline__ u64 dup2(float x) { return pk2(x, x); }
__device__ __forceinline__ float2 up2(u64 v) {
    float2 f; asm("mov.b64 {%0,%1}, %2;" : "=f"(f.x), "=f"(f.y) : "l"(v)); return f;
}
__device__ __forceinline__ u64 ffma2(u64 a, u64 b, u64 c) {
    u64 d; asm("fma.rn.f32x2 %0, %1, %2, %3;" : "=l"(d) : "l"(a), "l"(b), "l"(c)); return d;
}
__device__ __forceinline__ u64 fadd2(u64 a, u64 b) {
    u64 d; asm("add.rn.f32x2 %0, %1, %2;" : "=l"(d) : "l"(a), "l"(b)); return d;
}
__device__ __forceinline__ u64 fmul2(u64 a, u64 b) {
    u64 d; asm("mul.rn.f32x2 %0, %1, %2;" : "=l"(d) : "l"(a), "l"(b)); return d;
}

__device__ __forceinline__ uint32_t smem_to_u32(const void* p) {
    uint32_t a;
    asm("{ .reg .u64 t; cvta.to.shared.u64 t, %1; cvt.u32.u64 %0, t; }" : "=r"(a) : "l"(p));
    return a;
}
#define SW128(o) ((o) ^ (((o) >> 3) & 0x70))

#define CP16(dst, src) \
    asm volatile("cp.async.cg.shared.global [%0], [%1], 16;" \
                 :: "r"(dst), "l"(src) : "memory")
#define CP_COMMIT() asm volatile("cp.async.commit_group;" ::: "memory")
#define CP_WAIT1()  asm volatile("cp.async.wait_group 1;" ::: "memory")

__device__ __forceinline__ void ldsm_x4(uint32_t* r, uint32_t addr) {
    asm volatile("ldmatrix.sync.aligned.m8n8.x4.shared.b16 {%0,%1,%2,%3}, [%4];"
                 : "=r"(r[0]), "=r"(r[1]), "=r"(r[2]), "=r"(r[3]) : "r"(addr));
}
__device__ __forceinline__ void ldsm_x2(uint32_t* r, uint32_t addr) {
    asm volatile("ldmatrix.sync.aligned.m8n8.x2.shared.b16 {%0,%1}, [%2];"
                 : "=r"(r[0]), "=r"(r[1]) : "r"(addr));
}
__device__ __forceinline__ void ldsm_x4t(uint32_t* r, uint32_t addr) {
    asm volatile("ldmatrix.sync.aligned.m8n8.x4.trans.shared.b16 {%0,%1,%2,%3}, [%4];"
                 : "=r"(r[0]), "=r"(r[1]), "=r"(r[2]), "=r"(r[3]) : "r"(addr));
}
__device__ __forceinline__ void mma16816(float* c, const uint32_t* a,
                                         uint32_t b0, uint32_t b1) {
    asm volatile(
        "mma.sync.aligned.m16n8k16.row.col.f32.bf16.bf16.f32 "
        "{%0,%1,%2,%3}, {%4,%5,%6,%7}, {%8,%9}, {%0,%1,%2,%3};"
        : "+f"(c[0]), "+f"(c[1]), "+f"(c[2]), "+f"(c[3])
        : "r"(a[0]), "r"(a[1]), "r"(a[2]), "r"(a[3]), "r"(b0), "r"(b1));
}

// -------- scratch --------
__device__ float g_kg[BATCH * S_LEN * EMB];
__device__ float g_vg[BATCH * S_LEN * EMB];
__device__ float g_qg[BATCH * GLB * EMB];
__device__ __nv_bfloat16 g_xh[BATCH * S_LEN * EMB];
__device__ __nv_bfloat16 g_xl[BATCH * S_LEN * EMB];
__device__ __nv_bfloat16 g_wth[6 * EMB * EMB];
__device__ __nv_bfloat16 g_wtl[6 * EMB * EMB];
__device__ __nv_bfloat16 g_qh[BATCH * S_LEN * EMB];
__device__ __nv_bfloat16 g_ql[BATCH * S_LEN * EMB];
__device__ __nv_bfloat16 g_kh[BATCH * S_LEN * EMB];
__device__ __nv_bfloat16 g_kl[BATCH * S_LEN * EMB];
__device__ __nv_bfloat16 g_vh[BATCH * S_LEN * EMB];
__device__ __nv_bfloat16 g_vl[BATCH * S_LEN * EMB];
__device__ float g_po[NSEG * BATCH * NH * GLB * HDIM];
__device__ float g_pm[NSEG * BATCH * NH * GLB];
__device__ float g_pl[NSEG * BATCH * NH * GLB];

// ---------------- prep: x -> bf16 hi/lo ----------------
__global__ __launch_bounds__(256) void convx_kernel(
    const float* __restrict__ x, __nv_bfloat16* __restrict__ xh,
    __nv_bfloat16* __restrict__ xl)
{
    int i = (blockIdx.x * 256 + threadIdx.x) * 4;
    float4 a = *(const float4*)(x + i);
    __nv_bfloat16 h[4], l[4];
    float av[4] = {a.x, a.y, a.z, a.w};
#pragma unroll
    for (int j = 0; j < 4; j++) {
        h[j] = __float2bfloat16(av[j]);
        l[j] = __float2bfloat16(av[j] - __bfloat162float(h[j]));
    }
    *(uint2*)(xh + i) = *(const uint2*)h;
    *(uint2*)(xl + i) = *(const uint2*)l;
}

// ---------------- prep: W -> W^T bf16 hi/lo (6 weights) ----------------
__global__ __launch_bounds__(256) void convw_kernel(
    const float* __restrict__ w0, const float* __restrict__ w1,
    const float* __restrict__ w2, const float* __restrict__ w3,
    const float* __restrict__ w4, const float* __restrict__ w5,
    __nv_bfloat16* __restrict__ wth, __nv_bfloat16* __restrict__ wtl)
{
    __shared__ float tile[32][33];
    int z = blockIdx.z;
    const float* W = (z == 0) ? w0 : (z == 1) ? w1 : (z == 2) ? w2 :
                     (z == 3) ? w3 : (z == 4) ? w4 : w5;
    int kb = blockIdx.y * 32, nb = blockIdx.x * 32;
    int tx = threadIdx.x & 31, ty = threadIdx.x >> 5;
    for (int i = ty; i < 32; i += 8)
        tile[i][tx] = W[(size_t)(kb + i) * EMB + nb + tx];
    __syncthreads();
    for (int j = ty; j < 32; j += 8) {
        float a = tile[tx][j];
        __nv_bfloat16 h = __float2bfloat16(a);
        float l = a - __bfloat162float(h);
        size_t o = (size_t)z * EMB * EMB + (size_t)(nb + j) * EMB + kb + tx;
        wth[o] = h;
        wtl[o] = __float2bfloat16(l);
    }
}

// ---------------- mma.sync GEMM, 128x128 CTA, 512 thr, cp.async 2-stage ----
#define GST  65536                  // bytes per stage
#define GSM2 (2 * GST)
// stage layout: AH +0, AL +16384, BH +32768, BL +49152 (each 128x64 bf16=16KB)

__global__ __launch_bounds__(512) void mma_gemm6_kernel(
    const __nv_bfloat16* __restrict__ xh, const __nv_bfloat16* __restrict__ xl,
    const __nv_bfloat16* __restrict__ wth, const __nv_bfloat16* __restrict__ wtl,
    const float* __restrict__ bq, const float* __restrict__ bk,
    const float* __restrict__ bv, const float* __restrict__ bkg,
    const float* __restrict__ bvg, const float* __restrict__ bqg,
    __nv_bfloat16* qh, __nv_bfloat16* ql, __nv_bfloat16* kh, __nv_bfloat16* kl,
    __nv_bfloat16* vh, __nv_bfloat16* vl,
    float* kg, float* vg, float* qg)
{
    extern __shared__ char dsm[];
    int z = blockIdx.z;
    if (z == 5 && blockIdx.y > 0) return;
    int t = threadIdx.x, wid = t >> 5, lane = t & 31;
    int m0 = blockIdx.y * 128, n0 = blockIdx.x * 128;
    int wm = wid & 3, wn = wid >> 2;   // 4x4 warp grid, 32x32 warp tile

    const float* bias;
    switch (z) {
        case 0:  bias = bq;  break;
        case 1:  bias = bk;  break;
        case 2:  bias = bv;  break;
        case 3:  bias = bkg; break;
        case 4:  bias = bvg; break;
        default: bias = bqg; break;
    }
    float scale = (z == 0 || z == 5) ? 0.125f : 1.0f;
    const __nv_bfloat16* Bh = wth + (size_t)z * EMB * EMB;
    const __nv_bfloat16* Bl = wtl + (size_t)z * EMB * EMB;

    uint32_t sb = smem_to_u32(dsm);

    float acc[2][4][4];
#pragma unroll
    for (int mi = 0; mi < 2; mi++)
#pragma unroll
        for (int ni = 0; ni < 4; ni++)
#pragma unroll
            for (int c = 0; c < 4; c++) acc[mi][ni][c] = 0.f;

    uint32_t a_off[2], b_off[2];
#pragma unroll
    for (int mi = 0; mi < 2; mi++) {
        int row = wm * 32 + mi * 16 + (lane & 15);
        a_off[mi] = (uint32_t)(row * 128) + ((lane >> 4) << 4);
    }
#pragma unroll
    for (int bi = 0; bi < 2; bi++) {
        int row = wn * 32 + bi * 16 + (lane & 15);
        b_off[bi] = (uint32_t)(row * 128) + ((lane >> 4) << 4);
    }

    // per-thread load coords (2 iters x 4 streams = 8 cp.async of 16B)
    int lr0 = t >> 3, lu0 = t & 7;                 // rows 0..63
    int lr1 = (t + 512) >> 3, lu1 = (t + 512) & 7; // rows 64..127

#define LOAD_STAGE(chunk, s) do {                                            \
        int k0 = (chunk) * 64;                                               \
        uint32_t base = sb + (s) * GST;                                      \
        int rr[2] = {lr0, lr1}; int uu[2] = {lu0, lu1};                      \
        _Pragma("unroll")                                                    \
        for (int i = 0; i < 2; i++) {                                        \
            int r = rr[i], u = uu[i];                                        \
            uint32_t sw = SW128((uint32_t)(r * 128 + u * 16));               \
            size_t arow;                                                     \
            if (z == 5) { int q2r = r & 63;                                  \
                arow = (size_t)((q2r >> 5) * S_LEN + (q2r & 31)); }          \
            else arow = (size_t)(m0 + r);                                    \
            const __nv_bfloat16* pa = xh + arow * EMB + k0 + u * 8;          \
            const __nv_bfloat16* pb = xl + arow * EMB + k0 + u * 8;          \
            CP16(base + sw, pa);                                             \
            CP16(base + 16384 + sw, pb);                                     \
            size_t brow = (size_t)(n0 + r) * EMB + k0 + u * 8;               \
            CP16(base + 32768 + sw, Bh + brow);                              \
            CP16(base + 49152 + sw, Bl + brow);                              \
        }                                                                    \
    } while (0)

    LOAD_STAGE(0, 0);
    CP_COMMIT();

    for (int c = 0; c < 12; c++) {
        if (c < 11) LOAD_STAGE(c + 1, (c + 1) & 1);
        CP_COMMIT();
        CP_WAIT1();
        __syncthreads();
        uint32_t base = sb + (c & 1) * GST;
        uint32_t uAh = base, uAl = base + 16384;
        uint32_t uBh = base + 32768, uBl = base + 49152;
#pragma unroll
        for (int ks = 0; ks < 4; ks++) {
            uint32_t kb = (uint32_t)(ks * 32);
            uint32_t ah[2][4], al[2][4], bh[2][4], bl[2][4];
#pragma unroll
            for (int mi = 0; mi < 2; mi++) {
                uint32_t sw = SW128(a_off[mi] + kb);
                ldsm_x4(ah[mi], uAh + sw);
                ldsm_x4(al[mi], uAl + sw);
            }
#pragma unroll
            for (int bi = 0; bi < 2; bi++) {
                uint32_t sw = SW128(b_off[bi] + kb);
                ldsm_x4(bh[bi], uBh + sw);
                ldsm_x4(bl[bi], uBl + sw);
            }
#pragma unroll
            for (int mi = 0; mi < 2; mi++)
#pragma unroll
                for (int ni = 0; ni < 4; ni++) {
                    int bi = ni >> 1, sel = ni & 1;
                    mma16816(acc[mi][ni], ah[mi], bh[bi][sel], bh[bi][sel + 2]);
                    mma16816(acc[mi][ni], ah[mi], bl[bi][sel], bl[bi][sel + 2]);
                    mma16816(acc[mi][ni], al[mi], bh[bi][sel], bh[bi][sel + 2]);
                }
        }
        __syncthreads();
    }
#undef LOAD_STAGE

    int r = lane >> 2, cp = (lane & 3) * 2;
    if (z < 3) {
        __nv_bfloat16 *Yh, *Yl;
        if (z == 0)      { Yh = qh; Yl = ql; }
        else if (z == 1) { Yh = kh; Yl = kl; }
        else             { Yh = vh; Yl = vl; }
#pragma unroll
        for (int mi = 0; mi < 2; mi++) {
            int mbase = m0 + wm * 32 + mi * 16;
#pragma unroll
            for (int ni = 0; ni < 4; ni++) {
                int nbase = n0 + wn * 32 + ni * 8 + cp;
                float b0 = bias[nbase], b1 = bias[nbase + 1];
#pragma unroll
                for (int hr = 0; hr < 2; hr++) {
                    int row = mbase + r + hr * 8;
                    float v0 = (acc[mi][ni][hr * 2 + 0] + b0) * scale;
                    float v1 = (acc[mi][ni][hr * 2 + 1] + b1) * scale;
                    __nv_bfloat16 h0 = __float2bfloat16(v0);
                    __nv_bfloat16 h1 = __float2bfloat16(v1);
                    __nv_bfloat16 l0 = __float2bfloat16(v0 - __bfloat162float(h0));
                    __nv_bfloat16 l1 = __float2bfloat16(v1 - __bfloat162float(h1));
                    __nv_bfloat162 ph; ph.x = h0; ph.y = h1;
                    __nv_bfloat162 pl; pl.x = l0; pl.y = l1;
                    *(__nv_bfloat162*)(Yh + (size_t)row * EMB + nbase) = ph;
                    *(__nv_bfloat162*)(Yl + (size_t)row * EMB + nbase) = pl;
                }
            }
        }
    } else {
        float* Y = (z == 3) ? kg : (z == 4) ? vg : qg;
#pragma unroll
        for (int mi = 0; mi < 2; mi++) {
            int mbase = m0 + wm * 32 + mi * 16;
#pragma unroll
            for (int ni = 0; ni < 4; ni++) {
                int nbase = n0 + wn * 32 + ni * 8 + cp;
                float b0 = bias[nbase], b1 = bias[nbase + 1];
#pragma unroll
                for (int hr = 0; hr < 2; hr++) {
                    int row = mbase + r + hr * 8;
                    if (z == 5 && row >= BATCH * GLB) continue;
                    float2 o;
                    o.x = (acc[mi][ni][hr * 2 + 0] + b0) * scale;
                    o.y = (acc[mi][ni][hr * 2 + 1] + b1) * scale;
                    *(float2*)(Y + (size_t)row * EMB + nbase) = o;
                }
            }
        }
    }
}

// ---------------- Local attention, tensor-core flash style ----------------
__global__ __launch_bounds__(256) void local_attn_mma(
    const __nv_bfloat16* __restrict__ qh, const __nv_bfloat16* __restrict__ ql,
    const __nv_bfloat16* __restrict__ kh, const __nv_bfloat16* __restrict__ kl,
    const __nv_bfloat16* __restrict__ vh, const __nv_bfloat16* __restrict__ vl,
    const int* __restrict__ mask, float* __restrict__ out)
{
    __shared__ __align__(128) __nv_bfloat16 sQh[32 * 64], sQl[32 * 64];
    __shared__ __align__(128) __nv_bfloat16 sKh[32 * 64], sKl[32 * 64];
    __shared__ __align__(128) __nv_bfloat16 sVh[32 * 64], sVl[32 * 64];
    __shared__ float sc[32][36];
    __shared__ __align__(16) __nv_bfloat16 pbh[32 * 40], pbl[32 * 40];
    __shared__ float rs[32], ls[32];
    __shared__ int msk[32];

    int b = blockIdx.z, h = blockIdx.y, i0 = blockIdx.x * QT;
    int t = threadIdx.x, w = t >> 5, lane = t & 31;
    int qi = t >> 3, sub = t & 7;
    int iq = i0 + qi;

    uint32_t uQh = smem_to_u32(sQh), uQl = smem_to_u32(sQl);
    uint32_t uKh = smem_to_u32(sKh), uKl = smem_to_u32(sKl);
    uint32_t uVh = smem_to_u32(sVh), uVl = smem_to_u32(sVl);
    uint32_t uPh = smem_to_u32(pbh), uPl = smem_to_u32(pbl);

    {
        int r = t >> 3, u = t & 7;
        size_t g = ((size_t)(b * S_LEN + i0 + r)) * EMB + h * HDIM + u * 8;
        uint32_t sw = SW128((uint32_t)(r * 128 + u * 16));
        *(uint4*)((char*)sQh + sw) = *(const uint4*)(qh + g);
        *(uint4*)((char*)sQl + sw) = *(const uint4*)(ql + g);
    }

    int wm = w & 1;
    int wn = w >> 1;
    uint32_t aoff = (uint32_t)((wm * 16 + (lane & 15)) * 128 + ((lane >> 4) << 4));
    uint32_t boff = (uint32_t)((wn * 8 + (lane & 7)) * 128 + (((lane >> 3) & 1) << 4));
    uint32_t poff = (uint32_t)((wm * 16 + (lane & 15)) * 80 + ((lane >> 4) << 4));
    int vtile = lane >> 3, vrow = lane & 7;
    uint32_t voff = (uint32_t)(((vtile & 1) * 8 + vrow) * 128 +
                               wn * 32 + ((vtile >> 1) << 4));

    float oacc[2][4] = {{0.f, 0.f, 0.f, 0.f}, {0.f, 0.f, 0.f, 0.f}};
    float m_run = -1e30f, l_run = 0.f;

    int lo = i0 - WIN; if (lo < 0) lo = 0;
    int hi = i0 + QT - 1 + WIN; if (hi > S_LEN - 1) hi = S_LEN - 1;
    int wstart = lo & ~(QT - 1);
    int nwin = (hi - wstart) / QT + 1;

    for (int ci = -1; ci < nwin; ci++) {
        bool gl = (ci < 0);
        int kstart = gl ? 0 : wstart + ci * QT;

        __syncthreads();
        {
            int r = t >> 3, u = t & 7;
            int p = kstart + r;
            uint32_t sw = SW128((uint32_t)(r * 128 + u * 16));
            uint4 z4 = make_uint4(0, 0, 0, 0);
            uint4 akh = z4, akl = z4, avh = z4, avl = z4;
            if (p < S_LEN) {
                size_t g = ((size_t)(b * S_LEN + p)) * EMB + h * HDIM + u * 8;
                akh = *(const uint4*)(kh + g);
                akl = *(const uint4*)(kl + g);
                avh = *(const uint4*)(vh + g);
                avl = *(const uint4*)(vl + g);
            }
            *(uint4*)((char*)sKh + sw) = akh;
            *(uint4*)((char*)sKl + sw) = akl;
            *(uint4*)((char*)sVh + sw) = avh;
            *(uint4*)((char*)sVl + sw) = avl;
            if (t < 32) {
                int p2 = kstart + t;
                msk[t] = (p2 < S_LEN) ? mask[b * S_LEN + p2] : 0;
            }
        }
        __syncthreads();

        {
            float f[4] = {0.f, 0.f, 0.f, 0.f};
#pragma unroll
            for (int ks = 0; ks < 4; ks++) {
                uint32_t kb = (uint32_t)(ks * 32);
                uint32_t a0[4], a1[4], b0[2], b1[2];
                ldsm_x4(a0, uQh + SW128(aoff + kb));
                ldsm_x4(a1, uQl + SW128(aoff + kb));
                ldsm_x2(b0, uKh + SW128(boff + kb));
                ldsm_x2(b1, uKl + SW128(boff + kb));
                mma16816(f, a0, b0[0], b0[1]);
                mma16816(f, a0, b1[0], b1[1]);
                mma16816(f, a1, b0[0], b0[1]);
            }
            int r = wm * 16 + (lane >> 2), c = wn * 8 + (lane & 3) * 2;
            *(float2*)&sc[r][c]     = make_float2(f[0], f[1]);
            *(float2*)&sc[r + 8][c] = make_float2(f[2], f[3]);
        }
        __syncthreads();

        {
            float4 s4 = *(float4*)&sc[qi][sub * 4];
            float sv[4] = {s4.x, s4.y, s4.z, s4.w};
            if (!gl) {
#pragma unroll
                for (int u2 = 0; u2 < 4; u2++) {
                    int j = sub * 4 + u2, p = kstart + j;
                    bool valid = (p < S_LEN) && (p >= iq - WIN) && (p <= iq + WIN);
                    if (!valid) sv[u2] = -1e30f;
                    else if (msk[j]) sv[u2] -= 10000.f;
                }
            }
            float cm = fmaxf(fmaxf(sv[0], sv[1]), fmaxf(sv[2], sv[3]));
            cm = fmaxf(cm, __shfl_xor_sync(0xffffffffu, cm, 1));
            cm = fmaxf(cm, __shfl_xor_sync(0xffffffffu, cm, 2));
            cm = fmaxf(cm, __shfl_xor_sync(0xffffffffu, cm, 4));
            float m_new = fmaxf(m_run, cm);
            float rsc = __expf(m_run - m_new);
            float psum = 0.f;
            __nv_bfloat16 eh[4], el[4];
#pragma unroll
            for (int u2 = 0; u2 < 4; u2++) {
                float e = __expf(sv[u2] - m_new);
                psum += e;
                eh[u2] = __float2bfloat16(e);
                el[u2] = __float2bfloat16(e - __bfloat162float(eh[u2]));
            }
            psum += __shfl_xor_sync(0xffffffffu, psum, 1);
            psum += __shfl_xor_sync(0xffffffffu, psum, 2);
            psum += __shfl_xor_sync(0xffffffffu, psum, 4);
            l_run = l_run * rsc + psum;
            m_run = m_new;
            *(uint2*)(pbh + qi * 40 + sub * 4) = *(const uint2*)eh;
            *(uint2*)(pbl + qi * 40 + sub * 4) = *(const uint2*)el;
            if (sub == 0) rs[qi] = rsc;
        }
        __syncthreads();

        {
            float r0 = rs[wm * 16 + (lane >> 2)];
            float r1 = rs[wm * 16 + 8 + (lane >> 2)];
#pragma unroll
            for (int ni = 0; ni < 2; ni++) {
                oacc[ni][0] *= r0; oacc[ni][1] *= r0;
                oacc[ni][2] *= r1; oacc[ni][3] *= r1;
            }
#pragma unroll
            for (int ks = 0; ks < 2; ks++) {
                uint32_t ap0[4], ap1[4], bv0[4], bv1[4];
                ldsm_x4(ap0, uPh + poff + ks * 32);
                ldsm_x4(ap1, uPl + poff + ks * 32);
                uint32_t va = SW128(voff + (uint32_t)(ks * 2048));
                ldsm_x4t(bv0, uVh + va);
                ldsm_x4t(bv1, uVl + va);
                mma16816(oacc[0], ap0, bv0[0], bv0[1]);
                mma16816(oacc[0], ap0, bv1[0], bv1[1]);
                mma16816(oacc[0], ap1, bv0[0], bv0[1]);
                mma16816(oacc[1], ap0, bv0[2], bv0[3]);
                mma16816(oacc[1], ap0, bv1[2], bv1[3]);
                mma16816(oacc[1], ap1, bv0[2], bv0[3]);
            }
        }
    }

    if (sub == 0) ls[qi] = l_run;
    __syncthreads();
    {
        float i0v = 1.f / ls[wm * 16 + (lane >> 2)];
        float i1v = 1.f / ls[wm * 16 + 8 + (lane >> 2)];
        int r = wm * 16 + (lane >> 2);
#pragma unroll
        for (int ni = 0; ni < 2; ni++) {
            int c = wn * 16 + ni * 8 + (lane & 3) * 2;
            size_t o0 = ((size_t)(b * S_LEN + i0 + r)) * EMB + h * HDIM + c;
            size_t o1 = ((size_t)(b * S_LEN + i0 + r + 8)) * EMB + h * HDIM + c;
            float2 v0; v0.x = oacc[ni][0] * i0v; v0.y = oacc[ni][1] * i0v;
            float2 v1; v1.x = oacc[ni][2] * i1v; v1.y = oacc[ni][3] * i1v;
            *(float2*)(out + o0) = v0;
            *(float2*)(out + o1) = v1;
        }
    }
}

// ---------------- Global rows: split-K partial flash ----------------
__global__ __launch_bounds__(256, 2) void global_part_kernel(
    const float* __restrict__ qg, const float* __restrict__ kg,
    const float* __restrict__ vg,
    float* __restrict__ po, float* __restrict__ pm, float* __restrict__ pl)
{
    __shared__ float ks[32][68];
    __shared__ float vs[32][68];
    __shared__ float sc[32][36];

    int seg = blockIdx.x, h = blockIdx.y, b = blockIdx.z;
    int t = threadIdx.x;
    int qi = t >> 3, sub = t & 7;

    u64 q2[32];
    {
        const ulonglong2* qrow = (const ulonglong2*)
            (qg + ((size_t)(b * GLB + qi)) * EMB + h * HDIM);
#pragma unroll
        for (int e = 0; e < 16; e++) {
            ulonglong2 t2 = qrow[e];
            q2[e * 2] = t2.x; q2[e * 2 + 1] = t2.y;
        }
    }
    u64 acc2[4] = {0ULL, 0ULL, 0ULL, 0ULL};
    float m_run = -1e30f, l_run = 0.f;

    for (int c = 0; c < SEGLEN / 32; c++) {
        int kstart = seg * SEGLEN + c * 32;
        __syncthreads();
        for (int u = t; u < 32 * 16; u += 256) {
            int r = u >> 4, cc = (u & 15) << 2;
            size_t off = ((size_t)(b * S_LEN + kstart + r)) * EMB + h * HDIM + cc;
            *(float4*)&ks[r][cc] = *(const float4*)(kg + off);
            *(float4*)&vs[r][cc] = *(const float4*)(vg + off);
        }
        __syncthreads();

        float sv[4];
#pragma unroll
        for (int u2 = 0; u2 < 4; u2++) {
            int j = sub * 4 + u2;
            const ulonglong2* kr = (const ulonglong2*)&ks[j][0];
            u64 s0 = 0ULL, s1 = 0ULL, s2 = 0ULL, s3 = 0ULL;
#pragma unroll
            for (int e = 0; e < 16; e += 2) {
                ulonglong2 ka = kr[e];
                ulonglong2 kb = kr[e + 1];
                s0 = ffma2(q2[e * 2],     ka.x, s0);
                s1 = ffma2(q2[e * 2 + 1], ka.y, s1);
                s2 = ffma2(q2[e * 2 + 2], kb.x, s2);
                s3 = ffma2(q2[e * 2 + 3], kb.y, s3);
            }
            float2 r2 = up2(fadd2(fadd2(s0, s1), fadd2(s2, s3)));
            sv[u2] = r2.x + r2.y;
        }
        float cm = fmaxf(fmaxf(sv[0], sv[1]), fmaxf(sv[2], sv[3]));
        cm = fmaxf(cm, __shfl_xor_sync(0xffffffffu, cm, 1));
        cm = fmaxf(cm, __shfl_xor_sync(0xffffffffu, cm, 2));
        cm = fmaxf(cm, __shfl_xor_sync(0xffffffffu, cm, 4));
        float m_new = fmaxf(m_run, cm);
        float rsc = __expf(m_run - m_new);
        float psum = 0.f;
#pragma unroll
        for (int u2 = 0; u2 < 4; u2++) {
            float e = __expf(sv[u2] - m_new);
            sc[qi][sub * 4 + u2] = e;
            psum += e;
        }
        psum += __shfl_xor_sync(0xffffffffu, psum, 1);
        psum += __shfl_xor_sync(0xffffffffu, psum, 2);
        psum += __shfl_xor_sync(0xffffffffu, psum, 4);
        l_run = l_run * rsc + psum;
        m_run = m_new;
        __syncwarp();

        u64 rb = dup2(rsc);
#pragma unroll
        for (int d = 0; d < 4; d++) acc2[d] = fmul2(acc2[d], rb);
#pragma unroll 4
        for (int j = 0; j < 32; j++) {
            u64 eb = dup2(sc[qi][j]);
            ulonglong2 v0 = *(const ulonglong2*)&vs[j][sub * 4];
            ulonglong2 v1 = *(const ulonglong2*)&vs[j][sub * 4 + 32];
            acc2[0] = ffma2(eb, v0.x, acc2[0]);
            acc2[1] = ffma2(eb, v0.y, acc2[1]);
            acc2[2] = ffma2(eb, v1.x, acc2[2]);
            acc2[3] = ffma2(eb, v1.y, acc2[3]);
        }
    }

    size_t pidx = (((size_t)seg * BATCH + b) * NH + h) * GLB + qi;
    float2 a0 = up2(acc2[0]), a1 = up2(acc2[1]);
    float2 a2 = up2(acc2[2]), a3 = up2(acc2[3]);
    float* prow = po + pidx * HDIM;
    *(float4*)(prow + sub * 4)      = make_float4(a0.x, a0.y, a1.x, a1.y);
    *(float4*)(prow + 32 + sub * 4) = make_float4(a2.x, a2.y, a3.x, a3.y);
    if (sub == 0) { pm[pidx] = m_run; pl[pidx] = l_run; }
}

__global__ __launch_bounds__(64) void global_merge_kernel(
    const float* __restrict__ po, const float* __restrict__ pm,
    const float* __restrict__ pl, float* __restrict__ out)
{
    int g = blockIdx.x, h = blockIdx.y, b = blockIdx.z;
    int d = threadIdx.x;

    float mv[NSEG];
    float mx = -1e30f;
#pragma unroll
    for (int s = 0; s < NSEG; s++) {
        mv[s] = pm[(((size_t)s * BATCH + b) * NH + h) * GLB + g];
        mx = fmaxf(mx, mv[s]);
    }
    float num = 0.f, den = 0.f;
#pragma unroll
    for (int s = 0; s < NSEG; s++) {
        size_t pidx = (((size_t)s * BATCH + b) * NH + h) * GLB + g;
        float w = __expf(mv[s] - mx);
        num += w * po[pidx * HDIM + d];
        den += w * pl[pidx];
    }
    out[((size_t)(b * S_LEN + g)) * EMB + h * HDIM + d] = num / den;
}

// ---------------- launch ----------------
extern "C" void kernel_launch(void* const* d_in, const int* in_sizes, int n_in,
                              void* d_out, int out_size)
{
    (void)n_in; (void)out_size;
    int base = (in_sizes[2] == EMB * EMB) ? 2 : 3;

    const float* x    = (const float*)d_in[0];
    const int*   mask = (const int*)d_in[1];
    const float* wq   = (const float*)d_in[base + 0];
    const float* bq   = (const float*)d_in[base + 1];
    const float* wk   = (const float*)d_in[base + 2];
    const float* bk   = (const float*)d_in[base + 3];
    const float* wv   = (const float*)d_in[base + 4];
    const float* bv   = (const float*)d_in[base + 5];
    const float* wqg  = (const float*)d_in[base + 6];
    const float* bqg  = (const float*)d_in[base + 7];
    const float* wkg  = (const float*)d_in[base + 8];
    const float* bkg  = (const float*)d_in[base + 9];
    const float* wvg  = (const float*)d_in[base + 10];
    const float* bvg  = (const float*)d_in[base + 11];
    float* out = (float*)d_out;

    float *kg, *vg, *qg, *po, *pm, *pl;
    __nv_bfloat16 *xh, *xl, *wth, *wtl, *qh, *ql, *kh, *kl, *vh, *vl;
    cudaGetSymbolAddress((void**)&kg,  g_kg);
    cudaGetSymbolAddress((void**)&vg,  g_vg);
    cudaGetSymbolAddress((void**)&qg,  g_qg);
    cudaGetSymbolAddress((void**)&xh,  g_xh);
    cudaGetSymbolAddress((void**)&xl,  g_xl);
    cudaGetSymbolAddress((void**)&wth, g_wth);
    cudaGetSymbolAddress((void**)&wtl, g_wtl);
    cudaGetSymbolAddress((void**)&qh,  g_qh);
    cudaGetSymbolAddress((void**)&ql,  g_ql);
    cudaGetSymbolAddress((void**)&kh,  g_kh);
    cudaGetSymbolAddress((void**)&kl,  g_kl);
    cudaGetSymbolAddress((void**)&vh,  g_vh);
    cudaGetSymbolAddress((void**)&vl,  g_vl);
    cudaGetSymbolAddress((void**)&po,  g_po);
    cudaGetSymbolAddress((void**)&pm,  g_pm);
    cudaGetSymbolAddress((void**)&pl,  g_pl);

    cudaFuncSetAttribute(mma_gemm6_kernel,
                         cudaFuncAttributeMaxDynamicSharedMemorySize, GSM2);

    convx_kernel<<<(BATCH * S_LEN * EMB) / (256 * 4), 256>>>(x, xh, xl);
    convw_kernel<<<dim3(EMB / 32, EMB / 32, 6), 256>>>(
        wq, wk, wv, wkg, wvg, wqg, wth, wtl);
    mma_gemm6_kernel<<<dim3(EMB / 128, BATCH * S_LEN / 128, 6), 512, GSM2>>>(
        xh, xl, wth, wtl, bq, bk, bv, bkg, bvg, bqg,
        qh, ql, kh, kl, vh, vl, kg, vg, qg);
    local_attn_mma<<<dim3(S_LEN / QT, NH, BATCH), 256>>>(
        qh, ql, kh, kl, vh, vl, mask, out);
    global_part_kernel<<<dim3(NSEG, NH, BATCH), 256>>>(qg, kg, vg, po, pm, pl);
    global_merge_kernel<<<dim3(GLB, NH, BATCH), 64>>>(po, pm, pl, out);
}

// round 8
// speedup vs baseline: 4.3449x; 1.0540x over previous
#include <cuda_runtime.h>
#include <cuda_bf16.h>
#include <cstdint>

#define S_LEN 4096
#define BATCH 2
#define EMB   768
#define NH    12
#define HDIM  64
#define WIN   256
#define GLB   32
#define QT    32
#define NSEG  8
#define SEGLEN (S_LEN / NSEG)

typedef unsigned long long u64;

// ---------- packed f32x2 helpers ----------
__device__ __forceinline__ u64 pk2(float x, float y) {
    u64 r; asm("mov.b64 %0, {%1,%2};" : "=l"(r) : "f"(x), "f"(y)); return r;
}
__device__ __forceinline__ u64 dup2(float x) { return pk2(x, x); }
__device__ __forceinline__ float2 up2(u64 v) {
    float2 f; asm("mov.b64 {%0,%1}, %2;" : "=f"(f.x), "=f"(f.y) : "l"(v)); return f;
}
__device__ __forceinline__ u64 ffma2(u64 a, u64 b, u64 c) {
    u64 d; asm("fma.rn.f32x2 %0, %1, %2, %3;" : "=l"(d) : "l"(a), "l"(b), "l"(c)); return d;
}
__device__ __forceinline__ u64 fadd2(u64 a, u64 b) {
    u64 d; asm("add.rn.f32x2 %0, %1, %2;" : "=l"(d) : "l"(a), "l"(b)); return d;
}
__device__ __forceinline__ u64 fmul2(u64 a, u64 b) {
    u64 d; asm("mul.rn.f32x2 %0, %1, %2;" : "=l"(d) : "l"(a), "l"(b)); return d;
}

__device__ __forceinline__ uint32_t smem_to_u32(const void* p) {
    uint32_t a;
    asm("{ .reg .u64 t; cvta.to.shared.u64 t, %1; cvt.u32.u64 %0, t; }" : "=r"(a) : "l"(p));
    return a;
}
#define SW128(o) ((o) ^ (((o) >> 3) & 0x70))

#define CP16(dst, src) \
    asm volatile("cp.async.cg.shared.global [%0], [%1], 16;" \
                 :: "r"(dst), "l"(src) : "memory")
#define CP_COMMIT() asm volatile("cp.async.commit_group;" ::: "memory")
#define CP_WAIT1()  asm volatile("cp.async.wait_group 1;" ::: "memory")

__device__ __forceinline__ void ldsm_x4(uint32_t* r, uint32_t addr) {
    asm volatile("ldmatrix.sync.aligned.m8n8.x4.shared.b16 {%0,%1,%2,%3}, [%4];"
                 : "=r"(r[0]), "=r"(r[1]), "=r"(r[2]), "=r"(r[3]) : "r"(addr));
}
__device__ __forceinline__ void ldsm_x2(uint32_t* r, uint32_t addr) {
    asm volatile("ldmatrix.sync.aligned.m8n8.x2.shared.b16 {%0,%1}, [%2];"
                 : "=r"(r[0]), "=r"(r[1]) : "r"(addr));
}
__device__ __forceinline__ void ldsm_x4t(uint32_t* r, uint32_t addr) {
    asm volatile("ldmatrix.sync.aligned.m8n8.x4.trans.shared.b16 {%0,%1,%2,%3}, [%4];"
                 : "=r"(r[0]), "=r"(r[1]), "=r"(r[2]), "=r"(r[3]) : "r"(addr));
}
__device__ __forceinline__ void mma16816(float* c, const uint32_t* a,
                                         uint32_t b0, uint32_t b1) {
    asm volatile(
        "mma.sync.aligned.m16n8k16.row.col.f32.bf16.bf16.f32 "
        "{%0,%1,%2,%3}, {%4,%5,%6,%7}, {%8,%9}, {%0,%1,%2,%3};"
        : "+f"(c[0]), "+f"(c[1]), "+f"(c[2]), "+f"(c[3])
        : "r"(a[0]), "r"(a[1]), "r"(a[2]), "r"(a[3]), "r"(b0), "r"(b1));
}

// -------- scratch --------
__device__ float g_kg[BATCH * S_LEN * EMB];
__device__ float g_vg[BATCH * S_LEN * EMB];
__device__ float g_qg[BATCH * GLB * EMB];
__device__ __nv_bfloat16 g_xh[BATCH * S_LEN * EMB];
__device__ __nv_bfloat16 g_xl[BATCH * S_LEN * EMB];
__device__ __nv_bfloat16 g_wth[6 * EMB * EMB];
__device__ __nv_bfloat16 g_wtl[6 * EMB * EMB];
__device__ __nv_bfloat16 g_qh[BATCH * S_LEN * EMB];
__device__ __nv_bfloat16 g_ql[BATCH * S_LEN * EMB];
__device__ __nv_bfloat16 g_kh[BATCH * S_LEN * EMB];
__device__ __nv_bfloat16 g_kl[BATCH * S_LEN * EMB];
__device__ __nv_bfloat16 g_vh[BATCH * S_LEN * EMB];
__device__ __nv_bfloat16 g_vl[BATCH * S_LEN * EMB];
__device__ float g_po[NSEG * BATCH * NH * GLB * HDIM];
__device__ float g_pm[NSEG * BATCH * NH * GLB];
__device__ float g_pl[NSEG * BATCH * NH * GLB];

// ---------------- prep: x -> bf16 hi/lo ----------------
__global__ __launch_bounds__(256) void convx_kernel(
    const float* __restrict__ x, __nv_bfloat16* __restrict__ xh,
    __nv_bfloat16* __restrict__ xl)
{
    int i = (blockIdx.x * 256 + threadIdx.x) * 4;
    float4 a = *(const float4*)(x + i);
    __nv_bfloat16 h[4], l[4];
    float av[4] = {a.x, a.y, a.z, a.w};
#pragma unroll
    for (int j = 0; j < 4; j++) {
        h[j] = __float2bfloat16(av[j]);
        l[j] = __float2bfloat16(av[j] - __bfloat162float(h[j]));
    }
    *(uint2*)(xh + i) = *(const uint2*)h;
    *(uint2*)(xl + i) = *(const uint2*)l;
}

// ---------------- prep: W -> W^T bf16 hi/lo (6 weights) ----------------
__global__ __launch_bounds__(256) void convw_kernel(
    const float* __restrict__ w0, const float* __restrict__ w1,
    const float* __restrict__ w2, const float* __restrict__ w3,
    const float* __restrict__ w4, const float* __restrict__ w5,
    __nv_bfloat16* __restrict__ wth, __nv_bfloat16* __restrict__ wtl)
{
    __shared__ float tile[32][33];
    int z = blockIdx.z;
    const float* W = (z == 0) ? w0 : (z == 1) ? w1 : (z == 2) ? w2 :
                     (z == 3) ? w3 : (z == 4) ? w4 : w5;
    int kb = blockIdx.y * 32, nb = blockIdx.x * 32;
    int tx = threadIdx.x & 31, ty = threadIdx.x >> 5;
    for (int i = ty; i < 32; i += 8)
        tile[i][tx] = W[(size_t)(kb + i) * EMB + nb + tx];
    __syncthreads();
    for (int j = ty; j < 32; j += 8) {
        float a = tile[tx][j];
        __nv_bfloat16 h = __float2bfloat16(a);
        float l = a - __bfloat162float(h);
        size_t o = (size_t)z * EMB * EMB + (size_t)(nb + j) * EMB + kb + tx;
        wth[o] = h;
        wtl[o] = __float2bfloat16(l);
    }
}

// ------- mma.sync GEMM, 128x64 CTA, 256 thr, cp.async 2-stage, 2 CTA/SM ----
#define GST  49152                  // bytes per stage: AH 16K, AL 16K, BH 8K, BL 8K
#define GSM2 (2 * GST)              // 96 KB

__global__ __launch_bounds__(256) void mma_gemm6_kernel(
    const __nv_bfloat16* __restrict__ xh, const __nv_bfloat16* __restrict__ xl,
    const __nv_bfloat16* __restrict__ wth, const __nv_bfloat16* __restrict__ wtl,
    const float* __restrict__ bq, const float* __restrict__ bk,
    const float* __restrict__ bv, const float* __restrict__ bkg,
    const float* __restrict__ bvg, const float* __restrict__ bqg,
    __nv_bfloat16* qh, __nv_bfloat16* ql, __nv_bfloat16* kh, __nv_bfloat16* kl,
    __nv_bfloat16* vh, __nv_bfloat16* vl,
    float* kg, float* vg, float* qg)
{
    extern __shared__ char dsm[];
    int z = blockIdx.z;
    if (z == 5 && blockIdx.y > 0) return;
    int t = threadIdx.x, wid = t >> 5, lane = t & 31;
    int m0 = blockIdx.y * 128, n0 = blockIdx.x * 64;
    int wm = wid & 3, wn = wid >> 2;   // 4x2 warp grid, 32x32 warp tile

    const float* bias;
    switch (z) {
        case 0:  bias = bq;  break;
        case 1:  bias = bk;  break;
        case 2:  bias = bv;  break;
        case 3:  bias = bkg; break;
        case 4:  bias = bvg; break;
        default: bias = bqg; break;
    }
    float scale = (z == 0 || z == 5) ? 0.125f : 1.0f;
    const __nv_bfloat16* Bh = wth + (size_t)z * EMB * EMB;
    const __nv_bfloat16* Bl = wtl + (size_t)z * EMB * EMB;

    uint32_t sb = smem_to_u32(dsm);

    float acc[2][4][4];
#pragma unroll
    for (int mi = 0; mi < 2; mi++)
#pragma unroll
        for (int ni = 0; ni < 4; ni++)
#pragma unroll
            for (int c = 0; c < 4; c++) acc[mi][ni][c] = 0.f;

    uint32_t a_off[2], b_off[2];
#pragma unroll
    for (int mi = 0; mi < 2; mi++) {
        int row = wm * 32 + mi * 16 + (lane & 15);
        a_off[mi] = (uint32_t)(row * 128) + ((lane >> 4) << 4);
    }
#pragma unroll
    for (int bi = 0; bi < 2; bi++) {
        int row = wn * 32 + bi * 16 + (lane & 15);
        b_off[bi] = (uint32_t)(row * 128) + ((lane >> 4) << 4);
    }

#define LOAD_STAGE(chunk, s) do {                                            \
        int k0 = (chunk) * 64;                                               \
        uint32_t base = sb + (s) * GST;                                      \
        _Pragma("unroll")                                                    \
        for (int i = 0; i < 4; i++) {                                        \
            int idx = t + i * 256;                                           \
            int r = idx >> 3, u = idx & 7;                                   \
            uint32_t sw = SW128((uint32_t)(r * 128 + u * 16));               \
            size_t arow;                                                     \
            if (z == 5) { int q2r = r & 63;                                  \
                arow = (size_t)((q2r >> 5) * S_LEN + (q2r & 31)); }          \
            else arow = (size_t)(m0 + r);                                    \
            CP16(base + sw,         xh + arow * EMB + k0 + u * 8);           \
            CP16(base + 16384 + sw, xl + arow * EMB + k0 + u * 8);           \
        }                                                                    \
        _Pragma("unroll")                                                    \
        for (int i = 0; i < 2; i++) {                                        \
            int idx = t + i * 256;                                           \
            int r = idx >> 3, u = idx & 7;                                   \
            uint32_t sw = SW128((uint32_t)(r * 128 + u * 16));               \
            size_t brow = (size_t)(n0 + r) * EMB + k0 + u * 8;               \
            CP16(base + 32768 + sw, Bh + brow);                              \
            CP16(base + 40960 + sw, Bl + brow);                              \
        }                                                                    \
    } while (0)

    LOAD_STAGE(0, 0);
    CP_COMMIT();

    for (int c = 0; c < 12; c++) {
        if (c < 11) LOAD_STAGE(c + 1, (c + 1) & 1);
        CP_COMMIT();
        CP_WAIT1();
        __syncthreads();
        uint32_t base = sb + (c & 1) * GST;
        uint32_t uAh = base, uAl = base + 16384;
        uint32_t uBh = base + 32768, uBl = base + 40960;
#pragma unroll
        for (int ks = 0; ks < 4; ks++) {
            uint32_t kb = (uint32_t)(ks * 32);
            uint32_t ah[2][4], al[2][4], bh[2][4], bl[2][4];
#pragma unroll
            for (int mi = 0; mi < 2; mi++) {
                uint32_t sw = SW128(a_off[mi] + kb);
                ldsm_x4(ah[mi], uAh + sw);
                ldsm_x4(al[mi], uAl + sw);
            }
#pragma unroll
            for (int bi = 0; bi < 2; bi++) {
                uint32_t sw = SW128(b_off[bi] + kb);
                ldsm_x4(bh[bi], uBh + sw);
                ldsm_x4(bl[bi], uBl + sw);
            }
#pragma unroll
            for (int mi = 0; mi < 2; mi++)
#pragma unroll
                for (int ni = 0; ni < 4; ni++) {
                    int bi = ni >> 1, sel = ni & 1;
                    mma16816(acc[mi][ni], ah[mi], bh[bi][sel], bh[bi][sel + 2]);
                    mma16816(acc[mi][ni], ah[mi], bl[bi][sel], bl[bi][sel + 2]);
                    mma16816(acc[mi][ni], al[mi], bh[bi][sel], bh[bi][sel + 2]);
                }
        }
        __syncthreads();
    }
#undef LOAD_STAGE

    int r = lane >> 2, cp = (lane & 3) * 2;
    if (z < 3) {
        __nv_bfloat16 *Yh, *Yl;
        if (z == 0)      { Yh = qh; Yl = ql; }
        else if (z == 1) { Yh = kh; Yl = kl; }
        else             { Yh = vh; Yl = vl; }
#pragma unroll
        for (int mi = 0; mi < 2; mi++) {
            int mbase = m0 + wm * 32 + mi * 16;
#pragma unroll
            for (int ni = 0; ni < 4; ni++) {
                int nbase = n0 + wn * 32 + ni * 8 + cp;
                float b0 = bias[nbase], b1 = bias[nbase + 1];
#pragma unroll
                for (int hr = 0; hr < 2; hr++) {
                    int row = mbase + r + hr * 8;
                    float v0 = (acc[mi][ni][hr * 2 + 0] + b0) * scale;
                    float v1 = (acc[mi][ni][hr * 2 + 1] + b1) * scale;
                    __nv_bfloat16 h0 = __float2bfloat16(v0);
                    __nv_bfloat16 h1 = __float2bfloat16(v1);
                    __nv_bfloat16 l0 = __float2bfloat16(v0 - __bfloat162float(h0));
                    __nv_bfloat16 l1 = __float2bfloat16(v1 - __bfloat162float(h1));
                    __nv_bfloat162 ph; ph.x = h0; ph.y = h1;
                    __nv_bfloat162 pl; pl.x = l0; pl.y = l1;
                    *(__nv_bfloat162*)(Yh + (size_t)row * EMB + nbase) = ph;
                    *(__nv_bfloat162*)(Yl + (size_t)row * EMB + nbase) = pl;
                }
            }
        }
    } else {
        float* Y = (z == 3) ? kg : (z == 4) ? vg : qg;
#pragma unroll
        for (int mi = 0; mi < 2; mi++) {
            int mbase = m0 + wm * 32 + mi * 16;
#pragma unroll
            for (int ni = 0; ni < 4; ni++) {
                int nbase = n0 + wn * 32 + ni * 8 + cp;
                float b0 = bias[nbase], b1 = bias[nbase + 1];
#pragma unroll
                for (int hr = 0; hr < 2; hr++) {
                    int row = mbase + r + hr * 8;
                    if (z == 5 && row >= BATCH * GLB) continue;
                    float2 o;
                    o.x = (acc[mi][ni][hr * 2 + 0] + b0) * scale;
                    o.y = (acc[mi][ni][hr * 2 + 1] + b1) * scale;
                    *(float2*)(Y + (size_t)row * EMB + nbase) = o;
                }
            }
        }
    }
}

// ---------------- Local attention, tensor-core flash style ----------------
// Q fragments hoisted into registers (loaded once, reused across all chunks).
__global__ __launch_bounds__(256) void local_attn_mma(
    const __nv_bfloat16* __restrict__ qh, const __nv_bfloat16* __restrict__ ql,
    const __nv_bfloat16* __restrict__ kh, const __nv_bfloat16* __restrict__ kl,
    const __nv_bfloat16* __restrict__ vh, const __nv_bfloat16* __restrict__ vl,
    const int* __restrict__ mask, float* __restrict__ out)
{
    __shared__ __align__(128) __nv_bfloat16 sQh[32 * 64], sQl[32 * 64];
    __shared__ __align__(128) __nv_bfloat16 sKh[32 * 64], sKl[32 * 64];
    __shared__ __align__(128) __nv_bfloat16 sVh[32 * 64], sVl[32 * 64];
    __shared__ float sc[32][36];
    __shared__ __align__(16) __nv_bfloat16 pbh[32 * 40], pbl[32 * 40];
    __shared__ float rs[32], ls[32];
    __shared__ int msk[32];

    int b = blockIdx.z, h = blockIdx.y, i0 = blockIdx.x * QT;
    int t = threadIdx.x, w = t >> 5, lane = t & 31;
    int qi = t >> 3, sub = t & 7;
    int iq = i0 + qi;

    uint32_t uQh = smem_to_u32(sQh), uQl = smem_to_u32(sQl);
    uint32_t uKh = smem_to_u32(sKh), uKl = smem_to_u32(sKl);
    uint32_t uVh = smem_to_u32(sVh), uVl = smem_to_u32(sVl);
    uint32_t uPh = smem_to_u32(pbh), uPl = smem_to_u32(pbl);

    {
        int r = t >> 3, u = t & 7;
        size_t g = ((size_t)(b * S_LEN + i0 + r)) * EMB + h * HDIM + u * 8;
        uint32_t sw = SW128((uint32_t)(r * 128 + u * 16));
        *(uint4*)((char*)sQh + sw) = *(const uint4*)(qh + g);
        *(uint4*)((char*)sQl + sw) = *(const uint4*)(ql + g);
    }

    int wm = w & 1;
    int wn = w >> 1;
    uint32_t aoff = (uint32_t)((wm * 16 + (lane & 15)) * 128 + ((lane >> 4) << 4));
    uint32_t boff = (uint32_t)((wn * 8 + (lane & 7)) * 128 + (((lane >> 3) & 1) << 4));
    uint32_t poff = (uint32_t)((wm * 16 + (lane & 15)) * 80 + ((lane >> 4) << 4));
    int vtile = lane >> 3, vrow = lane & 7;
    uint32_t voff = (uint32_t)(((vtile & 1) * 8 + vrow) * 128 +
                               wn * 32 + ((vtile >> 1) << 4));

    // hoist Q fragments (persistent across chunks)
    __syncthreads();
    uint32_t qfh[4][4], qfl[4][4];
#pragma unroll
    for (int ks = 0; ks < 4; ks++) {
        uint32_t kb = (uint32_t)(ks * 32);
        ldsm_x4(qfh[ks], uQh + SW128(aoff + kb));
        ldsm_x4(qfl[ks], uQl + SW128(aoff + kb));
    }

    float oacc[2][4] = {{0.f, 0.f, 0.f, 0.f}, {0.f, 0.f, 0.f, 0.f}};
    float m_run = -1e30f, l_run = 0.f;

    int lo = i0 - WIN; if (lo < 0) lo = 0;
    int hi = i0 + QT - 1 + WIN; if (hi > S_LEN - 1) hi = S_LEN - 1;
    int wstart = lo & ~(QT - 1);
    int nwin = (hi - wstart) / QT + 1;

    for (int ci = -1; ci < nwin; ci++) {
        bool gl = (ci < 0);
        int kstart = gl ? 0 : wstart + ci * QT;

        __syncthreads();
        {
            int r = t >> 3, u = t & 7;
            int p = kstart + r;
            uint32_t sw = SW128((uint32_t)(r * 128 + u * 16));
            uint4 z4 = make_uint4(0, 0, 0, 0);
            uint4 akh = z4, akl = z4, avh = z4, avl = z4;
            if (p < S_LEN) {
                size_t g = ((size_t)(b * S_LEN + p)) * EMB + h * HDIM + u * 8;
                akh = *(const uint4*)(kh + g);
                akl = *(const uint4*)(kl + g);
                avh = *(const uint4*)(vh + g);
                avl = *(const uint4*)(vl + g);
            }
            *(uint4*)((char*)sKh + sw) = akh;
            *(uint4*)((char*)sKl + sw) = akl;
            *(uint4*)((char*)sVh + sw) = avh;
            *(uint4*)((char*)sVl + sw) = avl;
            if (t < 32) {
                int p2 = kstart + t;
                msk[t] = (p2 < S_LEN) ? mask[b * S_LEN + p2] : 0;
            }
        }
        __syncthreads();

        {
            float f[4] = {0.f, 0.f, 0.f, 0.f};
#pragma unroll
            for (int ks = 0; ks < 4; ks++) {
                uint32_t kb = (uint32_t)(ks * 32);
                uint32_t b0[2], b1[2];
                ldsm_x2(b0, uKh + SW128(boff + kb));
                ldsm_x2(b1, uKl + SW128(boff + kb));
                mma16816(f, qfh[ks], b0[0], b0[1]);
                mma16816(f, qfh[ks], b1[0], b1[1]);
                mma16816(f, qfl[ks], b0[0], b0[1]);
            }
            int r = wm * 16 + (lane >> 2), c = wn * 8 + (lane & 3) * 2;
            *(float2*)&sc[r][c]     = make_float2(f[0], f[1]);
            *(float2*)&sc[r + 8][c] = make_float2(f[2], f[3]);
        }
        __syncthreads();

        {
            float4 s4 = *(float4*)&sc[qi][sub * 4];
            float sv[4] = {s4.x, s4.y, s4.z, s4.w};
            if (!gl) {
#pragma unroll
                for (int u2 = 0; u2 < 4; u2++) {
                    int j = sub * 4 + u2, p = kstart + j;
                    bool valid = (p < S_LEN) && (p >= iq - WIN) && (p <= iq + WIN);
                    if (!valid) sv[u2] = -1e30f;
                    else if (msk[j]) sv[u2] -= 10000.f;
                }
            }
            float cm = fmaxf(fmaxf(sv[0], sv[1]), fmaxf(sv[2], sv[3]));
            cm = fmaxf(cm, __shfl_xor_sync(0xffffffffu, cm, 1));
            cm = fmaxf(cm, __shfl_xor_sync(0xffffffffu, cm, 2));
            cm = fmaxf(cm, __shfl_xor_sync(0xffffffffu, cm, 4));
            float m_new = fmaxf(m_run, cm);
            float rsc = __expf(m_run - m_new);
            float psum = 0.f;
            __nv_bfloat16 eh[4], el[4];
#pragma unroll
            for (int u2 = 0; u2 < 4; u2++) {
                float e = __expf(sv[u2] - m_new);
                psum += e;
                eh[u2] = __float2bfloat16(e);
                el[u2] = __float2bfloat16(e - __bfloat162float(eh[u2]));
            }
            psum += __shfl_xor_sync(0xffffffffu, psum, 1);
            psum += __shfl_xor_sync(0xffffffffu, psum, 2);
            psum += __shfl_xor_sync(0xffffffffu, psum, 4);
            l_run = l_run * rsc + psum;
            m_run = m_new;
            *(uint2*)(pbh + qi * 40 + sub * 4) = *(const uint2*)eh;
            *(uint2*)(pbl + qi * 40 + sub * 4) = *(const uint2*)el;
            if (sub == 0) rs[qi] = rsc;
        }
        __syncthreads();

        {
            float r0 = rs[wm * 16 + (lane >> 2)];
            float r1 = rs[wm * 16 + 8 + (lane >> 2)];
#pragma unroll
            for (int ni = 0; ni < 2; ni++) {
                oacc[ni][0] *= r0; oacc[ni][1] *= r0;
                oacc[ni][2] *= r1; oacc[ni][3] *= r1;
            }
#pragma unroll
            for (int ks = 0; ks < 2; ks++) {
                uint32_t ap0[4], ap1[4], bv0[4], bv1[4];
                ldsm_x4(ap0, uPh + poff + ks * 32);
                ldsm_x4(ap1, uPl + poff + ks * 32);
                uint32_t va = SW128(voff + (uint32_t)(ks * 2048));
                ldsm_x4t(bv0, uVh + va);
                ldsm_x4t(bv1, uVl + va);
                mma16816(oacc[0], ap0, bv0[0], bv0[1]);
                mma16816(oacc[0], ap0, bv1[0], bv1[1]);
                mma16816(oacc[0], ap1, bv0[0], bv0[1]);
                mma16816(oacc[1], ap0, bv0[2], bv0[3]);
                mma16816(oacc[1], ap0, bv1[2], bv1[3]);
                mma16816(oacc[1], ap1, bv0[2], bv0[3]);
            }
        }
    }

    if (sub == 0) ls[qi] = l_run;
    __syncthreads();
    {
        float i0v = 1.f / ls[wm * 16 + (lane >> 2)];
        float i1v = 1.f / ls[wm * 16 + 8 + (lane >> 2)];
        int r = wm * 16 + (lane >> 2);
#pragma unroll
        for (int ni = 0; ni < 2; ni++) {
            int c = wn * 16 + ni * 8 + (lane & 3) * 2;
            size_t o0 = ((size_t)(b * S_LEN + i0 + r)) * EMB + h * HDIM + c;
            size_t o1 = ((size_t)(b * S_LEN + i0 + r + 8)) * EMB + h * HDIM + c;
            float2 v0; v0.x = oacc[ni][0] * i0v; v0.y = oacc[ni][1] * i0v;
            float2 v1; v1.x = oacc[ni][2] * i1v; v1.y = oacc[ni][3] * i1v;
            *(float2*)(out + o0) = v0;
            *(float2*)(out + o1) = v1;
        }
    }
}

// ---------------- Global rows: split-K partial flash ----------------
__global__ __launch_bounds__(256, 2) void global_part_kernel(
    const float* __restrict__ qg, const float* __restrict__ kg,
    const float* __restrict__ vg,
    float* __restrict__ po, float* __restrict__ pm, float* __restrict__ pl)
{
    __shared__ float ks[32][68];
    __shared__ float vs[32][68];
    __shared__ float sc[32][36];

    int seg = blockIdx.x, h = blockIdx.y, b = blockIdx.z;
    int t = threadIdx.x;
    int qi = t >> 3, sub = t & 7;

    u64 q2[32];
    {
        const ulonglong2* qrow = (const ulonglong2*)
            (qg + ((size_t)(b * GLB + qi)) * EMB + h * HDIM);
#pragma unroll
        for (int e = 0; e < 16; e++) {
            ulonglong2 t2 = qrow[e];
            q2[e * 2] = t2.x; q2[e * 2 + 1] = t2.y;
        }
    }
    u64 acc2[4] = {0ULL, 0ULL, 0ULL, 0ULL};
    float m_run = -1e30f, l_run = 0.f;

    for (int c = 0; c < SEGLEN / 32; c++) {
        int kstart = seg * SEGLEN + c * 32;
        __syncthreads();
        for (int u = t; u < 32 * 16; u += 256) {
            int r = u >> 4, cc = (u & 15) << 2;
            size_t off = ((size_t)(b * S_LEN + kstart + r)) * EMB + h * HDIM + cc;
            *(float4*)&ks[r][cc] = *(const float4*)(kg + off);
            *(float4*)&vs[r][cc] = *(const float4*)(vg + off);
        }
        __syncthreads();

        float sv[4];
#pragma unroll
        for (int u2 = 0; u2 < 4; u2++) {
            int j = sub * 4 + u2;
            const ulonglong2* kr = (const ulonglong2*)&ks[j][0];
            u64 s0 = 0ULL, s1 = 0ULL, s2 = 0ULL, s3 = 0ULL;
#pragma unroll
            for (int e = 0; e < 16; e += 2) {
                ulonglong2 ka = kr[e];
                ulonglong2 kb = kr[e + 1];
                s0 = ffma2(q2[e * 2],     ka.x, s0);
                s1 = ffma2(q2[e * 2 + 1], ka.y, s1);
                s2 = ffma2(q2[e * 2 + 2], kb.x, s2);
                s3 = ffma2(q2[e * 2 + 3], kb.y, s3);
            }
            float2 r2 = up2(fadd2(fadd2(s0, s1), fadd2(s2, s3)));
            sv[u2] = r2.x + r2.y;
        }
        float cm = fmaxf(fmaxf(sv[0], sv[1]), fmaxf(sv[2], sv[3]));
        cm = fmaxf(cm, __shfl_xor_sync(0xffffffffu, cm, 1));
        cm = fmaxf(cm, __shfl_xor_sync(0xffffffffu, cm, 2));
        cm = fmaxf(cm, __shfl_xor_sync(0xffffffffu, cm, 4));
        float m_new = fmaxf(m_run, cm);
        float rsc = __expf(m_run - m_new);
        float psum = 0.f;
#pragma unroll
        for (int u2 = 0; u2 < 4; u2++) {
            float e = __expf(sv[u2] - m_new);
            sc[qi][sub * 4 + u2] = e;
            psum += e;
        }
        psum += __shfl_xor_sync(0xffffffffu, psum, 1);
        psum += __shfl_xor_sync(0xffffffffu, psum, 2);
        psum += __shfl_xor_sync(0xffffffffu, psum, 4);
        l_run = l_run * rsc + psum;
        m_run = m_new;
        __syncwarp();

        u64 rb = dup2(rsc);
#pragma unroll
        for (int d = 0; d < 4; d++) acc2[d] = fmul2(acc2[d], rb);
#pragma unroll 4
        for (int j = 0; j < 32; j++) {
            u64 eb = dup2(sc[qi][j]);
            ulonglong2 v0 = *(const ulonglong2*)&vs[j][sub * 4];
            ulonglong2 v1 = *(const ulonglong2*)&vs[j][sub * 4 + 32];
            acc2[0] = ffma2(eb, v0.x, acc2[0]);
            acc2[1] = ffma2(eb, v0.y, acc2[1]);
            acc2[2] = ffma2(eb, v1.x, acc2[2]);
            acc2[3] = ffma2(eb, v1.y, acc2[3]);
        }
    }

    size_t pidx = (((size_t)seg * BATCH + b) * NH + h) * GLB + qi;
    float2 a0 = up2(acc2[0]), a1 = up2(acc2[1]);
    float2 a2 = up2(acc2[2]), a3 = up2(acc2[3]);
    float* prow = po + pidx * HDIM;
    *(float4*)(prow + sub * 4)      = make_float4(a0.x, a0.y, a1.x, a1.y);
    *(float4*)(prow + 32 + sub * 4) = make_float4(a2.x, a2.y, a3.x, a3.y);
    if (sub == 0) { pm[pidx] = m_run; pl[pidx] = l_run; }
}

__global__ __launch_bounds__(64) void global_merge_kernel(
    const float* __restrict__ po, const float* __restrict__ pm,
    const float* __restrict__ pl, float* __restrict__ out)
{
    int g = blockIdx.x, h = blockIdx.y, b = blockIdx.z;
    int d = threadIdx.x;

    float mv[NSEG];
    float mx = -1e30f;
#pragma unroll
    for (int s = 0; s < NSEG; s++) {
        mv[s] = pm[(((size_t)s * BATCH + b) * NH + h) * GLB + g];
        mx = fmaxf(mx, mv[s]);
    }
    float num = 0.f, den = 0.f;
#pragma unroll
    for (int s = 0; s < NSEG; s++) {
        size_t pidx = (((size_t)s * BATCH + b) * NH + h) * GLB + g;
        float w = __expf(mv[s] - mx);
        num += w * po[pidx * HDIM + d];
        den += w * pl[pidx];
    }
    out[((size_t)(b * S_LEN + g)) * EMB + h * HDIM + d] = num / den;
}

// ---------------- launch ----------------
extern "C" void kernel_launch(void* const* d_in, const int* in_sizes, int n_in,
                              void* d_out, int out_size)
{
    (void)n_in; (void)out_size;
    int base = (in_sizes[2] == EMB * EMB) ? 2 : 3;

    const float* x    = (const float*)d_in[0];
    const int*   mask = (const int*)d_in[1];
    const float* wq   = (const float*)d_in[base + 0];
    const float* bq   = (const float*)d_in[base + 1];
    const float* wk   = (const float*)d_in[base + 2];
    const float* bk   = (const float*)d_in[base + 3];
    const float* wv   = (const float*)d_in[base + 4];
    const float* bv   = (const float*)d_in[base + 5];
    const float* wqg  = (const float*)d_in[base + 6];
    const float* bqg  = (const float*)d_in[base + 7];
    const float* wkg  = (const float*)d_in[base + 8];
    const float* bkg  = (const float*)d_in[base + 9];
    const float* wvg  = (const float*)d_in[base + 10];
    const float* bvg  = (const float*)d_in[base + 11];
    float* out = (float*)d_out;

    float *kg, *vg, *qg, *po, *pm, *pl;
    __nv_bfloat16 *xh, *xl, *wth, *wtl, *qh, *ql, *kh, *kl, *vh, *vl;
    cudaGetSymbolAddress((void**)&kg,  g_kg);
    cudaGetSymbolAddress((void**)&vg,  g_vg);
    cudaGetSymbolAddress((void**)&qg,  g_qg);
    cudaGetSymbolAddress((void**)&xh,  g_xh);
    cudaGetSymbolAddress((void**)&xl,  g_xl);
    cudaGetSymbolAddress((void**)&wth, g_wth);
    cudaGetSymbolAddress((void**)&wtl, g_wtl);
    cudaGetSymbolAddress((void**)&qh,  g_qh);
    cudaGetSymbolAddress((void**)&ql,  g_ql);
    cudaGetSymbolAddress((void**)&kh,  g_kh);
    cudaGetSymbolAddress((void**)&kl,  g_kl);
    cudaGetSymbolAddress((void**)&vh,  g_vh);
    cudaGetSymbolAddress((void**)&vl,  g_vl);
    cudaGetSymbolAddress((void**)&po,  g_po);
    cudaGetSymbolAddress((void**)&pm,  g_pm);
    cudaGetSymbolAddress((void**)&pl,  g_pl);

    cudaFuncSetAttribute(mma_gemm6_kernel,
                         cudaFuncAttributeMaxDynamicSharedMemorySize, GSM2);

    convx_kernel<<<(BATCH * S_LEN * EMB) / (256 * 4), 256>>>(x, xh, xl);
    convw_kernel<<<dim3(EMB / 32, EMB / 32, 6), 256>>>(
        wq, wk, wv, wkg, wvg, wqg, wth, wtl);
    mma_gemm6_kernel<<<dim3(EMB / 64, BATCH * S_LEN / 128, 6), 256, GSM2>>>(
        xh, xl, wth, wtl, bq, bk, bv, bkg, bvg, bqg,
        qh, ql, kh, kl, vh, vl, kg, vg, qg);
    local_attn_mma<<<dim3(S_LEN / QT, NH, BATCH), 256>>>(
        qh, ql, kh, kl, vh, vl, mask, out);
    global_part_kernel<<<dim3(NSEG, NH, BATCH), 256>>>(qg, kg, vg, po, pm, pl);
    global_merge_kernel<<<dim3(GLB, NH, BATCH), 64>>>(po, pm, pl, out);
}

// round 9
// speedup vs baseline: 5.2918x; 1.2179x over previous
#include <cuda_runtime.h>
#include <cuda_fp16.h>
#include <cstdint>

#define S_LEN 4096
#define BATCH 2
#define EMB   768
#define NH    12
#define HDIM  64
#define WIN   256
#define GLB   32
#define QT    32
#define NSEG  8
#define SEGLEN (S_LEN / NSEG)

typedef unsigned long long u64;

// ---------- packed f32x2 helpers ----------
__device__ __forceinline__ u64 pk2(float x, float y) {
    u64 r; asm("mov.b64 %0, {%1,%2};" : "=l"(r) : "f"(x), "f"(y)); return r;
}
__device__ __forceinline__ u64 dup2(float x) { return pk2(x, x); }
__device__ __forceinline__ float2 up2(u64 v) {
    float2 f; asm("mov.b64 {%0,%1}, %2;" : "=f"(f.x), "=f"(f.y) : "l"(v)); return f;
}
__device__ __forceinline__ u64 ffma2(u64 a, u64 b, u64 c) {
    u64 d; asm("fma.rn.f32x2 %0, %1, %2, %3;" : "=l"(d) : "l"(a), "l"(b), "l"(c)); return d;
}
__device__ __forceinline__ u64 fadd2(u64 a, u64 b) {
    u64 d; asm("add.rn.f32x2 %0, %1, %2;" : "=l"(d) : "l"(a), "l"(b)); return d;
}
__device__ __forceinline__ u64 fmul2(u64 a, u64 b) {
    u64 d; asm("mul.rn.f32x2 %0, %1, %2;" : "=l"(d) : "l"(a), "l"(b)); return d;
}

__device__ __forceinline__ uint32_t smem_to_u32(const void* p) {
    uint32_t a;
    asm("{ .reg .u64 t; cvta.to.shared.u64 t, %1; cvt.u32.u64 %0, t; }" : "=r"(a) : "l"(p));
    return a;
}
#define SW128(o) ((o) ^ (((o) >> 3) & 0x70))

#define CP16(dst, src) \
    asm volatile("cp.async.cg.shared.global [%0], [%1], 16;" \
                 :: "r"(dst), "l"(src) : "memory")
#define CP_COMMIT() asm volatile("cp.async.commit_group;" ::: "memory")
#define CP_WAIT1()  asm volatile("cp.async.wait_group 1;" ::: "memory")

__device__ __forceinline__ void ldsm_x4(uint32_t* r, uint32_t addr) {
    asm volatile("ldmatrix.sync.aligned.m8n8.x4.shared.b16 {%0,%1,%2,%3}, [%4];"
                 : "=r"(r[0]), "=r"(r[1]), "=r"(r[2]), "=r"(r[3]) : "r"(addr));
}
__device__ __forceinline__ void ldsm_x2(uint32_t* r, uint32_t addr) {
    asm volatile("ldmatrix.sync.aligned.m8n8.x2.shared.b16 {%0,%1}, [%2];"
                 : "=r"(r[0]), "=r"(r[1]) : "r"(addr));
}
__device__ __forceinline__ void ldsm_x4t(uint32_t* r, uint32_t addr) {
    asm volatile("ldmatrix.sync.aligned.m8n8.x4.trans.shared.b16 {%0,%1,%2,%3}, [%4];"
                 : "=r"(r[0]), "=r"(r[1]), "=r"(r[2]), "=r"(r[3]) : "r"(addr));
}
// fp16 mma, fp32 accum
__device__ __forceinline__ void mma16816(float* c, const uint32_t* a,
                                         uint32_t b0, uint32_t b1) {
    asm volatile(
        "mma.sync.aligned.m16n8k16.row.col.f32.f16.f16.f32 "
        "{%0,%1,%2,%3}, {%4,%5,%6,%7}, {%8,%9}, {%0,%1,%2,%3};"
        : "+f"(c[0]), "+f"(c[1]), "+f"(c[2]), "+f"(c[3])
        : "r"(a[0]), "r"(a[1]), "r"(a[2]), "r"(a[3]), "r"(b0), "r"(b1));
}

// -------- scratch --------
__device__ float g_kg[BATCH * S_LEN * EMB];
__device__ float g_vg[BATCH * S_LEN * EMB];
__device__ float g_qg[BATCH * GLB * EMB];
__device__ __half g_xh[BATCH * S_LEN * EMB];
__device__ __half g_xl[BATCH * S_LEN * EMB];
__device__ __half g_wt[6 * EMB * EMB];
__device__ __half g_q1[BATCH * S_LEN * EMB];
__device__ __half g_q2[BATCH * S_LEN * EMB];
__device__ __half g_k1[BATCH * S_LEN * EMB];
__device__ __half g_v1[BATCH * S_LEN * EMB];
__device__ float g_po[NSEG * BATCH * NH * GLB * HDIM];
__device__ float g_pm[NSEG * BATCH * NH * GLB];
__device__ float g_pl[NSEG * BATCH * NH * GLB];

// ---------------- prep: x -> fp16 hi/lo ----------------
__global__ __launch_bounds__(256) void convx_kernel(
    const float* __restrict__ x, __half* __restrict__ xh,
    __half* __restrict__ xl)
{
    int i = (blockIdx.x * 256 + threadIdx.x) * 4;
    float4 a = *(const float4*)(x + i);
    __half h[4], l[4];
    float av[4] = {a.x, a.y, a.z, a.w};
#pragma unroll
    for (int j = 0; j < 4; j++) {
        h[j] = __float2half(av[j]);
        l[j] = __float2half(av[j] - __half2float(h[j]));
    }
    *(uint2*)(xh + i) = *(const uint2*)h;
    *(uint2*)(xl + i) = *(const uint2*)l;
}

// ---------------- prep: W -> W^T single fp16 (6 weights) ----------------
__global__ __launch_bounds__(256) void convw_kernel(
    const float* __restrict__ w0, const float* __restrict__ w1,
    const float* __restrict__ w2, const float* __restrict__ w3,
    const float* __restrict__ w4, const float* __restrict__ w5,
    __half* __restrict__ wt)
{
    __shared__ float tile[32][33];
    int z = blockIdx.z;
    const float* W = (z == 0) ? w0 : (z == 1) ? w1 : (z == 2) ? w2 :
                     (z == 3) ? w3 : (z == 4) ? w4 : w5;
    int kb = blockIdx.y * 32, nb = blockIdx.x * 32;
    int tx = threadIdx.x & 31, ty = threadIdx.x >> 5;
    for (int i = ty; i < 32; i += 8)
        tile[i][tx] = W[(size_t)(kb + i) * EMB + nb + tx];
    __syncthreads();
    for (int j = ty; j < 32; j += 8) {
        size_t o = (size_t)z * EMB * EMB + (size_t)(nb + j) * EMB + kb + tx;
        wt[o] = __float2half(tile[tx][j]);
    }
}

// ------- mma.sync GEMM, 128x64 CTA, 256 thr, cp.async 2-stage -------------
// D = xh*w + xl*w (x 2-term fp16, w single fp16, fp32 accum)
#define GST  40960                  // AH 16K, AL 16K, B 8K
#define GSM2 (2 * GST)              // 80 KB

__global__ __launch_bounds__(256) void mma_gemm6_kernel(
    const __half* __restrict__ xh, const __half* __restrict__ xl,
    const __half* __restrict__ wt,
    const float* __restrict__ bq, const float* __restrict__ bk,
    const float* __restrict__ bv, const float* __restrict__ bkg,
    const float* __restrict__ bvg, const float* __restrict__ bqg,
    __half* q1, __half* q2, __half* k1, __half* v1,
    float* kg, float* vg, float* qg)
{
    extern __shared__ char dsm[];
    int z = blockIdx.z;
    if (z == 5 && blockIdx.y > 0) return;
    int t = threadIdx.x, wid = t >> 5, lane = t & 31;
    int m0 = blockIdx.y * 128, n0 = blockIdx.x * 64;
    int wm = wid & 3, wn = wid >> 2;   // 4x2 warp grid, 32x32 warp tile

    const float* bias;
    switch (z) {
        case 0:  bias = bq;  break;
        case 1:  bias = bk;  break;
        case 2:  bias = bv;  break;
        case 3:  bias = bkg; break;
        case 4:  bias = bvg; break;
        default: bias = bqg; break;
    }
    float scale = (z == 0 || z == 5) ? 0.125f : 1.0f;
    const __half* Bw = wt + (size_t)z * EMB * EMB;

    uint32_t sb = smem_to_u32(dsm);

    float acc[2][4][4];
#pragma unroll
    for (int mi = 0; mi < 2; mi++)
#pragma unroll
        for (int ni = 0; ni < 4; ni++)
#pragma unroll
            for (int c = 0; c < 4; c++) acc[mi][ni][c] = 0.f;

    uint32_t a_off[2], b_off[2];
#pragma unroll
    for (int mi = 0; mi < 2; mi++) {
        int row = wm * 32 + mi * 16 + (lane & 15);
        a_off[mi] = (uint32_t)(row * 128) + ((lane >> 4) << 4);
    }
#pragma unroll
    for (int bi = 0; bi < 2; bi++) {
        int row = wn * 32 + bi * 16 + (lane & 15);
        b_off[bi] = (uint32_t)(row * 128) + ((lane >> 4) << 4);
    }

#define LOAD_STAGE(chunk, s) do {                                            \
        int k0 = (chunk) * 64;                                               \
        uint32_t base = sb + (s) * GST;                                      \
        _Pragma("unroll")                                                    \
        for (int i = 0; i < 4; i++) {                                        \
            int idx = t + i * 256;                                           \
            int r = idx >> 3, u = idx & 7;                                   \
            uint32_t sw = SW128((uint32_t)(r * 128 + u * 16));               \
            size_t arow;                                                     \
            if (z == 5) { int q2r = r & 63;                                  \
                arow = (size_t)((q2r >> 5) * S_LEN + (q2r & 31)); }          \
            else arow = (size_t)(m0 + r);                                    \
            CP16(base + sw,         xh + arow * EMB + k0 + u * 8);           \
            CP16(base + 16384 + sw, xl + arow * EMB + k0 + u * 8);           \
        }                                                                    \
        _Pragma("unroll")                                                    \
        for (int i = 0; i < 2; i++) {                                        \
            int idx = t + i * 256;                                           \
            int r = idx >> 3, u = idx & 7;                                   \
            uint32_t sw = SW128((uint32_t)(r * 128 + u * 16));               \
            CP16(base + 32768 + sw, Bw + (size_t)(n0 + r) * EMB + k0 + u * 8); \
        }                                                                    \
    } while (0)

    LOAD_STAGE(0, 0);
    CP_COMMIT();

    for (int c = 0; c < 12; c++) {
        if (c < 11) LOAD_STAGE(c + 1, (c + 1) & 1);
        CP_COMMIT();
        CP_WAIT1();
        __syncthreads();
        uint32_t base = sb + (c & 1) * GST;
        uint32_t uAh = base, uAl = base + 16384;
        uint32_t uB  = base + 32768;
#pragma unroll
        for (int ks = 0; ks < 4; ks++) {
            uint32_t kb = (uint32_t)(ks * 32);
            uint32_t ah[2][4], al[2][4], bw[2][4];
#pragma unroll
            for (int mi = 0; mi < 2; mi++) {
                uint32_t sw = SW128(a_off[mi] + kb);
                ldsm_x4(ah[mi], uAh + sw);
                ldsm_x4(al[mi], uAl + sw);
            }
#pragma unroll
            for (int bi = 0; bi < 2; bi++)
                ldsm_x4(bw[bi], uB + SW128(b_off[bi] + kb));
#pragma unroll
            for (int mi = 0; mi < 2; mi++)
#pragma unroll
                for (int ni = 0; ni < 4; ni++) {
                    int bi = ni >> 1, sel = ni & 1;
                    mma16816(acc[mi][ni], ah[mi], bw[bi][sel], bw[bi][sel + 2]);
                    mma16816(acc[mi][ni], al[mi], bw[bi][sel], bw[bi][sel + 2]);
                }
        }
        __syncthreads();
    }
#undef LOAD_STAGE

    int r = lane >> 2, cp = (lane & 3) * 2;
    if (z == 0) {
        // q: 2-term fp16 output
#pragma unroll
        for (int mi = 0; mi < 2; mi++) {
            int mbase = m0 + wm * 32 + mi * 16;
#pragma unroll
            for (int ni = 0; ni < 4; ni++) {
                int nbase = n0 + wn * 32 + ni * 8 + cp;
                float b0 = bias[nbase], b1 = bias[nbase + 1];
#pragma unroll
                for (int hr = 0; hr < 2; hr++) {
                    int row = mbase + r + hr * 8;
                    float v0 = (acc[mi][ni][hr * 2 + 0] + b0) * scale;
                    float v1 = (acc[mi][ni][hr * 2 + 1] + b1) * scale;
                    __half h0 = __float2half(v0);
                    __half h1 = __float2half(v1);
                    __half l0 = __float2half(v0 - __half2float(h0));
                    __half l1 = __float2half(v1 - __half2float(h1));
                    __half ph[2] = {h0, h1}, pl[2] = {l0, l1};
                    *(uint32_t*)(q1 + (size_t)row * EMB + nbase) = *(uint32_t*)ph;
                    *(uint32_t*)(q2 + (size_t)row * EMB + nbase) = *(uint32_t*)pl;
                }
            }
        }
    } else if (z == 1 || z == 2) {
        __half* Y = (z == 1) ? k1 : v1;
#pragma unroll
        for (int mi = 0; mi < 2; mi++) {
            int mbase = m0 + wm * 32 + mi * 16;
#pragma unroll
            for (int ni = 0; ni < 4; ni++) {
                int nbase = n0 + wn * 32 + ni * 8 + cp;
                float b0 = bias[nbase], b1 = bias[nbase + 1];
#pragma unroll
                for (int hr = 0; hr < 2; hr++) {
                    int row = mbase + r + hr * 8;
                    __half ph[2];
                    ph[0] = __float2half(acc[mi][ni][hr * 2 + 0] + b0);
                    ph[1] = __float2half(acc[mi][ni][hr * 2 + 1] + b1);
                    *(uint32_t*)(Y + (size_t)row * EMB + nbase) = *(uint32_t*)ph;
                }
            }
        }
    } else {
        float* Y = (z == 3) ? kg : (z == 4) ? vg : qg;
#pragma unroll
        for (int mi = 0; mi < 2; mi++) {
            int mbase = m0 + wm * 32 + mi * 16;
#pragma unroll
            for (int ni = 0; ni < 4; ni++) {
                int nbase = n0 + wn * 32 + ni * 8 + cp;
                float b0 = bias[nbase], b1 = bias[nbase + 1];
#pragma unroll
                for (int hr = 0; hr < 2; hr++) {
                    int row = mbase + r + hr * 8;
                    if (z == 5 && row >= BATCH * GLB) continue;
                    float2 o;
                    o.x = (acc[mi][ni][hr * 2 + 0] + b0) * scale;
                    o.y = (acc[mi][ni][hr * 2 + 1] + b1) * scale;
                    *(float2*)(Y + (size_t)row * EMB + nbase) = o;
                }
            }
        }
    }
}

// ---------------- Local attention, tensor-core flash (fp16) ----------------
__global__ __launch_bounds__(256) void local_attn_mma(
    const __half* __restrict__ q1, const __half* __restrict__ q2,
    const __half* __restrict__ k1, const __half* __restrict__ v1,
    const int* __restrict__ mask, float* __restrict__ out)
{
    __shared__ __align__(128) __half sQh[32 * 64], sQl[32 * 64];
    __shared__ __align__(128) __half sK[32 * 64];
    __shared__ __align__(128) __half sV[32 * 64];
    __shared__ float sc[32][36];
    __shared__ __align__(16) __half pbh[32 * 40], pbl[32 * 40];
    __shared__ float rs[32], ls[32];
    __shared__ int msk[32];

    int b = blockIdx.z, h = blockIdx.y, i0 = blockIdx.x * QT;
    int t = threadIdx.x, w = t >> 5, lane = t & 31;
    int qi = t >> 3, sub = t & 7;
    int iq = i0 + qi;

    uint32_t uQh = smem_to_u32(sQh), uQl = smem_to_u32(sQl);
    uint32_t uK = smem_to_u32(sK), uV = smem_to_u32(sV);
    uint32_t uPh = smem_to_u32(pbh), uPl = smem_to_u32(pbl);

    {
        int r = t >> 3, u = t & 7;
        size_t g = ((size_t)(b * S_LEN + i0 + r)) * EMB + h * HDIM + u * 8;
        uint32_t sw = SW128((uint32_t)(r * 128 + u * 16));
        *(uint4*)((char*)sQh + sw) = *(const uint4*)(q1 + g);
        *(uint4*)((char*)sQl + sw) = *(const uint4*)(q2 + g);
    }

    int wm = w & 1;
    int wn = w >> 1;
    uint32_t aoff = (uint32_t)((wm * 16 + (lane & 15)) * 128 + ((lane >> 4) << 4));
    uint32_t boff = (uint32_t)((wn * 8 + (lane & 7)) * 128 + (((lane >> 3) & 1) << 4));
    uint32_t poff = (uint32_t)((wm * 16 + (lane & 15)) * 80 + ((lane >> 4) << 4));
    int vtile = lane >> 3, vrow = lane & 7;
    uint32_t voff = (uint32_t)(((vtile & 1) * 8 + vrow) * 128 +
                               wn * 32 + ((vtile >> 1) << 4));

    // hoist Q fragments (persistent across chunks)
    __syncthreads();
    uint32_t qfh[4][4], qfl[4][4];
#pragma unroll
    for (int ks = 0; ks < 4; ks++) {
        uint32_t kb = (uint32_t)(ks * 32);
        ldsm_x4(qfh[ks], uQh + SW128(aoff + kb));
        ldsm_x4(qfl[ks], uQl + SW128(aoff + kb));
    }

    float oacc[2][4] = {{0.f, 0.f, 0.f, 0.f}, {0.f, 0.f, 0.f, 0.f}};
    float m_run = -1e30f, l_run = 0.f;

    int lo = i0 - WIN; if (lo < 0) lo = 0;
    int hi = i0 + QT - 1 + WIN; if (hi > S_LEN - 1) hi = S_LEN - 1;
    int wstart = lo & ~(QT - 1);
    int nwin = (hi - wstart) / QT + 1;

    for (int ci = -1; ci < nwin; ci++) {
        bool gl = (ci < 0);
        int kstart = gl ? 0 : wstart + ci * QT;

        __syncthreads();
        {
            int r = t >> 3, u = t & 7;
            int p = kstart + r;
            uint32_t sw = SW128((uint32_t)(r * 128 + u * 16));
            uint4 z4 = make_uint4(0, 0, 0, 0);
            uint4 ak = z4, av = z4;
            if (p < S_LEN) {
                size_t g = ((size_t)(b * S_LEN + p)) * EMB + h * HDIM + u * 8;
                ak = *(const uint4*)(k1 + g);
                av = *(const uint4*)(v1 + g);
            }
            *(uint4*)((char*)sK + sw) = ak;
            *(uint4*)((char*)sV + sw) = av;
            if (t < 32) {
                int p2 = kstart + t;
                msk[t] = (p2 < S_LEN) ? mask[b * S_LEN + p2] : 0;
            }
        }
        __syncthreads();

        {
            float f[4] = {0.f, 0.f, 0.f, 0.f};
#pragma unroll
            for (int ks = 0; ks < 4; ks++) {
                uint32_t kb = (uint32_t)(ks * 32);
                uint32_t b0[2];
                ldsm_x2(b0, uK + SW128(boff + kb));
                mma16816(f, qfh[ks], b0[0], b0[1]);
                mma16816(f, qfl[ks], b0[0], b0[1]);
            }
            int r = wm * 16 + (lane >> 2), c = wn * 8 + (lane & 3) * 2;
            *(float2*)&sc[r][c]     = make_float2(f[0], f[1]);
            *(float2*)&sc[r + 8][c] = make_float2(f[2], f[3]);
        }
        __syncthreads();

        {
            float4 s4 = *(float4*)&sc[qi][sub * 4];
            float sv[4] = {s4.x, s4.y, s4.z, s4.w};
            if (!gl) {
#pragma unroll
                for (int u2 = 0; u2 < 4; u2++) {
                    int j = sub * 4 + u2, p = kstart + j;
                    bool valid = (p < S_LEN) && (p >= iq - WIN) && (p <= iq + WIN);
                    if (!valid) sv[u2] = -1e30f;
                    else if (msk[j]) sv[u2] -= 10000.f;
                }
            }
            float cm = fmaxf(fmaxf(sv[0], sv[1]), fmaxf(sv[2], sv[3]));
            cm = fmaxf(cm, __shfl_xor_sync(0xffffffffu, cm, 1));
            cm = fmaxf(cm, __shfl_xor_sync(0xffffffffu, cm, 2));
            cm = fmaxf(cm, __shfl_xor_sync(0xffffffffu, cm, 4));
            float m_new = fmaxf(m_run, cm);
            float rsc = __expf(m_run - m_new);
            float psum = 0.f;
            __half eh[4], el[4];
#pragma unroll
            for (int u2 = 0; u2 < 4; u2++) {
                float e = __expf(sv[u2] - m_new);
                psum += e;
                eh[u2] = __float2half(e);
                el[u2] = __float2half(e - __half2float(eh[u2]));
            }
            psum += __shfl_xor_sync(0xffffffffu, psum, 1);
            psum += __shfl_xor_sync(0xffffffffu, psum, 2);
            psum += __shfl_xor_sync(0xffffffffu, psum, 4);
            l_run = l_run * rsc + psum;
            m_run = m_new;
            *(uint2*)(pbh + qi * 40 + sub * 4) = *(const uint2*)eh;
            *(uint2*)(pbl + qi * 40 + sub * 4) = *(const uint2*)el;
            if (sub == 0) rs[qi] = rsc;
        }
        __syncthreads();

        {
            float r0 = rs[wm * 16 + (lane >> 2)];
            float r1 = rs[wm * 16 + 8 + (lane >> 2)];
#pragma unroll
            for (int ni = 0; ni < 2; ni++) {
                oacc[ni][0] *= r0; oacc[ni][1] *= r0;
                oacc[ni][2] *= r1; oacc[ni][3] *= r1;
            }
#pragma unroll
            for (int ks = 0; ks < 2; ks++) {
                uint32_t ap0[4], ap1[4], bv0[4];
                ldsm_x4(ap0, uPh + poff + ks * 32);
                ldsm_x4(ap1, uPl + poff + ks * 32);
                ldsm_x4t(bv0, uV + SW128(voff + (uint32_t)(ks * 2048)));
                mma16816(oacc[0], ap0, bv0[0], bv0[1]);
                mma16816(oacc[0], ap1, bv0[0], bv0[1]);
                mma16816(oacc[1], ap0, bv0[2], bv0[3]);
                mma16816(oacc[1], ap1, bv0[2], bv0[3]);
            }
        }
    }

    if (sub == 0) ls[qi] = l_run;
    __syncthreads();
    {
        float i0v = 1.f / ls[wm * 16 + (lane >> 2)];
        float i1v = 1.f / ls[wm * 16 + 8 + (lane >> 2)];
        int r = wm * 16 + (lane >> 2);
#pragma unroll
        for (int ni = 0; ni < 2; ni++) {
            int c = wn * 16 + ni * 8 + (lane & 3) * 2;
            size_t o0 = ((size_t)(b * S_LEN + i0 + r)) * EMB + h * HDIM + c;
            size_t o1 = ((size_t)(b * S_LEN + i0 + r + 8)) * EMB + h * HDIM + c;
            float2 v0; v0.x = oacc[ni][0] * i0v; v0.y = oacc[ni][1] * i0v;
            float2 v1; v1.x = oacc[ni][2] * i1v; v1.y = oacc[ni][3] * i1v;
            *(float2*)(out + o0) = v0;
            *(float2*)(out + o1) = v1;
        }
    }
}

// ---------------- Global rows: split-K partial flash ----------------
__global__ __launch_bounds__(256, 2) void global_part_kernel(
    const float* __restrict__ qg, const float* __restrict__ kg,
    const float* __restrict__ vg,
    float* __restrict__ po, float* __restrict__ pm, float* __restrict__ pl)
{
    __shared__ float ks[32][68];
    __shared__ float vs[32][68];
    __shared__ float sc[32][36];

    int seg = blockIdx.x, h = blockIdx.y, b = blockIdx.z;
    int t = threadIdx.x;
    int qi = t >> 3, sub = t & 7;

    u64 q2[32];
    {
        const ulonglong2* qrow = (const ulonglong2*)
            (qg + ((size_t)(b * GLB + qi)) * EMB + h * HDIM);
#pragma unroll
        for (int e = 0; e < 16; e++) {
            ulonglong2 t2 = qrow[e];
            q2[e * 2] = t2.x; q2[e * 2 + 1] = t2.y;
        }
    }
    u64 acc2[4] = {0ULL, 0ULL, 0ULL, 0ULL};
    float m_run = -1e30f, l_run = 0.f;

    for (int c = 0; c < SEGLEN / 32; c++) {
        int kstart = seg * SEGLEN + c * 32;
        __syncthreads();
        for (int u = t; u < 32 * 16; u += 256) {
            int r = u >> 4, cc = (u & 15) << 2;
            size_t off = ((size_t)(b * S_LEN + kstart + r)) * EMB + h * HDIM + cc;
            *(float4*)&ks[r][cc] = *(const float4*)(kg + off);
            *(float4*)&vs[r][cc] = *(const float4*)(vg + off);
        }
        __syncthreads();

        float sv[4];
#pragma unroll
        for (int u2 = 0; u2 < 4; u2++) {
            int j = sub * 4 + u2;
            const ulonglong2* kr = (const ulonglong2*)&ks[j][0];
            u64 s0 = 0ULL, s1 = 0ULL, s2 = 0ULL, s3 = 0ULL;
#pragma unroll
            for (int e = 0; e < 16; e += 2) {
                ulonglong2 ka = kr[e];
                ulonglong2 kb = kr[e + 1];
                s0 = ffma2(q2[e * 2],     ka.x, s0);
                s1 = ffma2(q2[e * 2 + 1], ka.y, s1);
                s2 = ffma2(q2[e * 2 + 2], kb.x, s2);
                s3 = ffma2(q2[e * 2 + 3], kb.y, s3);
            }
            float2 r2 = up2(fadd2(fadd2(s0, s1), fadd2(s2, s3)));
            sv[u2] = r2.x + r2.y;
        }
        float cm = fmaxf(fmaxf(sv[0], sv[1]), fmaxf(sv[2], sv[3]));
        cm = fmaxf(cm, __shfl_xor_sync(0xffffffffu, cm, 1));
        cm = fmaxf(cm, __shfl_xor_sync(0xffffffffu, cm, 2));
        cm = fmaxf(cm, __shfl_xor_sync(0xffffffffu, cm, 4));
        float m_new = fmaxf(m_run, cm);
        float rsc = __expf(m_run - m_new);
        float psum = 0.f;
#pragma unroll
        for (int u2 = 0; u2 < 4; u2++) {
            float e = __expf(sv[u2] - m_new);
            sc[qi][sub * 4 + u2] = e;
            psum += e;
        }
        psum += __shfl_xor_sync(0xffffffffu, psum, 1);
        psum += __shfl_xor_sync(0xffffffffu, psum, 2);
        psum += __shfl_xor_sync(0xffffffffu, psum, 4);
        l_run = l_run * rsc + psum;
        m_run = m_new;
        __syncwarp();

        u64 rb = dup2(rsc);
#pragma unroll
        for (int d = 0; d < 4; d++) acc2[d] = fmul2(acc2[d], rb);
#pragma unroll 4
        for (int j = 0; j < 32; j++) {
            u64 eb = dup2(sc[qi][j]);
            ulonglong2 v0 = *(const ulonglong2*)&vs[j][sub * 4];
            ulonglong2 v1 = *(const ulonglong2*)&vs[j][sub * 4 + 32];
            acc2[0] = ffma2(eb, v0.x, acc2[0]);
            acc2[1] = ffma2(eb, v0.y, acc2[1]);
            acc2[2] = ffma2(eb, v1.x, acc2[2]);
            acc2[3] = ffma2(eb, v1.y, acc2[3]);
        }
    }

    size_t pidx = (((size_t)seg * BATCH + b) * NH + h) * GLB + qi;
    float2 a0 = up2(acc2[0]), a1 = up2(acc2[1]);
    float2 a2 = up2(acc2[2]), a3 = up2(acc2[3]);
    float* prow = po + pidx * HDIM;
    *(float4*)(prow + sub * 4)      = make_float4(a0.x, a0.y, a1.x, a1.y);
    *(float4*)(prow + 32 + sub * 4) = make_float4(a2.x, a2.y, a3.x, a3.y);
    if (sub == 0) { pm[pidx] = m_run; pl[pidx] = l_run; }
}

__global__ __launch_bounds__(64) void global_merge_kernel(
    const float* __restrict__ po, const float* __restrict__ pm,
    const float* __restrict__ pl, float* __restrict__ out)
{
    int g = blockIdx.x, h = blockIdx.y, b = blockIdx.z;
    int d = threadIdx.x;

    float mv[NSEG];
    float mx = -1e30f;
#pragma unroll
    for (int s = 0; s < NSEG; s++) {
        mv[s] = pm[(((size_t)s * BATCH + b) * NH + h) * GLB + g];
        mx = fmaxf(mx, mv[s]);
    }
    float num = 0.f, den = 0.f;
#pragma unroll
    for (int s = 0; s < NSEG; s++) {
        size_t pidx = (((size_t)s * BATCH + b) * NH + h) * GLB + g;
        float w = __expf(mv[s] - mx);
        num += w * po[pidx * HDIM + d];
        den += w * pl[pidx];
    }
    out[((size_t)(b * S_LEN + g)) * EMB + h * HDIM + d] = num / den;
}

// ---------------- launch ----------------
extern "C" void kernel_launch(void* const* d_in, const int* in_sizes, int n_in,
                              void* d_out, int out_size)
{
    (void)n_in; (void)out_size;
    int base = (in_sizes[2] == EMB * EMB) ? 2 : 3;

    const float* x    = (const float*)d_in[0];
    const int*   mask = (const int*)d_in[1];
    const float* wq   = (const float*)d_in[base + 0];
    const float* bq   = (const float*)d_in[base + 1];
    const float* wk   = (const float*)d_in[base + 2];
    const float* bk   = (const float*)d_in[base + 3];
    const float* wv   = (const float*)d_in[base + 4];
    const float* bv   = (const float*)d_in[base + 5];
    const float* wqg  = (const float*)d_in[base + 6];
    const float* bqg  = (const float*)d_in[base + 7];
    const float* wkg  = (const float*)d_in[base + 8];
    const float* bkg  = (const float*)d_in[base + 9];
    const float* wvg  = (const float*)d_in[base + 10];
    const float* bvg  = (const float*)d_in[base + 11];
    float* out = (float*)d_out;

    float *kg, *vg, *qg, *po, *pm, *pl;
    __half *xh, *xl, *wt, *q1, *q2, *k1, *v1;
    cudaGetSymbolAddress((void**)&kg, g_kg);
    cudaGetSymbolAddress((void**)&vg, g_vg);
    cudaGetSymbolAddress((void**)&qg, g_qg);
    cudaGetSymbolAddress((void**)&xh, g_xh);
    cudaGetSymbolAddress((void**)&xl, g_xl);
    cudaGetSymbolAddress((void**)&wt, g_wt);
    cudaGetSymbolAddress((void**)&q1, g_q1);
    cudaGetSymbolAddress((void**)&q2, g_q2);
    cudaGetSymbolAddress((void**)&k1, g_k1);
    cudaGetSymbolAddress((void**)&v1, g_v1);
    cudaGetSymbolAddress((void**)&po, g_po);
    cudaGetSymbolAddress((void**)&pm, g_pm);
    cudaGetSymbolAddress((void**)&pl, g_pl);

    cudaFuncSetAttribute(mma_gemm6_kernel,
                         cudaFuncAttributeMaxDynamicSharedMemorySize, GSM2);

    convx_kernel<<<(BATCH * S_LEN * EMB) / (256 * 4), 256>>>(x, xh, xl);
    convw_kernel<<<dim3(EMB / 32, EMB / 32, 6), 256>>>(
        wq, wk, wv, wkg, wvg, wqg, wt);
    mma_gemm6_kernel<<<dim3(EMB / 64, BATCH * S_LEN / 128, 6), 256, GSM2>>>(
        xh, xl, wt, bq, bk, bv, bkg, bvg, bqg,
        q1, q2, k1, v1, kg, vg, qg);
    local_attn_mma<<<dim3(S_LEN / QT, NH, BATCH), 256>>>(
        q1, q2, k1, v1, mask, out);
    global_part_kernel<<<dim3(NSEG, NH, BATCH), 256>>>(qg, kg, vg, po, pm, pl);
    global_merge_kernel<<<dim3(GLB, NH, BATCH), 64>>>(po, pm, pl, out);
}

// round 10
// speedup vs baseline: 5.5269x; 1.0444x over previous
#include <cuda_runtime.h>
#include <cuda_fp16.h>
#include <cstdint>

#define S_LEN 4096
#define BATCH 2
#define EMB   768
#define NH    12
#define HDIM  64
#define WIN   256
#define GLB   32
#define QT2   64
#define NSEG  8
#define SEGLEN (S_LEN / NSEG)

typedef unsigned long long u64;

// ---------- packed f32x2 helpers ----------
__device__ __forceinline__ u64 pk2(float x, float y) {
    u64 r; asm("mov.b64 %0, {%1,%2};" : "=l"(r) : "f"(x), "f"(y)); return r;
}
__device__ __forceinline__ u64 dup2(float x) { return pk2(x, x); }
__device__ __forceinline__ float2 up2(u64 v) {
    float2 f; asm("mov.b64 {%0,%1}, %2;" : "=f"(f.x), "=f"(f.y) : "l"(v)); return f;
}
__device__ __forceinline__ u64 ffma2(u64 a, u64 b, u64 c) {
    u64 d; asm("fma.rn.f32x2 %0, %1, %2, %3;" : "=l"(d) : "l"(a), "l"(b), "l"(c)); return d;
}
__device__ __forceinline__ u64 fadd2(u64 a, u64 b) {
    u64 d; asm("add.rn.f32x2 %0, %1, %2;" : "=l"(d) : "l"(a), "l"(b)); return d;
}
__device__ __forceinline__ u64 fmul2(u64 a, u64 b) {
    u64 d; asm("mul.rn.f32x2 %0, %1, %2;" : "=l"(d) : "l"(a), "l"(b)); return d;
}

__device__ __forceinline__ uint32_t smem_to_u32(const void* p) {
    uint32_t a;
    asm("{ .reg .u64 t; cvta.to.shared.u64 t, %1; cvt.u32.u64 %0, t; }" : "=r"(a) : "l"(p));
    return a;
}
#define SW128(o) ((o) ^ (((o) >> 3) & 0x70))
#define SW64(o)  ((o) ^ (((o) >> 3) & 0x30))

#define CP16(dst, src) \
    asm volatile("cp.async.cg.shared.global [%0], [%1], 16;" \
                 :: "r"(dst), "l"(src) : "memory")
#define CP_COMMIT() asm volatile("cp.async.commit_group;" ::: "memory")
#define CP_WAIT1()  asm volatile("cp.async.wait_group 1;" ::: "memory")

__device__ __forceinline__ void ldsm_x4(uint32_t* r, uint32_t addr) {
    asm volatile("ldmatrix.sync.aligned.m8n8.x4.shared.b16 {%0,%1,%2,%3}, [%4];"
                 : "=r"(r[0]), "=r"(r[1]), "=r"(r[2]), "=r"(r[3]) : "r"(addr));
}
__device__ __forceinline__ void ldsm_x4t(uint32_t* r, uint32_t addr) {
    asm volatile("ldmatrix.sync.aligned.m8n8.x4.trans.shared.b16 {%0,%1,%2,%3}, [%4];"
                 : "=r"(r[0]), "=r"(r[1]), "=r"(r[2]), "=r"(r[3]) : "r"(addr));
}
// fp16 mma, fp32 accum
__device__ __forceinline__ void mma16816(float* c, const uint32_t* a,
                                         uint32_t b0, uint32_t b1) {
    asm volatile(
        "mma.sync.aligned.m16n8k16.row.col.f32.f16.f16.f32 "
        "{%0,%1,%2,%3}, {%4,%5,%6,%7}, {%8,%9}, {%0,%1,%2,%3};"
        : "+f"(c[0]), "+f"(c[1]), "+f"(c[2]), "+f"(c[3])
        : "r"(a[0]), "r"(a[1]), "r"(a[2]), "r"(a[3]), "r"(b0), "r"(b1));
}

// -------- scratch --------
__device__ float g_kg[BATCH * S_LEN * EMB];
__device__ float g_vg[BATCH * S_LEN * EMB];
__device__ float g_qg[BATCH * GLB * EMB];
__device__ __half g_xh[BATCH * S_LEN * EMB];
__device__ __half g_xl[BATCH * S_LEN * EMB];
__device__ __half g_wt[6 * EMB * EMB];
__device__ __half g_q1[BATCH * S_LEN * EMB];
__device__ __half g_q2[BATCH * S_LEN * EMB];
__device__ __half g_k1[BATCH * S_LEN * EMB];
__device__ __half g_v1[BATCH * S_LEN * EMB];
__device__ float g_po[NSEG * BATCH * NH * GLB * HDIM];
__device__ float g_pm[NSEG * BATCH * NH * GLB];
__device__ float g_pl[NSEG * BATCH * NH * GLB];

// ---------------- prep: x -> fp16 hi/lo ----------------
__global__ __launch_bounds__(256) void convx_kernel(
    const float* __restrict__ x, __half* __restrict__ xh,
    __half* __restrict__ xl)
{
    int i = (blockIdx.x * 256 + threadIdx.x) * 4;
    float4 a = *(const float4*)(x + i);
    __half h[4], l[4];
    float av[4] = {a.x, a.y, a.z, a.w};
#pragma unroll
    for (int j = 0; j < 4; j++) {
        h[j] = __float2half(av[j]);
        l[j] = __float2half(av[j] - __half2float(h[j]));
    }
    *(uint2*)(xh + i) = *(const uint2*)h;
    *(uint2*)(xl + i) = *(const uint2*)l;
}

// ---------------- prep: W -> W^T single fp16 (6 weights) ----------------
__global__ __launch_bounds__(256) void convw_kernel(
    const float* __restrict__ w0, const float* __restrict__ w1,
    const float* __restrict__ w2, const float* __restrict__ w3,
    const float* __restrict__ w4, const float* __restrict__ w5,
    __half* __restrict__ wt)
{
    __shared__ float tile[32][33];
    int z = blockIdx.z;
    const float* W = (z == 0) ? w0 : (z == 1) ? w1 : (z == 2) ? w2 :
                     (z == 3) ? w3 : (z == 4) ? w4 : w5;
    int kb = blockIdx.y * 32, nb = blockIdx.x * 32;
    int tx = threadIdx.x & 31, ty = threadIdx.x >> 5;
    for (int i = ty; i < 32; i += 8)
        tile[i][tx] = W[(size_t)(kb + i) * EMB + nb + tx];
    __syncthreads();
    for (int j = ty; j < 32; j += 8) {
        size_t o = (size_t)z * EMB * EMB + (size_t)(nb + j) * EMB + kb + tx;
        wt[o] = __float2half(tile[tx][j]);
    }
}

// ------- mma.sync GEMM: 128x128 CTA, 256 thr, warp 32x64, k-chunk 32, SW64 --
#define GST  24576                  // AH 8K, AL 8K, B 8K per stage
#define GSM2 (2 * GST)              // 48 KB -> 2 CTAs/SM

__global__ __launch_bounds__(256, 2) void mma_gemm6_kernel(
    const __half* __restrict__ xh, const __half* __restrict__ xl,
    const __half* __restrict__ wt,
    const float* __restrict__ bq, const float* __restrict__ bk,
    const float* __restrict__ bv, const float* __restrict__ bkg,
    const float* __restrict__ bvg, const float* __restrict__ bqg,
    __half* q1, __half* q2, __half* k1, __half* v1,
    float* kg, float* vg, float* qg)
{
    extern __shared__ char dsm[];
    int z = blockIdx.z;
    if (z == 5 && blockIdx.y > 0) return;
    int t = threadIdx.x, wid = t >> 5, lane = t & 31;
    int m0 = blockIdx.y * 128, n0 = blockIdx.x * 128;
    int wm = wid & 3, wn = wid >> 2;   // warp tile 32(m) x 64(n)

    const float* bias;
    switch (z) {
        case 0:  bias = bq;  break;
        case 1:  bias = bk;  break;
        case 2:  bias = bv;  break;
        case 3:  bias = bkg; break;
        case 4:  bias = bvg; break;
        default: bias = bqg; break;
    }
    float scale = (z == 0 || z == 5) ? 0.125f : 1.0f;
    const __half* Bw = wt + (size_t)z * EMB * EMB;

    uint32_t sb = smem_to_u32(dsm);

    float acc[2][8][4];
#pragma unroll
    for (int mi = 0; mi < 2; mi++)
#pragma unroll
        for (int ni = 0; ni < 8; ni++)
#pragma unroll
            for (int c = 0; c < 4; c++) acc[mi][ni][c] = 0.f;

    uint32_t a_off[2], b_off[4];
#pragma unroll
    for (int mi = 0; mi < 2; mi++) {
        int row = wm * 32 + mi * 16 + (lane & 15);
        a_off[mi] = (uint32_t)(row * 64) + ((lane >> 4) << 4);
    }
#pragma unroll
    for (int bi = 0; bi < 4; bi++) {
        int row = wn * 64 + bi * 16 + (lane & 15);
        b_off[bi] = (uint32_t)(row * 64) + ((lane >> 4) << 4);
    }

#define LOAD_STAGE(chunk, s) do {                                            \
        int k0 = (chunk) * 32;                                               \
        uint32_t base = sb + (s) * GST;                                      \
        _Pragma("unroll")                                                    \
        for (int i = 0; i < 2; i++) {                                        \
            int idx = t + i * 256;                                           \
            int r = idx >> 2, u = idx & 3;                                   \
            uint32_t sw = SW64((uint32_t)(r * 64 + u * 16));                 \
            size_t arow;                                                     \
            if (z == 5) { int q2r = r & 63;                                  \
                arow = (size_t)((q2r >> 5) * S_LEN + (q2r & 31)); }          \
            else arow = (size_t)(m0 + r);                                    \
            CP16(base + sw,        xh + arow * EMB + k0 + u * 8);            \
            CP16(base + 8192 + sw, xl + arow * EMB + k0 + u * 8);            \
            CP16(base + 16384 + sw, Bw + (size_t)(n0 + r) * EMB + k0 + u * 8); \
        }                                                                    \
    } while (0)

    LOAD_STAGE(0, 0);
    CP_COMMIT();

    for (int c = 0; c < 24; c++) {
        if (c < 23) LOAD_STAGE(c + 1, (c + 1) & 1);
        CP_COMMIT();
        CP_WAIT1();
        __syncthreads();
        uint32_t base = sb + (c & 1) * GST;
        uint32_t uAh = base, uAl = base + 8192;
        uint32_t uB  = base + 16384;
#pragma unroll
        for (int ks = 0; ks < 2; ks++) {
            uint32_t kb = (uint32_t)(ks * 32);
            uint32_t ah[2][4], al[2][4];
#pragma unroll
            for (int mi = 0; mi < 2; mi++) {
                uint32_t sw = SW64(a_off[mi] + kb);
                ldsm_x4(ah[mi], uAh + sw);
                ldsm_x4(al[mi], uAl + sw);
            }
#pragma unroll
            for (int bi = 0; bi < 4; bi++) {
                uint32_t bw[4];
                ldsm_x4(bw, uB + SW64(b_off[bi] + kb));
#pragma unroll
                for (int sel = 0; sel < 2; sel++) {
                    int ni = bi * 2 + sel;
#pragma unroll
                    for (int mi = 0; mi < 2; mi++) {
                        mma16816(acc[mi][ni], ah[mi], bw[sel], bw[sel + 2]);
                        mma16816(acc[mi][ni], al[mi], bw[sel], bw[sel + 2]);
                    }
                }
            }
        }
        __syncthreads();
    }
#undef LOAD_STAGE

    int r = lane >> 2, cp = (lane & 3) * 2;
    if (z == 0) {
#pragma unroll
        for (int mi = 0; mi < 2; mi++) {
            int mbase = m0 + wm * 32 + mi * 16;
#pragma unroll
            for (int ni = 0; ni < 8; ni++) {
                int nbase = n0 + wn * 64 + ni * 8 + cp;
                float b0 = bias[nbase], b1 = bias[nbase + 1];
#pragma unroll
                for (int hr = 0; hr < 2; hr++) {
                    int row = mbase + r + hr * 8;
                    float v0 = (acc[mi][ni][hr * 2 + 0] + b0) * scale;
                    float v1 = (acc[mi][ni][hr * 2 + 1] + b1) * scale;
                    __half h0 = __float2half(v0);
                    __half h1 = __float2half(v1);
                    __half l0 = __float2half(v0 - __half2float(h0));
                    __half l1 = __float2half(v1 - __half2float(h1));
                    __half ph[2] = {h0, h1}, pl[2] = {l0, l1};
                    *(uint32_t*)(q1 + (size_t)row * EMB + nbase) = *(uint32_t*)ph;
                    *(uint32_t*)(q2 + (size_t)row * EMB + nbase) = *(uint32_t*)pl;
                }
            }
        }
    } else if (z == 1 || z == 2) {
        __half* Y = (z == 1) ? k1 : v1;
#pragma unroll
        for (int mi = 0; mi < 2; mi++) {
            int mbase = m0 + wm * 32 + mi * 16;
#pragma unroll
            for (int ni = 0; ni < 8; ni++) {
                int nbase = n0 + wn * 64 + ni * 8 + cp;
                float b0 = bias[nbase], b1 = bias[nbase + 1];
#pragma unroll
                for (int hr = 0; hr < 2; hr++) {
                    int row = mbase + r + hr * 8;
                    __half ph[2];
                    ph[0] = __float2half(acc[mi][ni][hr * 2 + 0] + b0);
                    ph[1] = __float2half(acc[mi][ni][hr * 2 + 1] + b1);
                    *(uint32_t*)(Y + (size_t)row * EMB + nbase) = *(uint32_t*)ph;
                }
            }
        }
    } else {
        float* Y = (z == 3) ? kg : (z == 4) ? vg : qg;
#pragma unroll
        for (int mi = 0; mi < 2; mi++) {
            int mbase = m0 + wm * 32 + mi * 16;
#pragma unroll
            for (int ni = 0; ni < 8; ni++) {
                int nbase = n0 + wn * 64 + ni * 8 + cp;
                float b0 = bias[nbase], b1 = bias[nbase + 1];
#pragma unroll
                for (int hr = 0; hr < 2; hr++) {
                    int row = mbase + r + hr * 8;
                    if (z == 5 && row >= BATCH * GLB) continue;
                    float2 o;
                    o.x = (acc[mi][ni][hr * 2 + 0] + b0) * scale;
                    o.y = (acc[mi][ni][hr * 2 + 1] + b1) * scale;
                    *(float2*)(Y + (size_t)row * EMB + nbase) = o;
                }
            }
        }
    }
}

// ---------------- Local attention, Q-tile 64, tensor-core flash ------------
__global__ __launch_bounds__(256) void local_attn_mma(
    const __half* __restrict__ q1, const __half* __restrict__ q2,
    const __half* __restrict__ k1, const __half* __restrict__ v1,
    const int* __restrict__ mask, float* __restrict__ out)
{
    __shared__ __align__(128) __half sQh[64 * 64], sQl[64 * 64];
    __shared__ __align__(128) __half sK[32 * 64];
    __shared__ __align__(128) __half sV[32 * 64];
    __shared__ float sc[64][36];
    __shared__ __align__(16) __half pbh[64 * 40], pbl[64 * 40];
    __shared__ float rs[64], ls[64];
    __shared__ int msk[32];

    int b = blockIdx.z, h = blockIdx.y, i0 = blockIdx.x * QT2;
    int t = threadIdx.x, w = t >> 5, lane = t & 31;
    int qi = t >> 2, sub = t & 3;       // 4 threads per query, 8 keys each
    int iq = i0 + qi;

    uint32_t uQh = smem_to_u32(sQh), uQl = smem_to_u32(sQl);
    uint32_t uK = smem_to_u32(sK), uV = smem_to_u32(sV);
    uint32_t uPh = smem_to_u32(pbh), uPl = smem_to_u32(pbl);

    // load Q tile (64 rows)
#pragma unroll
    for (int i = 0; i < 2; i++) {
        int idx = t + i * 256;
        int r = idx >> 3, u = idx & 7;
        size_t g = ((size_t)(b * S_LEN + i0 + r)) * EMB + h * HDIM + u * 8;
        uint32_t sw = SW128((uint32_t)(r * 128 + u * 16));
        *(uint4*)((char*)sQh + sw) = *(const uint4*)(q1 + g);
        *(uint4*)((char*)sQl + sw) = *(const uint4*)(q2 + g);
    }

    int wm = w & 3;        // m-tile (16 rows) for QK and PV
    int wn = w >> 2;       // QK: key group (16); PV: dim group (32)
    uint32_t aoff = (uint32_t)((wm * 16 + (lane & 15)) * 128 + ((lane >> 4) << 4));
    uint32_t boff = (uint32_t)((wn * 16 + (lane & 15)) * 128 + ((lane >> 4) << 4));
    uint32_t poff = (uint32_t)((wm * 16 + (lane & 15)) * 80 + ((lane >> 4) << 4));
    int vtile = lane >> 3, vrow = lane & 7;
    uint32_t vbase0 = (uint32_t)(((vtile & 1) * 8 + vrow) * 128 +
                                 wn * 64 + ((vtile >> 1) << 4));

    // hoist Q fragments
    __syncthreads();
    uint32_t qfh[4][4], qfl[4][4];
#pragma unroll
    for (int ks = 0; ks < 4; ks++) {
        uint32_t kb = (uint32_t)(ks * 32);
        ldsm_x4(qfh[ks], uQh + SW128(aoff + kb));
        ldsm_x4(qfl[ks], uQl + SW128(aoff + kb));
    }

    float oacc[4][4];
#pragma unroll
    for (int ni = 0; ni < 4; ni++)
#pragma unroll
        for (int c = 0; c < 4; c++) oacc[ni][c] = 0.f;
    float m_run = -1e30f, l_run = 0.f;

    int lo = i0 - WIN; if (lo < 0) lo = 0;
    int hi = i0 + QT2 - 1 + WIN; if (hi > S_LEN - 1) hi = S_LEN - 1;
    int wstart = lo & ~31;
    int nwin = (hi - wstart) / 32 + 1;

    for (int ci = -1; ci < nwin; ci++) {
        bool gl = (ci < 0);
        int kstart = gl ? 0 : wstart + ci * 32;

        __syncthreads();
        {
            int r = t >> 3, u = t & 7;
            int p = kstart + r;
            uint32_t sw = SW128((uint32_t)(r * 128 + u * 16));
            uint4 z4 = make_uint4(0, 0, 0, 0);
            uint4 ak = z4, av = z4;
            if (p < S_LEN) {
                size_t g = ((size_t)(b * S_LEN + p)) * EMB + h * HDIM + u * 8;
                ak = *(const uint4*)(k1 + g);
                av = *(const uint4*)(v1 + g);
            }
            *(uint4*)((char*)sK + sw) = ak;
            *(uint4*)((char*)sV + sw) = av;
            if (t < 32) {
                int p2 = kstart + t;
                msk[t] = (p2 < S_LEN) ? mask[b * S_LEN + p2] : 0;
            }
        }
        __syncthreads();

        // QK: warp computes m16(wm) x n16(wn) scores, K=64, 2-term
        {
            float f0[4] = {0.f, 0.f, 0.f, 0.f};
            float f1[4] = {0.f, 0.f, 0.f, 0.f};
#pragma unroll
            for (int ks = 0; ks < 4; ks++) {
                uint32_t bw[4];
                ldsm_x4(bw, uK + SW128(boff + (uint32_t)(ks * 32)));
                mma16816(f0, qfh[ks], bw[0], bw[2]);
                mma16816(f0, qfl[ks], bw[0], bw[2]);
                mma16816(f1, qfh[ks], bw[1], bw[3]);
                mma16816(f1, qfl[ks], bw[1], bw[3]);
            }
            int r = wm * 16 + (lane >> 2), c = wn * 16 + (lane & 3) * 2;
            *(float2*)&sc[r][c]         = make_float2(f0[0], f0[1]);
            *(float2*)&sc[r + 8][c]     = make_float2(f0[2], f0[3]);
            *(float2*)&sc[r][c + 8]     = make_float2(f1[0], f1[1]);
            *(float2*)&sc[r + 8][c + 8] = make_float2(f1[2], f1[3]);
        }
        __syncthreads();

        // scalar online softmax (4 threads per query, 8 keys each)
        {
            float4 s4a = *(float4*)&sc[qi][sub * 8];
            float4 s4b = *(float4*)&sc[qi][sub * 8 + 4];
            float sv[8] = {s4a.x, s4a.y, s4a.z, s4a.w, s4b.x, s4b.y, s4b.z, s4b.w};
            if (!gl) {
#pragma unroll
                for (int u2 = 0; u2 < 8; u2++) {
                    int j = sub * 8 + u2, p = kstart + j;
                    bool valid = (p < S_LEN) && (p >= iq - WIN) && (p <= iq + WIN);
                    if (!valid) sv[u2] = -1e30f;
                    else if (msk[j]) sv[u2] -= 10000.f;
                }
            }
            float cm = sv[0];
#pragma unroll
            for (int u2 = 1; u2 < 8; u2++) cm = fmaxf(cm, sv[u2]);
            cm = fmaxf(cm, __shfl_xor_sync(0xffffffffu, cm, 1));
            cm = fmaxf(cm, __shfl_xor_sync(0xffffffffu, cm, 2));
            float m_new = fmaxf(m_run, cm);
            float rsc = __expf(m_run - m_new);
            float psum = 0.f;
            __half eh[8], el[8];
#pragma unroll
            for (int u2 = 0; u2 < 8; u2++) {
                float e = __expf(sv[u2] - m_new);
                psum += e;
                eh[u2] = __float2half(e);
                el[u2] = __float2half(e - __half2float(eh[u2]));
            }
            psum += __shfl_xor_sync(0xffffffffu, psum, 1);
            psum += __shfl_xor_sync(0xffffffffu, psum, 2);
            l_run = l_run * rsc + psum;
            m_run = m_new;
            *(uint4*)(pbh + qi * 40 + sub * 8) = *(const uint4*)eh;
            *(uint4*)(pbl + qi * 40 + sub * 8) = *(const uint4*)el;
            if (sub == 0) rs[qi] = rsc;
        }
        __syncthreads();

        // PV: warp accumulates m16(wm) x dims [wn*32, wn*32+31]
        {
            float r0 = rs[wm * 16 + (lane >> 2)];
            float r1 = rs[wm * 16 + 8 + (lane >> 2)];
#pragma unroll
            for (int ni = 0; ni < 4; ni++) {
                oacc[ni][0] *= r0; oacc[ni][1] *= r0;
                oacc[ni][2] *= r1; oacc[ni][3] *= r1;
            }
#pragma unroll
            for (int ks = 0; ks < 2; ks++) {
                uint32_t ap0[4], ap1[4];
                ldsm_x4(ap0, uPh + poff + ks * 32);
                ldsm_x4(ap1, uPl + poff + ks * 32);
#pragma unroll
                for (int hs = 0; hs < 2; hs++) {
                    uint32_t bv0[4];
                    uint32_t va = SW128(vbase0 + (uint32_t)(hs * 32) +
                                        (uint32_t)(ks * 2048));
                    ldsm_x4t(bv0, uV + va);
                    mma16816(oacc[hs * 2 + 0], ap0, bv0[0], bv0[1]);
                    mma16816(oacc[hs * 2 + 0], ap1, bv0[0], bv0[1]);
                    mma16816(oacc[hs * 2 + 1], ap0, bv0[2], bv0[3]);
                    mma16816(oacc[hs * 2 + 1], ap1, bv0[2], bv0[3]);
                }
            }
        }
    }

    if (sub == 0) ls[qi] = l_run;
    __syncthreads();
    {
        float i0v = 1.f / ls[wm * 16 + (lane >> 2)];
        float i1v = 1.f / ls[wm * 16 + 8 + (lane >> 2)];
        int r = wm * 16 + (lane >> 2);
#pragma unroll
        for (int ni = 0; ni < 4; ni++) {
            int c = wn * 32 + ni * 8 + (lane & 3) * 2;
            size_t o0 = ((size_t)(b * S_LEN + i0 + r)) * EMB + h * HDIM + c;
            size_t o1 = ((size_t)(b * S_LEN + i0 + r + 8)) * EMB + h * HDIM + c;
            float2 v0; v0.x = oacc[ni][0] * i0v; v0.y = oacc[ni][1] * i0v;
            float2 v1; v1.x = oacc[ni][2] * i1v; v1.y = oacc[ni][3] * i1v;
            *(float2*)(out + o0) = v0;
            *(float2*)(out + o1) = v1;
        }
    }
}

// ---------------- Global rows: split-K partial flash ----------------
__global__ __launch_bounds__(256, 2) void global_part_kernel(
    const float* __restrict__ qg, const float* __restrict__ kg,
    const float* __restrict__ vg,
    float* __restrict__ po, float* __restrict__ pm, float* __restrict__ pl)
{
    __shared__ float ks[32][68];
    __shared__ float vs[32][68];
    __shared__ float sc[32][36];

    int seg = blockIdx.x, h = blockIdx.y, b = blockIdx.z;
    int t = threadIdx.x;
    int qi = t >> 3, sub = t & 7;

    u64 q2[32];
    {
        const ulonglong2* qrow = (const ulonglong2*)
            (qg + ((size_t)(b * GLB + qi)) * EMB + h * HDIM);
#pragma unroll
        for (int e = 0; e < 16; e++) {
            ulonglong2 t2 = qrow[e];
            q2[e * 2] = t2.x; q2[e * 2 + 1] = t2.y;
        }
    }
    u64 acc2[4] = {0ULL, 0ULL, 0ULL, 0ULL};
    float m_run = -1e30f, l_run = 0.f;

    for (int c = 0; c < SEGLEN / 32; c++) {
        int kstart = seg * SEGLEN + c * 32;
        __syncthreads();
        for (int u = t; u < 32 * 16; u += 256) {
            int r = u >> 4, cc = (u & 15) << 2;
            size_t off = ((size_t)(b * S_LEN + kstart + r)) * EMB + h * HDIM + cc;
            *(float4*)&ks[r][cc] = *(const float4*)(kg + off);
            *(float4*)&vs[r][cc] = *(const float4*)(vg + off);
        }
        __syncthreads();

        float sv[4];
#pragma unroll
        for (int u2 = 0; u2 < 4; u2++) {
            int j = sub * 4 + u2;
            const ulonglong2* kr = (const ulonglong2*)&ks[j][0];
            u64 s0 = 0ULL, s1 = 0ULL, s2 = 0ULL, s3 = 0ULL;
#pragma unroll
            for (int e = 0; e < 16; e += 2) {
                ulonglong2 ka = kr[e];
                ulonglong2 kb = kr[e + 1];
                s0 = ffma2(q2[e * 2],     ka.x, s0);
                s1 = ffma2(q2[e * 2 + 1], ka.y, s1);
                s2 = ffma2(q2[e * 2 + 2], kb.x, s2);
                s3 = ffma2(q2[e * 2 + 3], kb.y, s3);
            }
            float2 r2 = up2(fadd2(fadd2(s0, s1), fadd2(s2, s3)));
            sv[u2] = r2.x + r2.y;
        }
        float cm = fmaxf(fmaxf(sv[0], sv[1]), fmaxf(sv[2], sv[3]));
        cm = fmaxf(cm, __shfl_xor_sync(0xffffffffu, cm, 1));
        cm = fmaxf(cm, __shfl_xor_sync(0xffffffffu, cm, 2));
        cm = fmaxf(cm, __shfl_xor_sync(0xffffffffu, cm, 4));
        float m_new = fmaxf(m_run, cm);
        float rsc = __expf(m_run - m_new);
        float psum = 0.f;
#pragma unroll
        for (int u2 = 0; u2 < 4; u2++) {
            float e = __expf(sv[u2] - m_new);
            sc[qi][sub * 4 + u2] = e;
            psum += e;
        }
        psum += __shfl_xor_sync(0xffffffffu, psum, 1);
        psum += __shfl_xor_sync(0xffffffffu, psum, 2);
        psum += __shfl_xor_sync(0xffffffffu, psum, 4);
        l_run = l_run * rsc + psum;
        m_run = m_new;
        __syncwarp();

        u64 rb = dup2(rsc);
#pragma unroll
        for (int d = 0; d < 4; d++) acc2[d] = fmul2(acc2[d], rb);
#pragma unroll 4
        for (int j = 0; j < 32; j++) {
            u64 eb = dup2(sc[qi][j]);
            ulonglong2 v0 = *(const ulonglong2*)&vs[j][sub * 4];
            ulonglong2 v1 = *(const ulonglong2*)&vs[j][sub * 4 + 32];
            acc2[0] = ffma2(eb, v0.x, acc2[0]);
            acc2[1] = ffma2(eb, v0.y, acc2[1]);
            acc2[2] = ffma2(eb, v1.x, acc2[2]);
            acc2[3] = ffma2(eb, v1.y, acc2[3]);
        }
    }

    size_t pidx = (((size_t)seg * BATCH + b) * NH + h) * GLB + qi;
    float2 a0 = up2(acc2[0]), a1 = up2(acc2[1]);
    float2 a2 = up2(acc2[2]), a3 = up2(acc2[3]);
    float* prow = po + pidx * HDIM;
    *(float4*)(prow + sub * 4)      = make_float4(a0.x, a0.y, a1.x, a1.y);
    *(float4*)(prow + 32 + sub * 4) = make_float4(a2.x, a2.y, a3.x, a3.y);
    if (sub == 0) { pm[pidx] = m_run; pl[pidx] = l_run; }
}

__global__ __launch_bounds__(64) void global_merge_kernel(
    const float* __restrict__ po, const float* __restrict__ pm,
    const float* __restrict__ pl, float* __restrict__ out)
{
    int g = blockIdx.x, h = blockIdx.y, b = blockIdx.z;
    int d = threadIdx.x;

    float mv[NSEG];
    float mx = -1e30f;
#pragma unroll
    for (int s = 0; s < NSEG; s++) {
        mv[s] = pm[(((size_t)s * BATCH + b) * NH + h) * GLB + g];
        mx = fmaxf(mx, mv[s]);
    }
    float num = 0.f, den = 0.f;
#pragma unroll
    for (int s = 0; s < NSEG; s++) {
        size_t pidx = (((size_t)s * BATCH + b) * NH + h) * GLB + g;
        float w = __expf(mv[s] - mx);
        num += w * po[pidx * HDIM + d];
        den += w * pl[pidx];
    }
    out[((size_t)(b * S_LEN + g)) * EMB + h * HDIM + d] = num / den;
}

// ---------------- launch ----------------
extern "C" void kernel_launch(void* const* d_in, const int* in_sizes, int n_in,
                              void* d_out, int out_size)
{
    (void)n_in; (void)out_size;
    int base = (in_sizes[2] == EMB * EMB) ? 2 : 3;

    const float* x    = (const float*)d_in[0];
    const int*   mask = (const int*)d_in[1];
    const float* wq   = (const float*)d_in[base + 0];
    const float* bq   = (const float*)d_in[base + 1];
    const float* wk   = (const float*)d_in[base + 2];
    const float* bk   = (const float*)d_in[base + 3];
    const float* wv   = (const float*)d_in[base + 4];
    const float* bv   = (const float*)d_in[base + 5];
    const float* wqg  = (const float*)d_in[base + 6];
    const float* bqg  = (const float*)d_in[base + 7];
    const float* wkg  = (const float*)d_in[base + 8];
    const float* bkg  = (const float*)d_in[base + 9];
    const float* wvg  = (const float*)d_in[base + 10];
    const float* bvg  = (const float*)d_in[base + 11];
    float* out = (float*)d_out;

    float *kg, *vg, *qg, *po, *pm, *pl;
    __half *xh, *xl, *wt, *q1, *q2, *k1, *v1;
    cudaGetSymbolAddress((void**)&kg, g_kg);
    cudaGetSymbolAddress((void**)&vg, g_vg);
    cudaGetSymbolAddress((void**)&qg, g_qg);
    cudaGetSymbolAddress((void**)&xh, g_xh);
    cudaGetSymbolAddress((void**)&xl, g_xl);
    cudaGetSymbolAddress((void**)&wt, g_wt);
    cudaGetSymbolAddress((void**)&q1, g_q1);
    cudaGetSymbolAddress((void**)&q2, g_q2);
    cudaGetSymbolAddress((void**)&k1, g_k1);
    cudaGetSymbolAddress((void**)&v1, g_v1);
    cudaGetSymbolAddress((void**)&po, g_po);
    cudaGetSymbolAddress((void**)&pm, g_pm);
    cudaGetSymbolAddress((void**)&pl, g_pl);

    cudaFuncSetAttribute(mma_gemm6_kernel,
                         cudaFuncAttributeMaxDynamicSharedMemorySize, GSM2);

    convx_kernel<<<(BATCH * S_LEN * EMB) / (256 * 4), 256>>>(x, xh, xl);
    convw_kernel<<<dim3(EMB / 32, EMB / 32, 6), 256>>>(
        wq, wk, wv, wkg, wvg, wqg, wt);
    mma_gemm6_kernel<<<dim3(EMB / 128, BATCH * S_LEN / 128, 6), 256, GSM2>>>(
        xh, xl, wt, bq, bk, bv, bkg, bvg, bqg,
        q1, q2, k1, v1, kg, vg, qg);
    local_attn_mma<<<dim3(S_LEN / QT2, NH, BATCH), 256>>>(
        q1, q2, k1, v1, mask, out);
    global_part_kernel<<<dim3(NSEG, NH, BATCH), 256>>>(qg, kg, vg, po, pm, pl);
    global_merge_kernel<<<dim3(GLB, NH, BATCH), 64>>>(po, pm, pl, out);
}

// round 11
// speedup vs baseline: 5.8339x; 1.0555x over previous
#include <cuda_runtime.h>
#include <cuda_fp16.h>
#include <cstdint>

#define S_LEN 4096
#define BATCH 2
#define EMB   768
#define NH    12
#define HDIM  64
#define WIN   256
#define GLB   32
#define QT2   64
#define NSEG  16
#define SEGLEN (S_LEN / NSEG)

typedef unsigned long long u64;

// ---------- packed f32x2 helpers ----------
__device__ __forceinline__ u64 pk2(float x, float y) {
    u64 r; asm("mov.b64 %0, {%1,%2};" : "=l"(r) : "f"(x), "f"(y)); return r;
}
__device__ __forceinline__ u64 dup2(float x) { return pk2(x, x); }
__device__ __forceinline__ float2 up2(u64 v) {
    float2 f; asm("mov.b64 {%0,%1}, %2;" : "=f"(f.x), "=f"(f.y) : "l"(v)); return f;
}
__device__ __forceinline__ u64 ffma2(u64 a, u64 b, u64 c) {
    u64 d; asm("fma.rn.f32x2 %0, %1, %2, %3;" : "=l"(d) : "l"(a), "l"(b), "l"(c)); return d;
}
__device__ __forceinline__ u64 fadd2(u64 a, u64 b) {
    u64 d; asm("add.rn.f32x2 %0, %1, %2;" : "=l"(d) : "l"(a), "l"(b)); return d;
}
__device__ __forceinline__ u64 fmul2(u64 a, u64 b) {
    u64 d; asm("mul.rn.f32x2 %0, %1, %2;" : "=l"(d) : "l"(a), "l"(b)); return d;
}

__device__ __forceinline__ uint32_t smem_to_u32(const void* p) {
    uint32_t a;
    asm("{ .reg .u64 t; cvta.to.shared.u64 t, %1; cvt.u32.u64 %0, t; }" : "=r"(a) : "l"(p));
    return a;
}
#define SW128(o) ((o) ^ (((o) >> 3) & 0x70))
#define SW64(o)  ((o) ^ (((o) >> 3) & 0x30))

#define CP16(dst, src) \
    asm volatile("cp.async.cg.shared.global [%0], [%1], 16;" \
                 :: "r"(dst), "l"(src) : "memory")
#define CPZ16(dst, src, pred) do { \
    int _sz = (pred) ? 16 : 0; \
    asm volatile("cp.async.cg.shared.global [%0], [%1], 16, %2;" \
                 :: "r"(dst), "l"(src), "r"(_sz) : "memory"); } while (0)
#define CPZ4(dst, src, pred) do { \
    int _sz = (pred) ? 4 : 0; \
    asm volatile("cp.async.ca.shared.global [%0], [%1], 4, %2;" \
                 :: "r"(dst), "l"(src), "r"(_sz) : "memory"); } while (0)
#define CP_COMMIT() asm volatile("cp.async.commit_group;" ::: "memory")
#define CP_WAIT1()  asm volatile("cp.async.wait_group 1;" ::: "memory")

__device__ __forceinline__ void ldsm_x4(uint32_t* r, uint32_t addr) {
    asm volatile("ldmatrix.sync.aligned.m8n8.x4.shared.b16 {%0,%1,%2,%3}, [%4];"
                 : "=r"(r[0]), "=r"(r[1]), "=r"(r[2]), "=r"(r[3]) : "r"(addr));
}
__device__ __forceinline__ void ldsm_x4t(uint32_t* r, uint32_t addr) {
    asm volatile("ldmatrix.sync.aligned.m8n8.x4.trans.shared.b16 {%0,%1,%2,%3}, [%4];"
                 : "=r"(r[0]), "=r"(r[1]), "=r"(r[2]), "=r"(r[3]) : "r"(addr));
}
// fp16 mma, fp32 accum
__device__ __forceinline__ void mma16816(float* c, const uint32_t* a,
                                         uint32_t b0, uint32_t b1) {
    asm volatile(
        "mma.sync.aligned.m16n8k16.row.col.f32.f16.f16.f32 "
        "{%0,%1,%2,%3}, {%4,%5,%6,%7}, {%8,%9}, {%0,%1,%2,%3};"
        : "+f"(c[0]), "+f"(c[1]), "+f"(c[2]), "+f"(c[3])
        : "r"(a[0]), "r"(a[1]), "r"(a[2]), "r"(a[3]), "r"(b0), "r"(b1));
}

// -------- scratch --------
__device__ float g_kg[BATCH * S_LEN * EMB];
__device__ float g_vg[BATCH * S_LEN * EMB];
__device__ float g_qg[BATCH * GLB * EMB];
__device__ __half g_xh[BATCH * S_LEN * EMB];
__device__ __half g_xl[BATCH * S_LEN * EMB];
__device__ __half g_wt[6 * EMB * EMB];
__device__ __half g_q1[BATCH * S_LEN * EMB];
__device__ __half g_q2[BATCH * S_LEN * EMB];
__device__ __half g_k1[BATCH * S_LEN * EMB];
__device__ __half g_v1[BATCH * S_LEN * EMB];
__device__ float g_po[NSEG * BATCH * NH * GLB * HDIM];
__device__ float g_pm[NSEG * BATCH * NH * GLB];
__device__ float g_pl[NSEG * BATCH * NH * GLB];

// ---------------- prep: x -> fp16 hi/lo ----------------
__global__ __launch_bounds__(256) void convx_kernel(
    const float* __restrict__ x, __half* __restrict__ xh,
    __half* __restrict__ xl)
{
    int i = (blockIdx.x * 256 + threadIdx.x) * 4;
    float4 a = *(const float4*)(x + i);
    __half h[4], l[4];
    float av[4] = {a.x, a.y, a.z, a.w};
#pragma unroll
    for (int j = 0; j < 4; j++) {
        h[j] = __float2half(av[j]);
        l[j] = __float2half(av[j] - __half2float(h[j]));
    }
    *(uint2*)(xh + i) = *(const uint2*)h;
    *(uint2*)(xl + i) = *(const uint2*)l;
}

// ---------------- prep: W -> W^T single fp16 (6 weights) ----------------
__global__ __launch_bounds__(256) void convw_kernel(
    const float* __restrict__ w0, const float* __restrict__ w1,
    const float* __restrict__ w2, const float* __restrict__ w3,
    const float* __restrict__ w4, const float* __restrict__ w5,
    __half* __restrict__ wt)
{
    __shared__ float tile[32][33];
    int z = blockIdx.z;
    const float* W = (z == 0) ? w0 : (z == 1) ? w1 : (z == 2) ? w2 :
                     (z == 3) ? w3 : (z == 4) ? w4 : w5;
    int kb = blockIdx.y * 32, nb = blockIdx.x * 32;
    int tx = threadIdx.x & 31, ty = threadIdx.x >> 5;
    for (int i = ty; i < 32; i += 8)
        tile[i][tx] = W[(size_t)(kb + i) * EMB + nb + tx];
    __syncthreads();
    for (int j = ty; j < 32; j += 8) {
        size_t o = (size_t)z * EMB * EMB + (size_t)(nb + j) * EMB + kb + tx;
        wt[o] = __float2half(tile[tx][j]);
    }
}

// ------- mma.sync GEMM: 128x128 CTA, 256 thr, warp 32x64, k-chunk 32, SW64 --
#define GST  24576
#define GSM2 (2 * GST)

__global__ __launch_bounds__(256, 2) void mma_gemm6_kernel(
    const __half* __restrict__ xh, const __half* __restrict__ xl,
    const __half* __restrict__ wt,
    const float* __restrict__ bq, const float* __restrict__ bk,
    const float* __restrict__ bv, const float* __restrict__ bkg,
    const float* __restrict__ bvg, const float* __restrict__ bqg,
    __half* q1, __half* q2, __half* k1, __half* v1,
    float* kg, float* vg, float* qg)
{
    extern __shared__ char dsm[];
    int z = blockIdx.z;
    if (z == 5 && blockIdx.y > 0) return;
    int t = threadIdx.x, wid = t >> 5, lane = t & 31;
    int m0 = blockIdx.y * 128, n0 = blockIdx.x * 128;
    int wm = wid & 3, wn = wid >> 2;

    const float* bias;
    switch (z) {
        case 0:  bias = bq;  break;
        case 1:  bias = bk;  break;
        case 2:  bias = bv;  break;
        case 3:  bias = bkg; break;
        case 4:  bias = bvg; break;
        default: bias = bqg; break;
    }
    float scale = (z == 0 || z == 5) ? 0.125f : 1.0f;
    const __half* Bw = wt + (size_t)z * EMB * EMB;

    uint32_t sb = smem_to_u32(dsm);

    float acc[2][8][4];
#pragma unroll
    for (int mi = 0; mi < 2; mi++)
#pragma unroll
        for (int ni = 0; ni < 8; ni++)
#pragma unroll
            for (int c = 0; c < 4; c++) acc[mi][ni][c] = 0.f;

    uint32_t a_off[2], b_off[4];
#pragma unroll
    for (int mi = 0; mi < 2; mi++) {
        int row = wm * 32 + mi * 16 + (lane & 15);
        a_off[mi] = (uint32_t)(row * 64) + ((lane >> 4) << 4);
    }
#pragma unroll
    for (int bi = 0; bi < 4; bi++) {
        int row = wn * 64 + bi * 16 + (lane & 15);
        b_off[bi] = (uint32_t)(row * 64) + ((lane >> 4) << 4);
    }

#define LOAD_STAGE(chunk, s) do {                                            \
        int k0 = (chunk) * 32;                                               \
        uint32_t base = sb + (s) * GST;                                      \
        _Pragma("unroll")                                                    \
        for (int i = 0; i < 2; i++) {                                        \
            int idx = t + i * 256;                                           \
            int r = idx >> 2, u = idx & 3;                                   \
            uint32_t sw = SW64((uint32_t)(r * 64 + u * 16));                 \
            size_t arow;                                                     \
            if (z == 5) { int q2r = r & 63;                                  \
                arow = (size_t)((q2r >> 5) * S_LEN + (q2r & 31)); }          \
            else arow = (size_t)(m0 + r);                                    \
            CP16(base + sw,        xh + arow * EMB + k0 + u * 8);            \
            CP16(base + 8192 + sw, xl + arow * EMB + k0 + u * 8);            \
            CP16(base + 16384 + sw, Bw + (size_t)(n0 + r) * EMB + k0 + u * 8); \
        }                                                                    \
    } while (0)

    LOAD_STAGE(0, 0);
    CP_COMMIT();

    for (int c = 0; c < 24; c++) {
        if (c < 23) LOAD_STAGE(c + 1, (c + 1) & 1);
        CP_COMMIT();
        CP_WAIT1();
        __syncthreads();
        uint32_t base = sb + (c & 1) * GST;
        uint32_t uAh = base, uAl = base + 8192;
        uint32_t uB  = base + 16384;
#pragma unroll
        for (int ks = 0; ks < 2; ks++) {
            uint32_t kb = (uint32_t)(ks * 32);
            uint32_t ah[2][4], al[2][4];
#pragma unroll
            for (int mi = 0; mi < 2; mi++) {
                uint32_t sw = SW64(a_off[mi] + kb);
                ldsm_x4(ah[mi], uAh + sw);
                ldsm_x4(al[mi], uAl + sw);
            }
#pragma unroll
            for (int bi = 0; bi < 4; bi++) {
                uint32_t bw[4];
                ldsm_x4(bw, uB + SW64(b_off[bi] + kb));
#pragma unroll
                for (int sel = 0; sel < 2; sel++) {
                    int ni = bi * 2 + sel;
#pragma unroll
                    for (int mi = 0; mi < 2; mi++) {
                        mma16816(acc[mi][ni], ah[mi], bw[sel], bw[sel + 2]);
                        mma16816(acc[mi][ni], al[mi], bw[sel], bw[sel + 2]);
                    }
                }
            }
        }
        __syncthreads();
    }
#undef LOAD_STAGE

    int r = lane >> 2, cp = (lane & 3) * 2;
    if (z == 0) {
#pragma unroll
        for (int mi = 0; mi < 2; mi++) {
            int mbase = m0 + wm * 32 + mi * 16;
#pragma unroll
            for (int ni = 0; ni < 8; ni++) {
                int nbase = n0 + wn * 64 + ni * 8 + cp;
                float b0 = bias[nbase], b1 = bias[nbase + 1];
#pragma unroll
                for (int hr = 0; hr < 2; hr++) {
                    int row = mbase + r + hr * 8;
                    float v0 = (acc[mi][ni][hr * 2 + 0] + b0) * scale;
                    float v1 = (acc[mi][ni][hr * 2 + 1] + b1) * scale;
                    __half h0 = __float2half(v0);
                    __half h1 = __float2half(v1);
                    __half l0 = __float2half(v0 - __half2float(h0));
                    __half l1 = __float2half(v1 - __half2float(h1));
                    __half ph[2] = {h0, h1}, pl[2] = {l0, l1};
                    *(uint32_t*)(q1 + (size_t)row * EMB + nbase) = *(uint32_t*)ph;
                    *(uint32_t*)(q2 + (size_t)row * EMB + nbase) = *(uint32_t*)pl;
                }
            }
        }
    } else if (z == 1 || z == 2) {
        __half* Y = (z == 1) ? k1 : v1;
#pragma unroll
        for (int mi = 0; mi < 2; mi++) {
            int mbase = m0 + wm * 32 + mi * 16;
#pragma unroll
            for (int ni = 0; ni < 8; ni++) {
                int nbase = n0 + wn * 64 + ni * 8 + cp;
                float b0 = bias[nbase], b1 = bias[nbase + 1];
#pragma unroll
                for (int hr = 0; hr < 2; hr++) {
                    int row = mbase + r + hr * 8;
                    __half ph[2];
                    ph[0] = __float2half(acc[mi][ni][hr * 2 + 0] + b0);
                    ph[1] = __float2half(acc[mi][ni][hr * 2 + 1] + b1);
                    *(uint32_t*)(Y + (size_t)row * EMB + nbase) = *(uint32_t*)ph;
                }
            }
        }
    } else {
        float* Y = (z == 3) ? kg : (z == 4) ? vg : qg;
#pragma unroll
        for (int mi = 0; mi < 2; mi++) {
            int mbase = m0 + wm * 32 + mi * 16;
#pragma unroll
            for (int ni = 0; ni < 8; ni++) {
                int nbase = n0 + wn * 64 + ni * 8 + cp;
                float b0 = bias[nbase], b1 = bias[nbase + 1];
#pragma unroll
                for (int hr = 0; hr < 2; hr++) {
                    int row = mbase + r + hr * 8;
                    if (z == 5 && row >= BATCH * GLB) continue;
                    float2 o;
                    o.x = (acc[mi][ni][hr * 2 + 0] + b0) * scale;
                    o.y = (acc[mi][ni][hr * 2 + 1] + b1) * scale;
                    *(float2*)(Y + (size_t)row * EMB + nbase) = o;
                }
            }
        }
    }
}

// ---------------- Local attention, Q-tile 64, cp.async double-buffered -----
#define L_QH 0
#define L_QL 8192
#define L_K  16384          // + s*4096, 2 stages
#define L_V  24576          // + s*4096, 2 stages
#define L_SC 32768          // float[64][36]
#define L_PH 41984          // half[64*40]
#define L_PL 47104
#define L_RS 52224          // float[64]
#define L_LS 52480          // float[64]
#define L_MS 52736          // int[2][32]
#define L_TOTAL 53248

__global__ __launch_bounds__(256) void local_attn_mma(
    const __half* __restrict__ q1, const __half* __restrict__ q2,
    const __half* __restrict__ k1, const __half* __restrict__ v1,
    const int* __restrict__ mask, float* __restrict__ out)
{
    extern __shared__ char lsm[];
    uint32_t sbase = smem_to_u32(lsm);
    float* sc = (float*)(lsm + L_SC);
    __half* pbh = (__half*)(lsm + L_PH);
    __half* pbl = (__half*)(lsm + L_PL);
    float* rs = (float*)(lsm + L_RS);
    float* ls = (float*)(lsm + L_LS);
    int* msk = (int*)(lsm + L_MS);

    int b = blockIdx.z, h = blockIdx.y, i0 = blockIdx.x * QT2;
    int t = threadIdx.x, w = t >> 5, lane = t & 31;
    int qi = t >> 2, sub = t & 3;       // 4 threads per query, 8 keys each
    int iq = i0 + qi;

    uint32_t uQh = sbase + L_QH, uQl = sbase + L_QL;
    uint32_t uPh = sbase + L_PH, uPl = sbase + L_PL;

    // load Q tile (64 rows)
#pragma unroll
    for (int i = 0; i < 2; i++) {
        int idx = t + i * 256;
        int r = idx >> 3, u = idx & 7;
        size_t g = ((size_t)(b * S_LEN + i0 + r)) * EMB + h * HDIM + u * 8;
        uint32_t sw = SW128((uint32_t)(r * 128 + u * 16));
        *(uint4*)(lsm + L_QH + sw) = *(const uint4*)(q1 + g);
        *(uint4*)(lsm + L_QL + sw) = *(const uint4*)(q2 + g);
    }

    int lo = i0 - WIN; if (lo < 0) lo = 0;
    int hi = i0 + QT2 - 1 + WIN; if (hi > S_LEN - 1) hi = S_LEN - 1;
    int wstart = lo & ~31;
    int nwin = (hi - wstart) / 32 + 1;

    // K/V/mask chunk loader: stage s
#define LOAD_KV(kstart_, s_) do {                                            \
        int r_ = t >> 3, u_ = t & 7;                                         \
        int p_ = (kstart_) + r_;                                             \
        int ok_ = p_ < S_LEN;                                                \
        int pc_ = ok_ ? p_ : (S_LEN - 1);                                    \
        size_t g_ = ((size_t)(b * S_LEN + pc_)) * EMB + h * HDIM + u_ * 8;   \
        uint32_t sw_ = SW128((uint32_t)(r_ * 128 + u_ * 16));                \
        CPZ16(sbase + L_K + (s_) * 4096 + sw_, k1 + g_, ok_);                \
        CPZ16(sbase + L_V + (s_) * 4096 + sw_, v1 + g_, ok_);                \
        if (t < 32) {                                                        \
            int p2_ = (kstart_) + t;                                         \
            int ok2_ = p2_ < S_LEN;                                          \
            const int* ms_ = mask + b * S_LEN + (ok2_ ? p2_ : (S_LEN - 1));  \
            CPZ4(sbase + L_MS + (s_) * 128 + t * 4, ms_, ok2_);              \
        }                                                                    \
    } while (0)

    // preload chunk -1 (global keys, kstart 0) into stage 0
    LOAD_KV(0, 0);
    CP_COMMIT();

    int wm = w & 3;
    int wn = w >> 2;
    uint32_t aoff = (uint32_t)((wm * 16 + (lane & 15)) * 128 + ((lane >> 4) << 4));
    uint32_t boff = (uint32_t)((wn * 16 + (lane & 15)) * 128 + ((lane >> 4) << 4));
    uint32_t poff = (uint32_t)((wm * 16 + (lane & 15)) * 80 + ((lane >> 4) << 4));
    int vtile = lane >> 3, vrow = lane & 7;
    uint32_t vbase0 = (uint32_t)(((vtile & 1) * 8 + vrow) * 128 +
                                 wn * 64 + ((vtile >> 1) << 4));

    // hoist Q fragments
    __syncthreads();
    uint32_t qfh[4][4], qfl[4][4];
#pragma unroll
    for (int ks = 0; ks < 4; ks++) {
        uint32_t kb = (uint32_t)(ks * 32);
        ldsm_x4(qfh[ks], uQh + SW128(aoff + kb));
        ldsm_x4(qfl[ks], uQl + SW128(aoff + kb));
    }

    float oacc[4][4];
#pragma unroll
    for (int ni = 0; ni < 4; ni++)
#pragma unroll
        for (int c = 0; c < 4; c++) oacc[ni][c] = 0.f;
    float m_run = -1e30f, l_run = 0.f;

    for (int ci = -1; ci < nwin; ci++) {
        bool gl = (ci < 0);
        int kstart = gl ? 0 : wstart + ci * 32;
        int s = (ci + 1) & 1;

        __syncthreads();   // all warps done reading stage s^1 (prev chunk)
        if (ci + 1 < nwin) LOAD_KV(wstart + (ci + 1) * 32, s ^ 1);
        CP_COMMIT();
        CP_WAIT1();        // stage s loads (issued last iter) complete
        __syncthreads();

        uint32_t uK = sbase + L_K + s * 4096;
        uint32_t uV = sbase + L_V + s * 4096;
        const int* mskS = msk + s * 32;

        // QK: warp computes m16(wm) x n16(wn) scores, K=64, 2-term
        {
            float f0[4] = {0.f, 0.f, 0.f, 0.f};
            float f1[4] = {0.f, 0.f, 0.f, 0.f};
#pragma unroll
            for (int ks = 0; ks < 4; ks++) {
                uint32_t bw[4];
                ldsm_x4(bw, uK + SW128(boff + (uint32_t)(ks * 32)));
                mma16816(f0, qfh[ks], bw[0], bw[2]);
                mma16816(f0, qfl[ks], bw[0], bw[2]);
                mma16816(f1, qfh[ks], bw[1], bw[3]);
                mma16816(f1, qfl[ks], bw[1], bw[3]);
            }
            int r = wm * 16 + (lane >> 2), c = wn * 16 + (lane & 3) * 2;
            *(float2*)&sc[r * 36 + c]           = make_float2(f0[0], f0[1]);
            *(float2*)&sc[(r + 8) * 36 + c]     = make_float2(f0[2], f0[3]);
            *(float2*)&sc[r * 36 + c + 8]       = make_float2(f1[0], f1[1]);
            *(float2*)&sc[(r + 8) * 36 + c + 8] = make_float2(f1[2], f1[3]);
        }
        __syncthreads();

        // scalar online softmax (4 threads per query, 8 keys each)
        {
            float4 s4a = *(float4*)&sc[qi * 36 + sub * 8];
            float4 s4b = *(float4*)&sc[qi * 36 + sub * 8 + 4];
            float sv[8] = {s4a.x, s4a.y, s4a.z, s4a.w, s4b.x, s4b.y, s4b.z, s4b.w};
            if (!gl) {
#pragma unroll
                for (int u2 = 0; u2 < 8; u2++) {
                    int j = sub * 8 + u2, p = kstart + j;
                    bool valid = (p < S_LEN) && (p >= iq - WIN) && (p <= iq + WIN);
                    if (!valid) sv[u2] = -1e30f;
                    else if (mskS[j]) sv[u2] -= 10000.f;
                }
            }
            float cm = sv[0];
#pragma unroll
            for (int u2 = 1; u2 < 8; u2++) cm = fmaxf(cm, sv[u2]);
            cm = fmaxf(cm, __shfl_xor_sync(0xffffffffu, cm, 1));
            cm = fmaxf(cm, __shfl_xor_sync(0xffffffffu, cm, 2));
            float m_new = fmaxf(m_run, cm);
            float rsc = __expf(m_run - m_new);
            float psum = 0.f;
            __half eh[8], el[8];
#pragma unroll
            for (int u2 = 0; u2 < 8; u2++) {
                float e = __expf(sv[u2] - m_new);
                psum += e;
                eh[u2] = __float2half(e);
                el[u2] = __float2half(e - __half2float(eh[u2]));
            }
            psum += __shfl_xor_sync(0xffffffffu, psum, 1);
            psum += __shfl_xor_sync(0xffffffffu, psum, 2);
            l_run = l_run * rsc + psum;
            m_run = m_new;
            *(uint4*)(pbh + qi * 40 + sub * 8) = *(const uint4*)eh;
            *(uint4*)(pbl + qi * 40 + sub * 8) = *(const uint4*)el;
            if (sub == 0) rs[qi] = rsc;
        }
        __syncthreads();

        // PV: warp accumulates m16(wm) x dims [wn*32, wn*32+31]
        {
            float r0 = rs[wm * 16 + (lane >> 2)];
            float r1 = rs[wm * 16 + 8 + (lane >> 2)];
#pragma unroll
            for (int ni = 0; ni < 4; ni++) {
                oacc[ni][0] *= r0; oacc[ni][1] *= r0;
                oacc[ni][2] *= r1; oacc[ni][3] *= r1;
            }
#pragma unroll
            for (int ks = 0; ks < 2; ks++) {
                uint32_t ap0[4], ap1[4];
                ldsm_x4(ap0, uPh + poff + ks * 32);
                ldsm_x4(ap1, uPl + poff + ks * 32);
#pragma unroll
                for (int hs = 0; hs < 2; hs++) {
                    uint32_t bv0[4];
                    uint32_t va = SW128(vbase0 + (uint32_t)(hs * 32) +
                                        (uint32_t)(ks * 2048));
                    ldsm_x4t(bv0, uV + va);
                    mma16816(oacc[hs * 2 + 0], ap0, bv0[0], bv0[1]);
                    mma16816(oacc[hs * 2 + 0], ap1, bv0[0], bv0[1]);
                    mma16816(oacc[hs * 2 + 1], ap0, bv0[2], bv0[3]);
                    mma16816(oacc[hs * 2 + 1], ap1, bv0[2], bv0[3]);
                }
            }
        }
    }
#undef LOAD_KV

    if (sub == 0) ls[qi] = l_run;
    __syncthreads();
    {
        float i0v = 1.f / ls[wm * 16 + (lane >> 2)];
        float i1v = 1.f / ls[wm * 16 + 8 + (lane >> 2)];
        int r = wm * 16 + (lane >> 2);
#pragma unroll
        for (int ni = 0; ni < 4; ni++) {
            int c = wn * 32 + ni * 8 + (lane & 3) * 2;
            size_t o0 = ((size_t)(b * S_LEN + i0 + r)) * EMB + h * HDIM + c;
            size_t o1 = ((size_t)(b * S_LEN + i0 + r + 8)) * EMB + h * HDIM + c;
            float2 v0; v0.x = oacc[ni][0] * i0v; v0.y = oacc[ni][1] * i0v;
            float2 v1; v1.x = oacc[ni][2] * i1v; v1.y = oacc[ni][3] * i1v;
            *(float2*)(out + o0) = v0;
            *(float2*)(out + o1) = v1;
        }
    }
}

// ---------------- Global rows: split-K partial flash ----------------
__global__ __launch_bounds__(256, 2) void global_part_kernel(
    const float* __restrict__ qg, const float* __restrict__ kg,
    const float* __restrict__ vg,
    float* __restrict__ po, float* __restrict__ pm, float* __restrict__ pl)
{
    __shared__ float ks[32][68];
    __shared__ float vs[32][68];
    __shared__ float sc[32][36];

    int seg = blockIdx.x, h = blockIdx.y, b = blockIdx.z;
    int t = threadIdx.x;
    int qi = t >> 3, sub = t & 7;

    u64 q2[32];
    {
        const ulonglong2* qrow = (const ulonglong2*)
            (qg + ((size_t)(b * GLB + qi)) * EMB + h * HDIM);
#pragma unroll
        for (int e = 0; e < 16; e++) {
            ulonglong2 t2 = qrow[e];
            q2[e * 2] = t2.x; q2[e * 2 + 1] = t2.y;
        }
    }
    u64 acc2[4] = {0ULL, 0ULL, 0ULL, 0ULL};
    float m_run = -1e30f, l_run = 0.f;

    for (int c = 0; c < SEGLEN / 32; c++) {
        int kstart = seg * SEGLEN + c * 32;
        __syncthreads();
        for (int u = t; u < 32 * 16; u += 256) {
            int r = u >> 4, cc = (u & 15) << 2;
            size_t off = ((size_t)(b * S_LEN + kstart + r)) * EMB + h * HDIM + cc;
            *(float4*)&ks[r][cc] = *(const float4*)(kg + off);
            *(float4*)&vs[r][cc] = *(const float4*)(vg + off);
        }
        __syncthreads();

        float sv[4];
#pragma unroll
        for (int u2 = 0; u2 < 4; u2++) {
            int j = sub * 4 + u2;
            const ulonglong2* kr = (const ulonglong2*)&ks[j][0];
            u64 s0 = 0ULL, s1 = 0ULL, s2 = 0ULL, s3 = 0ULL;
#pragma unroll
            for (int e = 0; e < 16; e += 2) {
                ulonglong2 ka = kr[e];
                ulonglong2 kb = kr[e + 1];
                s0 = ffma2(q2[e * 2],     ka.x, s0);
                s1 = ffma2(q2[e * 2 + 1], ka.y, s1);
                s2 = ffma2(q2[e * 2 + 2], kb.x, s2);
                s3 = ffma2(q2[e * 2 + 3], kb.y, s3);
            }
            float2 r2 = up2(fadd2(fadd2(s0, s1), fadd2(s2, s3)));
            sv[u2] = r2.x + r2.y;
        }
        float cm = fmaxf(fmaxf(sv[0], sv[1]), fmaxf(sv[2], sv[3]));
        cm = fmaxf(cm, __shfl_xor_sync(0xffffffffu, cm, 1));
        cm = fmaxf(cm, __shfl_xor_sync(0xffffffffu, cm, 2));
        cm = fmaxf(cm, __shfl_xor_sync(0xffffffffu, cm, 4));
        float m_new = fmaxf(m_run, cm);
        float rsc = __expf(m_run - m_new);
        float psum = 0.f;
#pragma unroll
        for (int u2 = 0; u2 < 4; u2++) {
            float e = __expf(sv[u2] - m_new);
            sc[qi][sub * 4 + u2] = e;
            psum += e;
        }
        psum += __shfl_xor_sync(0xffffffffu, psum, 1);
        psum += __shfl_xor_sync(0xffffffffu, psum, 2);
        psum += __shfl_xor_sync(0xffffffffu, psum, 4);
        l_run = l_run * rsc + psum;
        m_run = m_new;
        __syncwarp();

        u64 rb = dup2(rsc);
#pragma unroll
        for (int d = 0; d < 4; d++) acc2[d] = fmul2(acc2[d], rb);
#pragma unroll 4
        for (int j = 0; j < 32; j++) {
            u64 eb = dup2(sc[qi][j]);
            ulonglong2 v0 = *(const ulonglong2*)&vs[j][sub * 4];
            ulonglong2 v1 = *(const ulonglong2*)&vs[j][sub * 4 + 32];
            acc2[0] = ffma2(eb, v0.x, acc2[0]);
            acc2[1] = ffma2(eb, v0.y, acc2[1]);
            acc2[2] = ffma2(eb, v1.x, acc2[2]);
            acc2[3] = ffma2(eb, v1.y, acc2[3]);
        }
    }

    size_t pidx = (((size_t)seg * BATCH + b) * NH + h) * GLB + qi;
    float2 a0 = up2(acc2[0]), a1 = up2(acc2[1]);
    float2 a2 = up2(acc2[2]), a3 = up2(acc2[3]);
    float* prow = po + pidx * HDIM;
    *(float4*)(prow + sub * 4)      = make_float4(a0.x, a0.y, a1.x, a1.y);
    *(float4*)(prow + 32 + sub * 4) = make_float4(a2.x, a2.y, a3.x, a3.y);
    if (sub == 0) { pm[pidx] = m_run; pl[pidx] = l_run; }
}

__global__ __launch_bounds__(64) void global_merge_kernel(
    const float* __restrict__ po, const float* __restrict__ pm,
    const float* __restrict__ pl, float* __restrict__ out)
{
    int g = blockIdx.x, h = blockIdx.y, b = blockIdx.z;
    int d = threadIdx.x;

    float mv[NSEG];
    float mx = -1e30f;
#pragma unroll
    for (int s = 0; s < NSEG; s++) {
        mv[s] = pm[(((size_t)s * BATCH + b) * NH + h) * GLB + g];
        mx = fmaxf(mx, mv[s]);
    }
    float num = 0.f, den = 0.f;
#pragma unroll
    for (int s = 0; s < NSEG; s++) {
        size_t pidx = (((size_t)s * BATCH + b) * NH + h) * GLB + g;
        float w = __expf(mv[s] - mx);
        num += w * po[pidx * HDIM + d];
        den += w * pl[pidx];
    }
    out[((size_t)(b * S_LEN + g)) * EMB + h * HDIM + d] = num / den;
}

// ---------------- launch ----------------
extern "C" void kernel_launch(void* const* d_in, const int* in_sizes, int n_in,
                              void* d_out, int out_size)
{
    (void)n_in; (void)out_size;
    int base = (in_sizes[2] == EMB * EMB) ? 2 : 3;

    const float* x    = (const float*)d_in[0];
    const int*   mask = (const int*)d_in[1];
    const float* wq   = (const float*)d_in[base + 0];
    const float* bq   = (const float*)d_in[base + 1];
    const float* wk   = (const float*)d_in[base + 2];
    const float* bk   = (const float*)d_in[base + 3];
    const float* wv   = (const float*)d_in[base + 4];
    const float* bv   = (const float*)d_in[base + 5];
    const float* wqg  = (const float*)d_in[base + 6];
    const float* bqg  = (const float*)d_in[base + 7];
    const float* wkg  = (const float*)d_in[base + 8];
    const float* bkg  = (const float*)d_in[base + 9];
    const float* wvg  = (const float*)d_in[base + 10];
    const float* bvg  = (const float*)d_in[base + 11];
    float* out = (float*)d_out;

    float *kg, *vg, *qg, *po, *pm, *pl;
    __half *xh, *xl, *wt, *q1, *q2, *k1, *v1;
    cudaGetSymbolAddress((void**)&kg, g_kg);
    cudaGetSymbolAddress((void**)&vg, g_vg);
    cudaGetSymbolAddress((void**)&qg, g_qg);
    cudaGetSymbolAddress((void**)&xh, g_xh);
    cudaGetSymbolAddress((void**)&xl, g_xl);
    cudaGetSymbolAddress((void**)&wt, g_wt);
    cudaGetSymbolAddress((void**)&q1, g_q1);
    cudaGetSymbolAddress((void**)&q2, g_q2);
    cudaGetSymbolAddress((void**)&k1, g_k1);
    cudaGetSymbolAddress((void**)&v1, g_v1);
    cudaGetSymbolAddress((void**)&po, g_po);
    cudaGetSymbolAddress((void**)&pm, g_pm);
    cudaGetSymbolAddress((void**)&pl, g_pl);

    cudaFuncSetAttribute(mma_gemm6_kernel,
                         cudaFuncAttributeMaxDynamicSharedMemorySize, GSM2);
    cudaFuncSetAttribute(local_attn_mma,
                         cudaFuncAttributeMaxDynamicSharedMemorySize, L_TOTAL);

    convx_kernel<<<(BATCH * S_LEN * EMB) / (256 * 4), 256>>>(x, xh, xl);
    convw_kernel<<<dim3(EMB / 32, EMB / 32, 6), 256>>>(
        wq, wk, wv, wkg, wvg, wqg, wt);
    mma_gemm6_kernel<<<dim3(EMB / 128, BATCH * S_LEN / 128, 6), 256, GSM2>>>(
        xh, xl, wt, bq, bk, bv, bkg, bvg, bqg,
        q1, q2, k1, v1, kg, vg, qg);
    local_attn_mma<<<dim3(S_LEN / QT2, NH, BATCH), 256, L_TOTAL>>>(
        q1, q2, k1, v1, mask, out);
    global_part_kernel<<<dim3(NSEG, NH, BATCH), 256>>>(qg, kg, vg, po, pm, pl);
    global_merge_kernel<<<dim3(GLB, NH, BATCH), 64>>>(po, pm, pl, out);
}